// round 2
// baseline (speedup 1.0000x reference)
#include <cuda_runtime.h>
#include <math.h>

#define B 64
#define T 128
#define V 10000
#define E 1024
#define H 1024
#define G4 4096   // 4*H
#define L 2

typedef unsigned long long ull;

// packed f32x2 FMA: d = a*b + d (elementwise on 2 packed fp32 lanes)
__device__ __forceinline__ void ffma2(ull& d, ull a, ull b) {
    asm("fma.rn.f32x2 %0, %1, %2, %3;" : "=l"(d) : "l"(a), "l"(b), "l"(d));
}
__device__ __forceinline__ float f2_lo(ull v) { return __uint_as_float((unsigned)(v & 0xffffffffull)); }
__device__ __forceinline__ float f2_hi(ull v) { return __uint_as_float((unsigned)(v >> 32)); }

// ---------------- scratch (device globals; no runtime allocation) ----------
__device__ float g_x[(size_t)B * T * E];     // layer input/output  (32 MB)
__device__ float g_gx[(size_t)B * T * G4];   // input projections   (128 MB)
__device__ float g_h[2][B * H];              // ping-pong hidden state
__device__ float g_c[B * H];                 // cell state
__device__ int   g_len[B];

// ---------------- lengths = row-sum of attention mask ----------------------
__global__ void lengths_kernel(const int* __restrict__ mask) {
    int b = blockIdx.x;
    int v = mask[b * T + threadIdx.x];
#pragma unroll
    for (int o = 16; o > 0; o >>= 1) v += __shfl_down_sync(0xffffffffu, v, o);
    __shared__ int sh[4];
    if ((threadIdx.x & 31) == 0) sh[threadIdx.x >> 5] = v;
    __syncthreads();
    if (threadIdx.x == 0) g_len[b] = sh[0] + sh[1] + sh[2] + sh[3];
}

// ---------------- embedding gather -----------------------------------------
__global__ void embed_kernel(const int* __restrict__ ids, const float* __restrict__ emb) {
    int r = blockIdx.x;
    int id = __ldg(&ids[r]);
    const float4* s = reinterpret_cast<const float4*>(emb) + (size_t)id * (E / 4);
    float4* d = reinterpret_cast<float4*>(g_x) + (size_t)r * (E / 4);
    d[threadIdx.x] = s[threadIdx.x];
}

// ---------------- zero h (both buffers) and c -------------------------------
__global__ void zero_hc() {
    int i = blockIdx.x * blockDim.x + threadIdx.x;
    if (i < B * H) { g_h[0][i] = 0.f; g_h[1][i] = 0.f; g_c[i] = 0.f; }
}

// ---------------- fp32 GEMM with packed FFMA2:  C = g_x * Wm^T + b1 (+ b2) --
// CTA tile 128x128, 256 threads, per-thread 8x8 micro-tile. Rows are packed
// into f32x2 lanes (natural ulonglong2 pairs); W is stored DUPLICATED in smem
// so each weight loads as a pre-broadcast f32x2 pair (no pack MOVs).
__global__ void __launch_bounds__(256, 2) gemm_kernel(
    const float* __restrict__ Wm, const float* __restrict__ b1,
    const float* __restrict__ b2, float* __restrict__ Cout,
    int mode, int N, int K, int ldc)
{
    const float* __restrict__ A = g_x;
    float* __restrict__ C = (mode == 0) ? g_gx : Cout;

    __shared__ float As[16][132];    // [k][m]
    __shared__ float Ws2[16][264];   // [k][2n] duplicated columns

    const int tid  = threadIdx.x;
    const int row0 = blockIdx.y * 128;
    const int col0 = blockIdx.x * 128;
    const int ty   = tid >> 4;      // 0..15 -> 8 rows
    const int tx   = tid & 15;      // 0..15 -> 8 cols

    ull acc[4][8];                  // [row-pair][col]
#pragma unroll
    for (int i = 0; i < 4; i++)
#pragma unroll
        for (int j = 0; j < 8; j++) acc[i][j] = 0ull;

    float4 ra[2], rw[2];
    // prefetch chunk 0
#pragma unroll
    for (int i = 0; i < 2; i++) {
        int s = tid + i * 256; int r = s >> 2, kq = s & 3;
        ra[i] = *reinterpret_cast<const float4*>(&A[(size_t)(row0 + r) * K + kq * 4]);
    }
#pragma unroll
    for (int i = 0; i < 2; i++) {
        int s = tid + i * 256; int n = s >> 2, kq = s & 3; int col = col0 + n;
        rw[i] = (col < N) ? *reinterpret_cast<const float4*>(&Wm[(size_t)col * K + kq * 4])
                          : make_float4(0.f, 0.f, 0.f, 0.f);
    }

    const int nCh = K >> 4;
    for (int ch = 0; ch < nCh; ch++) {
#pragma unroll
        for (int i = 0; i < 2; i++) {
            int s = tid + i * 256; int r = s >> 2, kq = s & 3;
            As[kq * 4 + 0][r] = ra[i].x; As[kq * 4 + 1][r] = ra[i].y;
            As[kq * 4 + 2][r] = ra[i].z; As[kq * 4 + 3][r] = ra[i].w;
        }
#pragma unroll
        for (int i = 0; i < 2; i++) {
            int s = tid + i * 256; int n = s >> 2, kq = s & 3;
            float v0 = rw[i].x, v1 = rw[i].y, v2 = rw[i].z, v3 = rw[i].w;
            Ws2[kq * 4 + 0][2 * n] = v0; Ws2[kq * 4 + 0][2 * n + 1] = v0;
            Ws2[kq * 4 + 1][2 * n] = v1; Ws2[kq * 4 + 1][2 * n + 1] = v1;
            Ws2[kq * 4 + 2][2 * n] = v2; Ws2[kq * 4 + 2][2 * n + 1] = v2;
            Ws2[kq * 4 + 3][2 * n] = v3; Ws2[kq * 4 + 3][2 * n + 1] = v3;
        }
        __syncthreads();

        if (ch + 1 < nCh) {
            int k0 = (ch + 1) << 4;
#pragma unroll
            for (int i = 0; i < 2; i++) {
                int s = tid + i * 256; int r = s >> 2, kq = s & 3;
                ra[i] = *reinterpret_cast<const float4*>(&A[(size_t)(row0 + r) * K + k0 + kq * 4]);
            }
#pragma unroll
            for (int i = 0; i < 2; i++) {
                int s = tid + i * 256; int n = s >> 2, kq = s & 3; int col = col0 + n;
                rw[i] = (col < N) ? *reinterpret_cast<const float4*>(&Wm[(size_t)col * K + k0 + kq * 4])
                                  : make_float4(0.f, 0.f, 0.f, 0.f);
            }
        }

#pragma unroll
        for (int kk = 0; kk < 16; kk++) {
            ulonglong2 a01 = *reinterpret_cast<const ulonglong2*>(&As[kk][ty * 8]);
            ulonglong2 a23 = *reinterpret_cast<const ulonglong2*>(&As[kk][ty * 8 + 4]);
            ull ap[4] = { a01.x, a01.y, a23.x, a23.y };
            ulonglong2 w01 = *reinterpret_cast<const ulonglong2*>(&Ws2[kk][tx * 16]);
            ulonglong2 w23 = *reinterpret_cast<const ulonglong2*>(&Ws2[kk][tx * 16 + 4]);
            ulonglong2 w45 = *reinterpret_cast<const ulonglong2*>(&Ws2[kk][tx * 16 + 8]);
            ulonglong2 w67 = *reinterpret_cast<const ulonglong2*>(&Ws2[kk][tx * 16 + 12]);
            ull wp[8] = { w01.x, w01.y, w23.x, w23.y, w45.x, w45.y, w67.x, w67.y };
#pragma unroll
            for (int i = 0; i < 4; i++)
#pragma unroll
                for (int j = 0; j < 8; j++)
                    ffma2(acc[i][j], ap[i], wp[j]);
        }
        __syncthreads();
    }

    float bias[8];
#pragma unroll
    for (int j = 0; j < 8; j++) {
        int col = col0 + tx * 8 + j;
        bias[j] = (col < N) ? (b1[col] + (b2 ? b2[col] : 0.f)) : 0.f;
    }
#pragma unroll
    for (int i = 0; i < 4; i++) {
        int r0 = row0 + ty * 8 + 2 * i;
#pragma unroll
        for (int j = 0; j < 8; j++) {
            int col = col0 + tx * 8 + j;
            if (col < N) {
                C[(size_t)r0 * ldc + col]       = f2_lo(acc[i][j]) + bias[j];
                C[(size_t)(r0 + 1) * ldc + col] = f2_hi(acc[i][j]) + bias[j];
            }
        }
    }
}

// ---------------- fused LSTM step: gates GEMM + cell update -----------------
// grid = H/8 = 128 CTAs, 256 threads (2 warps/SMSP). CTA owns 8 h-columns ->
// a 64x32 gate tile, K = H = 1024, KC = 64. Rows packed into f32x2 lanes,
// W duplicated in smem.
#define KC 64
__global__ void __launch_bounds__(256) lstm_step_kernel(
    const float* __restrict__ Whh, int t)
{
    __shared__ float hsm[KC][66];    // [k][b]
    __shared__ float wsm2[KC][72];   // [k][2q] duplicated
    __shared__ float Ssm[64][33];    // gate pre-activations

    const float* __restrict__ hin  = g_h[t & 1];
    float* __restrict__       hout = g_h[(t + 1) & 1];

    const int tid = threadIdx.x;
    const int j0  = blockIdx.x * 8;
    const int ty  = tid >> 3;       // 0..31 -> rows (2ty, 2ty+1)
    const int tx  = tid & 7;        // 0..7  -> 4 gate-cols

    ull acc[4] = { 0ull, 0ull, 0ull, 0ull };

    float4 rh[4], rw[2];
    // prefetch chunk 0: h tile KC x 64 = 4096 floats, w tile KC x 32 = 2048
#pragma unroll
    for (int i = 0; i < 4; i++) {
        int s = tid + i * 256; int b = s >> 4, kq = s & 15;
        rh[i] = *reinterpret_cast<const float4*>(&hin[b * H + kq * 4]);
    }
#pragma unroll
    for (int i = 0; i < 2; i++) {
        int s = tid + i * 256; int q = s >> 4, kq = s & 15;
        int wr = (q >> 3) * H + j0 + (q & 7);
        rw[i] = *reinterpret_cast<const float4*>(&Whh[(size_t)wr * H + kq * 4]);
    }

    for (int ch = 0; ch < (H / KC); ch++) {
#pragma unroll
        for (int i = 0; i < 4; i++) {
            int s = tid + i * 256; int b = s >> 4, kq = s & 15;
            hsm[kq * 4 + 0][b] = rh[i].x; hsm[kq * 4 + 1][b] = rh[i].y;
            hsm[kq * 4 + 2][b] = rh[i].z; hsm[kq * 4 + 3][b] = rh[i].w;
        }
#pragma unroll
        for (int i = 0; i < 2; i++) {
            int s = tid + i * 256; int q = s >> 4, kq = s & 15;
            wsm2[kq * 4 + 0][2 * q] = rw[i].x; wsm2[kq * 4 + 0][2 * q + 1] = rw[i].x;
            wsm2[kq * 4 + 1][2 * q] = rw[i].y; wsm2[kq * 4 + 1][2 * q + 1] = rw[i].y;
            wsm2[kq * 4 + 2][2 * q] = rw[i].z; wsm2[kq * 4 + 2][2 * q + 1] = rw[i].z;
            wsm2[kq * 4 + 3][2 * q] = rw[i].w; wsm2[kq * 4 + 3][2 * q + 1] = rw[i].w;
        }
        __syncthreads();

        if (ch + 1 < (H / KC)) {
            int k0 = (ch + 1) * KC;
#pragma unroll
            for (int i = 0; i < 4; i++) {
                int s = tid + i * 256; int b = s >> 4, kq = s & 15;
                rh[i] = *reinterpret_cast<const float4*>(&hin[b * H + k0 + kq * 4]);
            }
#pragma unroll
            for (int i = 0; i < 2; i++) {
                int s = tid + i * 256; int q = s >> 4, kq = s & 15;
                int wr = (q >> 3) * H + j0 + (q & 7);
                rw[i] = *reinterpret_cast<const float4*>(&Whh[(size_t)wr * H + k0 + kq * 4]);
            }
        }

#pragma unroll
        for (int kk = 0; kk < KC; kk++) {
            ull ap = *reinterpret_cast<const ull*>(&hsm[kk][ty * 2]);
            ulonglong2 w01 = *reinterpret_cast<const ulonglong2*>(&wsm2[kk][tx * 8]);
            ulonglong2 w23 = *reinterpret_cast<const ulonglong2*>(&wsm2[kk][tx * 8 + 4]);
            ffma2(acc[0], ap, w01.x);
            ffma2(acc[1], ap, w01.y);
            ffma2(acc[2], ap, w23.x);
            ffma2(acc[3], ap, w23.y);
        }
        __syncthreads();
    }

    // exchange gate tile through smem: rows (2ty, 2ty+1), cols tx*4..tx*4+3
#pragma unroll
    for (int c = 0; c < 4; c++) {
        Ssm[2 * ty][tx * 4 + c]     = f2_lo(acc[c]);
        Ssm[2 * ty + 1][tx * 4 + c] = f2_hi(acc[c]);
    }
    __syncthreads();

#pragma unroll
    for (int ii = 0; ii < 2; ii++) {
        int idx = tid * 2 + ii;               // 0..511 = 64 batches x 8 cols
        int b = idx >> 3, jj = idx & 7;
        int j = j0 + jj;
        size_t gr = ((size_t)b * T + t) * G4;
        float iv = Ssm[b][jj]      + g_gx[gr + j];
        float fv = Ssm[b][8 + jj]  + g_gx[gr + H + j];
        float gv = Ssm[b][16 + jj] + g_gx[gr + 2 * H + j];
        float ov = Ssm[b][24 + jj] + g_gx[gr + 3 * H + j];

        float c_old = g_c[b * H + j];
        float h_old = hin[b * H + j];

        float si = 1.f / (1.f + expf(-iv));
        float sf = 1.f / (1.f + expf(-fv));
        float so = 1.f / (1.f + expf(-ov));
        float cn = fmaf(sf, c_old, si * tanhf(gv));
        float hn = so * tanhf(cn);

        bool ok = t < g_len[b];
        g_c[b * H + j]  = ok ? cn : c_old;
        hout[b * H + j] = ok ? hn : h_old;
        g_x[((size_t)b * T + t) * E + j] = ok ? hn : 0.f;
    }
}

// ---------------- final state copy ------------------------------------------
__global__ void copy_states_kernel(float* __restrict__ hs_out, float* __restrict__ cs_out) {
    int i = blockIdx.x * blockDim.x + threadIdx.x;
    if (i < B * H) {
        hs_out[i] = g_h[0][i];   // after T=128 steps, final h lives in buffer 0
        cs_out[i] = g_c[i];
    }
}

// ---------------- launch ------------------------------------------------------
extern "C" void kernel_launch(void* const* d_in, const int* in_sizes, int n_in,
                              void* d_out, int out_size)
{
    const int*   ids  = (const int*)d_in[0];
    const int*   mask = (const int*)d_in[1];
    const float* emb  = (const float*)d_in[2];
    const float* Wih  = (const float*)d_in[3];
    const float* Whh  = (const float*)d_in[4];
    const float* bih  = (const float*)d_in[5];
    const float* bhh  = (const float*)d_in[6];
    const float* fcw  = (const float*)d_in[7];
    const float* fcb  = (const float*)d_in[8];
    float* out = (float*)d_out;

    lengths_kernel<<<B, T>>>(mask);
    embed_kernel<<<B * T, E / 4>>>(ids, emb);

    const size_t HS_OFF = (size_t)B * T * V;           // 81,920,000
    const size_t CS_OFF = HS_OFF + (size_t)L * B * H;  // + 131,072

    for (int l = 0; l < L; l++) {
        // gx = x @ W_ih[l]^T + (b_ih[l] + b_hh[l])   : [8192, 4096]
        gemm_kernel<<<dim3(G4 / 128, (B * T) / 128), 256>>>(
            Wih + (size_t)l * G4 * E, bih + (size_t)l * G4, bhh + (size_t)l * G4,
            nullptr, /*mode=*/0, G4, E, G4);

        zero_hc<<<(B * H + 511) / 512, 512>>>();

        for (int t = 0; t < T; t++)
            lstm_step_kernel<<<H / 8, 256>>>(Whh + (size_t)l * G4 * H, t);

        copy_states_kernel<<<(B * H + 511) / 512, 512>>>(
            out + HS_OFF + (size_t)l * B * H,
            out + CS_OFF + (size_t)l * B * H);
    }

    // logits = x @ fc_w^T + fc_b : [8192, 10000] written straight into d_out
    gemm_kernel<<<dim3((V + 127) / 128, (B * T) / 128), 256>>>(
        fcw, fcb, nullptr, out, /*mode=*/1, V, H, V);
}

// round 4
// speedup vs baseline: 3.9673x; 3.9673x over previous
#include <cuda_runtime.h>
#include <cuda_bf16.h>
#include <math.h>
#include <stdint.h>

#define B 64
#define T 128
#define V 10000
#define E 1024
#define H 1024
#define G4 4096
#define L 2
#define KDIM 1024

// ---------------- scratch (device globals) ----------------------------------
__device__ float g_x[(size_t)B * T * E];
__device__ float g_gx[(size_t)B * T * G4];
__device__ float g_h[2][B * H];
__device__ float g_c[B * H];
__device__ int   g_len[B];
__device__ __nv_bfloat16 g_xhi[(size_t)B * T * E];
__device__ __nv_bfloat16 g_xlo[(size_t)B * T * E];
__device__ __nv_bfloat16 g_whi[(size_t)V * H];
__device__ __nv_bfloat16 g_wlo[(size_t)V * H];

// ---------------- PTX helpers (portable: sm_80+ PTX only) -------------------
__device__ __forceinline__ uint32_t smem_u32(const void* p) {
    uint32_t a;
    asm("{ .reg .u64 t; cvta.to.shared.u64 t, %1; cvt.u32.u64 %0, t; }" : "=r"(a) : "l"(p));
    return a;
}
__device__ __forceinline__ void ldmx4(uint32_t r[4], uint32_t addr) {
    asm volatile("ldmatrix.sync.aligned.m8n8.x4.shared.b16 {%0,%1,%2,%3}, [%4];"
                 : "=r"(r[0]), "=r"(r[1]), "=r"(r[2]), "=r"(r[3]) : "r"(addr));
}
__device__ __forceinline__ void mma16816(float d[4], const uint32_t a[4], const uint32_t b[2]) {
    asm volatile("mma.sync.aligned.m16n8k16.row.col.f32.bf16.bf16.f32 "
                 "{%0,%1,%2,%3}, {%4,%5,%6,%7}, {%8,%9}, {%0,%1,%2,%3};"
                 : "+f"(d[0]), "+f"(d[1]), "+f"(d[2]), "+f"(d[3])
                 : "r"(a[0]), "r"(a[1]), "r"(a[2]), "r"(a[3]), "r"(b[0]), "r"(b[1]));
}

// ---------------- small kernels ----------------------------------------------
__global__ void lengths_kernel(const int* __restrict__ mask) {
    int b = blockIdx.x;
    int v = mask[b * T + threadIdx.x];
#pragma unroll
    for (int o = 16; o > 0; o >>= 1) v += __shfl_down_sync(0xffffffffu, v, o);
    __shared__ int sh[4];
    if ((threadIdx.x & 31) == 0) sh[threadIdx.x >> 5] = v;
    __syncthreads();
    if (threadIdx.x == 0) g_len[b] = sh[0] + sh[1] + sh[2] + sh[3];
}

__global__ void embed_kernel(const int* __restrict__ ids, const float* __restrict__ emb) {
    int r = blockIdx.x;
    int id = __ldg(&ids[r]);
    const float4* s = reinterpret_cast<const float4*>(emb) + (size_t)id * (E / 4);
    float4* d = reinterpret_cast<float4*>(g_x) + (size_t)r * (E / 4);
    d[threadIdx.x] = s[threadIdx.x];
}

__global__ void zero_hc() {
    int i = blockIdx.x * blockDim.x + threadIdx.x;
    if (i < B * H) { g_h[0][i] = 0.f; g_h[1][i] = 0.f; g_c[i] = 0.f; }
}

// split fp32 -> bf16 hi + bf16 lo. mode 0: src = g_x -> g_xhi/g_xlo.
// mode 1: src = W param -> g_whi/g_wlo.
__global__ void convert_kernel(const float* __restrict__ wsrc, int mode, int n4) {
    int i = blockIdx.x * blockDim.x + threadIdx.x;
    if (i >= n4) return;
    const float* src = (mode == 0) ? g_x : wsrc;
    __nv_bfloat16* hi = (mode == 0) ? g_xhi : g_whi;
    __nv_bfloat16* lo = (mode == 0) ? g_xlo : g_wlo;
    float4 v = reinterpret_cast<const float4*>(src)[i];
    __nv_bfloat16 h0 = __float2bfloat16(v.x), h1 = __float2bfloat16(v.y);
    __nv_bfloat16 h2 = __float2bfloat16(v.z), h3 = __float2bfloat16(v.w);
    __nv_bfloat16 l0 = __float2bfloat16(v.x - __bfloat162float(h0));
    __nv_bfloat16 l1 = __float2bfloat16(v.y - __bfloat162float(h1));
    __nv_bfloat16 l2 = __float2bfloat16(v.z - __bfloat162float(h2));
    __nv_bfloat16 l3 = __float2bfloat16(v.w - __bfloat162float(h3));
    __nv_bfloat162* hp = reinterpret_cast<__nv_bfloat162*>(hi) + 2 * i;
    __nv_bfloat162* lp = reinterpret_cast<__nv_bfloat162*>(lo) + 2 * i;
    hp[0] = __nv_bfloat162(h0, h1); hp[1] = __nv_bfloat162(h2, h3);
    lp[0] = __nv_bfloat162(l0, l1); lp[1] = __nv_bfloat162(l2, l3);
}

// ---------------- split-bf16 tensor-core GEMM: C = x @ W^T + b1 (+ b2) ------
// CTA 128x128, 256 threads = 8 warps (2 m x 4 n), warp tile 64x32.
// K chunks of 32, single smem buffer + register prefetch.
// 3 mma passes per k-step: hi*hi + hi*lo + lo*hi (fp32 accum).
#define SSTR 40   // smem row stride in bf16 elements (80B): conflict-free ldmatrix
__global__ void __launch_bounds__(256, 1) mma_gemm(
    float* __restrict__ Cout, const float* __restrict__ b1,
    const float* __restrict__ b2, int Ncols, int ldc, int mode)
{
    __shared__ __nv_bfloat16 sAh[128 * SSTR];
    __shared__ __nv_bfloat16 sAl[128 * SSTR];
    __shared__ __nv_bfloat16 sBh[128 * SSTR];
    __shared__ __nv_bfloat16 sBl[128 * SSTR];

    float* __restrict__ C = (mode == 0) ? g_gx : Cout;

    const int tid  = threadIdx.x;
    const int wid  = tid >> 5;
    const int lane = tid & 31;
    const int row0 = blockIdx.y * 128;
    const int col0 = blockIdx.x * 128;
    const int wm0  = (wid >> 2) * 64;   // warp m offset (0/64)
    const int wn0  = (wid & 3) * 32;    // warp n offset (0/32/64/96)

    const uint32_t baseAh = smem_u32(sAh);
    const uint32_t baseAl = smem_u32(sAl);
    const uint32_t baseBh = smem_u32(sBh);
    const uint32_t baseBl = smem_u32(sBl);

    float acc[4][4][4];
#pragma unroll
    for (int mi = 0; mi < 4; mi++)
#pragma unroll
        for (int ni = 0; ni < 4; ni++)
#pragma unroll
            for (int q = 0; q < 4; q++) acc[mi][ni][q] = 0.f;

    // per-thread copy slots: idx = s*256 + tid; r = idx>>2 (0..127), g = idx&3
    const int r_s[2] = { (0 * 256 + tid) >> 2, (1 * 256 + tid) >> 2 };
    const int g_s[2] = { tid & 3, tid & 3 };
    const uint4 zero4 = make_uint4(0, 0, 0, 0);

    uint4 pAh[2], pAl[2], pBh[2], pBl[2];

    auto prefetch = [&](int kb) {
#pragma unroll
        for (int s = 0; s < 2; s++) {
            int r = r_s[s], g = g_s[s];
            size_t ga = (size_t)(row0 + r) * KDIM + kb + g * 8;
            pAh[s] = *reinterpret_cast<const uint4*>(g_xhi + ga);
            pAl[s] = *reinterpret_cast<const uint4*>(g_xlo + ga);
            int n = col0 + r;
            if (n < Ncols) {
                size_t gb = (size_t)n * KDIM + kb + g * 8;
                pBh[s] = *reinterpret_cast<const uint4*>(g_whi + gb);
                pBl[s] = *reinterpret_cast<const uint4*>(g_wlo + gb);
            } else { pBh[s] = zero4; pBl[s] = zero4; }
        }
    };

    prefetch(0);

    for (int ch = 0; ch < KDIM / 32; ch++) {
        __syncthreads();   // previous iteration's readers done
#pragma unroll
        for (int s = 0; s < 2; s++) {
            int r = r_s[s], g = g_s[s];
            int so = r * SSTR + g * 8;
            *reinterpret_cast<uint4*>(sAh + so) = pAh[s];
            *reinterpret_cast<uint4*>(sAl + so) = pAl[s];
            *reinterpret_cast<uint4*>(sBh + so) = pBh[s];
            *reinterpret_cast<uint4*>(sBl + so) = pBl[s];
        }
        __syncthreads();

        if (ch + 1 < KDIM / 32) prefetch((ch + 1) * 32);

#pragma unroll
        for (int ks = 0; ks < 2; ks++) {
            uint32_t Ah[4][4], Al[4][4], Bh[4][2], Bl[4][2];
            // A fragments: one ldmatrix.x4 per 16-row m-tile
            {
                int arow = wm0 + (lane & 7) + ((lane >> 3) & 1) * 8;
                int acol = ks * 16 + (lane >> 4) * 8;
#pragma unroll
                for (int mi = 0; mi < 4; mi++) {
                    uint32_t off = (uint32_t)(((arow + mi * 16) * SSTR + acol) * 2);
                    ldmx4(Ah[mi], baseAh + off);
                    ldmx4(Al[mi], baseAl + off);
                }
            }
            // B fragments: one ldmatrix.x4 per 16-col (two 8-wide n-tiles)
            {
                int brow = wn0 + (lane & 7) + ((lane >> 4) & 1) * 8;
                int bcol = ks * 16 + ((lane >> 3) & 1) * 8;
#pragma unroll
                for (int p = 0; p < 2; p++) {
                    uint32_t off = (uint32_t)(((brow + p * 16) * SSTR + bcol) * 2);
                    uint32_t rbh[4], rbl[4];
                    ldmx4(rbh, baseBh + off);
                    ldmx4(rbl, baseBl + off);
                    Bh[2 * p][0] = rbh[0]; Bh[2 * p][1] = rbh[1];
                    Bh[2 * p + 1][0] = rbh[2]; Bh[2 * p + 1][1] = rbh[3];
                    Bl[2 * p][0] = rbl[0]; Bl[2 * p][1] = rbl[1];
                    Bl[2 * p + 1][0] = rbl[2]; Bl[2 * p + 1][1] = rbl[3];
                }
            }
#pragma unroll
            for (int mi = 0; mi < 4; mi++)
#pragma unroll
                for (int ni = 0; ni < 4; ni++) {
                    mma16816(acc[mi][ni], Ah[mi], Bh[ni]);
                    mma16816(acc[mi][ni], Ah[mi], Bl[ni]);
                    mma16816(acc[mi][ni], Al[mi], Bh[ni]);
                }
        }
    }

    // epilogue: direct float2 stores with bias
#pragma unroll
    for (int ni = 0; ni < 4; ni++) {
        int col = col0 + wn0 + ni * 8 + (lane & 3) * 2;
        if (col >= Ncols) continue;
        float bx = b1[col], by = b1[col + 1];
        if (b2) { bx += b2[col]; by += b2[col + 1]; }
#pragma unroll
        for (int mi = 0; mi < 4; mi++) {
            int row = row0 + wm0 + mi * 16 + (lane >> 2);
            float2 v0 = make_float2(acc[mi][ni][0] + bx, acc[mi][ni][1] + by);
            float2 v1 = make_float2(acc[mi][ni][2] + bx, acc[mi][ni][3] + by);
            *reinterpret_cast<float2*>(&C[(size_t)row * ldc + col])       = v0;
            *reinterpret_cast<float2*>(&C[(size_t)(row + 8) * ldc + col]) = v1;
        }
    }
}

// ---------------- fused LSTM step (R1 version, known good) ------------------
__global__ void __launch_bounds__(128) lstm_step_kernel(
    const float* __restrict__ Whh, int t)
{
    __shared__ float hsm[32][68];
    __shared__ float wsm[32][36];
    __shared__ float Ssm[64][33];

    const float* __restrict__ hin  = g_h[t & 1];
    float* __restrict__       hout = g_h[(t + 1) & 1];

    const int tid = threadIdx.x;
    const int j0  = blockIdx.x * 8;
    const int ty  = tid >> 3;
    const int tx  = tid & 7;

    float acc[4][4];
#pragma unroll
    for (int i = 0; i < 4; i++)
#pragma unroll
        for (int j = 0; j < 4; j++) acc[i][j] = 0.f;

    float4 rh[4], rw[2];
#pragma unroll
    for (int i = 0; i < 4; i++) {
        int s = tid + i * 128; int b = s >> 3, kq = s & 7;
        rh[i] = *reinterpret_cast<const float4*>(&hin[b * H + kq * 4]);
    }
#pragma unroll
    for (int i = 0; i < 2; i++) {
        int s = tid + i * 128; int q = s >> 3, kq = s & 7;
        int wr = (q >> 3) * H + j0 + (q & 7);
        rw[i] = *reinterpret_cast<const float4*>(&Whh[(size_t)wr * H + kq * 4]);
    }

    for (int ch = 0; ch < 32; ch++) {
#pragma unroll
        for (int i = 0; i < 4; i++) {
            int s = tid + i * 128; int b = s >> 3, kq = s & 7;
            hsm[kq * 4 + 0][b] = rh[i].x; hsm[kq * 4 + 1][b] = rh[i].y;
            hsm[kq * 4 + 2][b] = rh[i].z; hsm[kq * 4 + 3][b] = rh[i].w;
        }
#pragma unroll
        for (int i = 0; i < 2; i++) {
            int s = tid + i * 128; int q = s >> 3, kq = s & 7;
            wsm[kq * 4 + 0][q] = rw[i].x; wsm[kq * 4 + 1][q] = rw[i].y;
            wsm[kq * 4 + 2][q] = rw[i].z; wsm[kq * 4 + 3][q] = rw[i].w;
        }
        __syncthreads();

        if (ch + 1 < 32) {
            int k0 = (ch + 1) * 32;
#pragma unroll
            for (int i = 0; i < 4; i++) {
                int s = tid + i * 128; int b = s >> 3, kq = s & 7;
                rh[i] = *reinterpret_cast<const float4*>(&hin[b * H + k0 + kq * 4]);
            }
#pragma unroll
            for (int i = 0; i < 2; i++) {
                int s = tid + i * 128; int q = s >> 3, kq = s & 7;
                int wr = (q >> 3) * H + j0 + (q & 7);
                rw[i] = *reinterpret_cast<const float4*>(&Whh[(size_t)wr * H + k0 + kq * 4]);
            }
        }

#pragma unroll
        for (int kk = 0; kk < 32; kk++) {
            float a[4], w[4];
            *reinterpret_cast<float4*>(&a[0]) = *reinterpret_cast<const float4*>(&hsm[kk][ty * 4]);
            *reinterpret_cast<float4*>(&w[0]) = *reinterpret_cast<const float4*>(&wsm[kk][tx * 4]);
#pragma unroll
            for (int i = 0; i < 4; i++)
#pragma unroll
                for (int j = 0; j < 4; j++)
                    acc[i][j] = fmaf(a[i], w[j], acc[i][j]);
        }
        __syncthreads();
    }

#pragma unroll
    for (int i = 0; i < 4; i++)
#pragma unroll
        for (int j = 0; j < 4; j++) Ssm[ty * 4 + i][tx * 4 + j] = acc[i][j];
    __syncthreads();

#pragma unroll
    for (int ii = 0; ii < 4; ii++) {
        int idx = tid * 4 + ii;
        int b = idx >> 3, jj = idx & 7;
        int j = j0 + jj;
        size_t gr = ((size_t)b * T + t) * G4;
        float iv = Ssm[b][jj]      + g_gx[gr + j];
        float fv = Ssm[b][8 + jj]  + g_gx[gr + H + j];
        float gv = Ssm[b][16 + jj] + g_gx[gr + 2 * H + j];
        float ov = Ssm[b][24 + jj] + g_gx[gr + 3 * H + j];

        float c_old = g_c[b * H + j];
        float h_old = hin[b * H + j];

        float si = 1.f / (1.f + expf(-iv));
        float sf = 1.f / (1.f + expf(-fv));
        float so = 1.f / (1.f + expf(-ov));
        float cn = fmaf(sf, c_old, si * tanhf(gv));
        float hn = so * tanhf(cn);

        bool ok = t < g_len[b];
        g_c[b * H + j]  = ok ? cn : c_old;
        hout[b * H + j] = ok ? hn : h_old;
        g_x[((size_t)b * T + t) * E + j] = ok ? hn : 0.f;
    }
}

__global__ void copy_states_kernel(float* __restrict__ hs_out, float* __restrict__ cs_out) {
    int i = blockIdx.x * blockDim.x + threadIdx.x;
    if (i < B * H) {
        hs_out[i] = g_h[0][i];
        cs_out[i] = g_c[i];
    }
}

// ---------------- launch ------------------------------------------------------
extern "C" void kernel_launch(void* const* d_in, const int* in_sizes, int n_in,
                              void* d_out, int out_size)
{
    const int*   ids  = (const int*)d_in[0];
    const int*   mask = (const int*)d_in[1];
    const float* emb  = (const float*)d_in[2];
    const float* Wih  = (const float*)d_in[3];
    const float* Whh  = (const float*)d_in[4];
    const float* bih  = (const float*)d_in[5];
    const float* bhh  = (const float*)d_in[6];
    const float* fcw  = (const float*)d_in[7];
    const float* fcb  = (const float*)d_in[8];
    float* out = (float*)d_out;

    lengths_kernel<<<B, T>>>(mask);
    embed_kernel<<<B * T, E / 4>>>(ids, emb);

    const size_t HS_OFF = (size_t)B * T * V;
    const size_t CS_OFF = HS_OFF + (size_t)L * B * H;
    const int X4 = B * T * E / 4;

    for (int l = 0; l < L; l++) {
        convert_kernel<<<(X4 + 255) / 256, 256>>>(nullptr, 0, X4);
        const int W4 = G4 * E / 4;
        convert_kernel<<<(W4 + 255) / 256, 256>>>(Wih + (size_t)l * G4 * E, 1, W4);

        mma_gemm<<<dim3(G4 / 128, (B * T) / 128), 256>>>(
            nullptr, bih + (size_t)l * G4, bhh + (size_t)l * G4, G4, G4, /*mode=*/0);

        zero_hc<<<(B * H + 511) / 512, 512>>>();

        for (int t = 0; t < T; t++)
            lstm_step_kernel<<<H / 8, 128>>>(Whh + (size_t)l * G4 * H, t);

        copy_states_kernel<<<(B * H + 511) / 512, 512>>>(
            out + HS_OFF + (size_t)l * B * H,
            out + CS_OFF + (size_t)l * B * H);
    }

    convert_kernel<<<(X4 + 255) / 256, 256>>>(nullptr, 0, X4);
    const int F4 = V * H / 4;
    convert_kernel<<<(F4 + 255) / 256, 256>>>(fcw, 1, F4);

    mma_gemm<<<dim3((V + 127) / 128, (B * T) / 128), 256>>>(
        out, fcb, nullptr, V, V, /*mode=*/1);
}

// round 5
// speedup vs baseline: 4.6647x; 1.1758x over previous
#include <cuda_runtime.h>
#include <cuda_bf16.h>
#include <math.h>
#include <stdint.h>

#define B 64
#define T 128
#define V 10000
#define E 1024
#define H 1024
#define G4 4096
#define L 2
#define KDIM 1024

// ---------------- scratch (device globals) ----------------------------------
__device__ float g_x[(size_t)B * T * E];
__device__ float g_gx[(size_t)B * T * G4];
__device__ float g_h[2][B * H];
__device__ float g_c[B * H];
__device__ int   g_len[B];
__device__ __nv_bfloat16 g_xhi[(size_t)B * T * E];
__device__ __nv_bfloat16 g_xlo[(size_t)B * T * E];
__device__ __nv_bfloat16 g_whi[(size_t)V * H];
__device__ __nv_bfloat16 g_wlo[(size_t)V * H];
__device__ __nv_bfloat16 g_hbf[2][2][B * H];          // [pingpong][hi/lo]
__device__ __nv_bfloat16 g_wrhi[(size_t)G4 * H];      // gate-interleaved Whh hi
__device__ __nv_bfloat16 g_wrlo[(size_t)G4 * H];      // gate-interleaved Whh lo

// ---------------- PTX helpers (portable sm_80+ PTX) --------------------------
__device__ __forceinline__ uint32_t smem_u32(const void* p) {
    uint32_t a;
    asm("{ .reg .u64 t; cvta.to.shared.u64 t, %1; cvt.u32.u64 %0, t; }" : "=r"(a) : "l"(p));
    return a;
}
__device__ __forceinline__ void ldmx4(uint32_t r[4], uint32_t addr) {
    asm volatile("ldmatrix.sync.aligned.m8n8.x4.shared.b16 {%0,%1,%2,%3}, [%4];"
                 : "=r"(r[0]), "=r"(r[1]), "=r"(r[2]), "=r"(r[3]) : "r"(addr));
}
__device__ __forceinline__ void mma16816(float d[4], const uint32_t a[4], const uint32_t b[2]) {
    asm volatile("mma.sync.aligned.m16n8k16.row.col.f32.bf16.bf16.f32 "
                 "{%0,%1,%2,%3}, {%4,%5,%6,%7}, {%8,%9}, {%0,%1,%2,%3};"
                 : "+f"(d[0]), "+f"(d[1]), "+f"(d[2]), "+f"(d[3])
                 : "r"(a[0]), "r"(a[1]), "r"(a[2]), "r"(a[3]), "r"(b[0]), "r"(b[1]));
}

// ---------------- small kernels ----------------------------------------------
__global__ void lengths_kernel(const int* __restrict__ mask) {
    int b = blockIdx.x;
    int v = mask[b * T + threadIdx.x];
#pragma unroll
    for (int o = 16; o > 0; o >>= 1) v += __shfl_down_sync(0xffffffffu, v, o);
    __shared__ int sh[4];
    if ((threadIdx.x & 31) == 0) sh[threadIdx.x >> 5] = v;
    __syncthreads();
    if (threadIdx.x == 0) g_len[b] = sh[0] + sh[1] + sh[2] + sh[3];
}

__global__ void embed_kernel(const int* __restrict__ ids, const float* __restrict__ emb) {
    int r = blockIdx.x;
    int id = __ldg(&ids[r]);
    const float4* s = reinterpret_cast<const float4*>(emb) + (size_t)id * (E / 4);
    float4* d = reinterpret_cast<float4*>(g_x) + (size_t)r * (E / 4);
    d[threadIdx.x] = s[threadIdx.x];
}

__global__ void zero_hc() {
    int i = blockIdx.x * blockDim.x + threadIdx.x;
    if (i < B * H) {
        g_h[0][i] = 0.f; g_h[1][i] = 0.f; g_c[i] = 0.f;
        __nv_bfloat16 z = __float2bfloat16(0.f);
        g_hbf[0][0][i] = z; g_hbf[0][1][i] = z;
        g_hbf[1][0][i] = z; g_hbf[1][1][i] = z;
    }
}

// split fp32 -> bf16 hi + lo. mode 0: g_x -> g_xhi/g_xlo; mode 1: W -> g_whi/g_wlo
__global__ void convert_kernel(const float* __restrict__ wsrc, int mode, int n4) {
    int i = blockIdx.x * blockDim.x + threadIdx.x;
    if (i >= n4) return;
    const float* src = (mode == 0) ? g_x : wsrc;
    __nv_bfloat16* hi = (mode == 0) ? g_xhi : g_whi;
    __nv_bfloat16* lo = (mode == 0) ? g_xlo : g_wlo;
    float4 v = reinterpret_cast<const float4*>(src)[i];
    __nv_bfloat16 h0 = __float2bfloat16(v.x), h1 = __float2bfloat16(v.y);
    __nv_bfloat16 h2 = __float2bfloat16(v.z), h3 = __float2bfloat16(v.w);
    __nv_bfloat16 l0 = __float2bfloat16(v.x - __bfloat162float(h0));
    __nv_bfloat16 l1 = __float2bfloat16(v.y - __bfloat162float(h1));
    __nv_bfloat16 l2 = __float2bfloat16(v.z - __bfloat162float(h2));
    __nv_bfloat16 l3 = __float2bfloat16(v.w - __bfloat162float(h3));
    __nv_bfloat162* hp = reinterpret_cast<__nv_bfloat162*>(hi) + 2 * i;
    __nv_bfloat162* lp = reinterpret_cast<__nv_bfloat162*>(lo) + 2 * i;
    hp[0] = __nv_bfloat162(h0, h1); hp[1] = __nv_bfloat162(h2, h3);
    lp[0] = __nv_bfloat162(l0, l1); lp[1] = __nv_bfloat162(l2, l3);
}

// gate-interleave + split Whh: out row 4j+g = Whh[g*H+j], bf16 hi/lo
__global__ void reorder_whh(const float* __restrict__ Whh) {
    int r = blockIdx.x;                 // 0..4095
    int j = r >> 2, g = r & 3;
    const float4* src = reinterpret_cast<const float4*>(Whh + (size_t)(g * H + j) * H);
    int i = threadIdx.x;                // 256 threads, 4 floats each
    float4 v = src[i];
    __nv_bfloat16 h0 = __float2bfloat16(v.x), h1 = __float2bfloat16(v.y);
    __nv_bfloat16 h2 = __float2bfloat16(v.z), h3 = __float2bfloat16(v.w);
    __nv_bfloat162* hp = reinterpret_cast<__nv_bfloat162*>(g_wrhi + (size_t)r * H) + 2 * i;
    __nv_bfloat162* lp = reinterpret_cast<__nv_bfloat162*>(g_wrlo + (size_t)r * H) + 2 * i;
    hp[0] = __nv_bfloat162(h0, h1); hp[1] = __nv_bfloat162(h2, h3);
    lp[0] = __nv_bfloat162(__float2bfloat16(v.x - __bfloat162float(h0)),
                           __float2bfloat16(v.y - __bfloat162float(h1)));
    lp[1] = __nv_bfloat162(__float2bfloat16(v.z - __bfloat162float(h2)),
                           __float2bfloat16(v.w - __bfloat162float(h3)));
}

// ---------------- split-bf16 tensor-core GEMM (unchanged, known good) -------
#define SSTR 40
__global__ void __launch_bounds__(256, 1) mma_gemm(
    float* __restrict__ Cout, const float* __restrict__ b1,
    const float* __restrict__ b2, int Ncols, int ldc, int mode)
{
    __shared__ __nv_bfloat16 sAh[128 * SSTR];
    __shared__ __nv_bfloat16 sAl[128 * SSTR];
    __shared__ __nv_bfloat16 sBh[128 * SSTR];
    __shared__ __nv_bfloat16 sBl[128 * SSTR];

    float* __restrict__ C = (mode == 0) ? g_gx : Cout;

    const int tid  = threadIdx.x;
    const int wid  = tid >> 5;
    const int lane = tid & 31;
    const int row0 = blockIdx.y * 128;
    const int col0 = blockIdx.x * 128;
    const int wm0  = (wid >> 2) * 64;
    const int wn0  = (wid & 3) * 32;

    const uint32_t baseAh = smem_u32(sAh);
    const uint32_t baseAl = smem_u32(sAl);
    const uint32_t baseBh = smem_u32(sBh);
    const uint32_t baseBl = smem_u32(sBl);

    float acc[4][4][4];
#pragma unroll
    for (int mi = 0; mi < 4; mi++)
#pragma unroll
        for (int ni = 0; ni < 4; ni++)
#pragma unroll
            for (int q = 0; q < 4; q++) acc[mi][ni][q] = 0.f;

    const int r_s[2] = { (0 * 256 + tid) >> 2, (1 * 256 + tid) >> 2 };
    const int g_s[2] = { tid & 3, tid & 3 };
    const uint4 zero4 = make_uint4(0, 0, 0, 0);

    uint4 pAh[2], pAl[2], pBh[2], pBl[2];

    auto prefetch = [&](int kb) {
#pragma unroll
        for (int s = 0; s < 2; s++) {
            int r = r_s[s], g = g_s[s];
            size_t ga = (size_t)(row0 + r) * KDIM + kb + g * 8;
            pAh[s] = *reinterpret_cast<const uint4*>(g_xhi + ga);
            pAl[s] = *reinterpret_cast<const uint4*>(g_xlo + ga);
            int n = col0 + r;
            if (n < Ncols) {
                size_t gb = (size_t)n * KDIM + kb + g * 8;
                pBh[s] = *reinterpret_cast<const uint4*>(g_whi + gb);
                pBl[s] = *reinterpret_cast<const uint4*>(g_wlo + gb);
            } else { pBh[s] = zero4; pBl[s] = zero4; }
        }
    };

    prefetch(0);

    for (int ch = 0; ch < KDIM / 32; ch++) {
        __syncthreads();
#pragma unroll
        for (int s = 0; s < 2; s++) {
            int r = r_s[s], g = g_s[s];
            int so = r * SSTR + g * 8;
            *reinterpret_cast<uint4*>(sAh + so) = pAh[s];
            *reinterpret_cast<uint4*>(sAl + so) = pAl[s];
            *reinterpret_cast<uint4*>(sBh + so) = pBh[s];
            *reinterpret_cast<uint4*>(sBl + so) = pBl[s];
        }
        __syncthreads();

        if (ch + 1 < KDIM / 32) prefetch((ch + 1) * 32);

#pragma unroll
        for (int ks = 0; ks < 2; ks++) {
            uint32_t Ah[4][4], Al[4][4], Bh[4][2], Bl[4][2];
            {
                int arow = wm0 + (lane & 7) + ((lane >> 3) & 1) * 8;
                int acol = ks * 16 + (lane >> 4) * 8;
#pragma unroll
                for (int mi = 0; mi < 4; mi++) {
                    uint32_t off = (uint32_t)(((arow + mi * 16) * SSTR + acol) * 2);
                    ldmx4(Ah[mi], baseAh + off);
                    ldmx4(Al[mi], baseAl + off);
                }
            }
            {
                int brow = wn0 + (lane & 7) + ((lane >> 4) & 1) * 8;
                int bcol = ks * 16 + ((lane >> 3) & 1) * 8;
#pragma unroll
                for (int p = 0; p < 2; p++) {
                    uint32_t off = (uint32_t)(((brow + p * 16) * SSTR + bcol) * 2);
                    uint32_t rbh[4], rbl[4];
                    ldmx4(rbh, baseBh + off);
                    ldmx4(rbl, baseBl + off);
                    Bh[2 * p][0] = rbh[0]; Bh[2 * p][1] = rbh[1];
                    Bh[2 * p + 1][0] = rbh[2]; Bh[2 * p + 1][1] = rbh[3];
                    Bl[2 * p][0] = rbl[0]; Bl[2 * p][1] = rbl[1];
                    Bl[2 * p + 1][0] = rbl[2]; Bl[2 * p + 1][1] = rbl[3];
                }
            }
#pragma unroll
            for (int mi = 0; mi < 4; mi++)
#pragma unroll
                for (int ni = 0; ni < 4; ni++) {
                    mma16816(acc[mi][ni], Ah[mi], Bh[ni]);
                    mma16816(acc[mi][ni], Ah[mi], Bl[ni]);
                    mma16816(acc[mi][ni], Al[mi], Bh[ni]);
                }
        }
    }

#pragma unroll
    for (int ni = 0; ni < 4; ni++) {
        int col = col0 + wn0 + ni * 8 + (lane & 3) * 2;
        if (col >= Ncols) continue;
        float bx = b1[col], by = b1[col + 1];
        if (b2) { bx += b2[col]; by += b2[col + 1]; }
#pragma unroll
        for (int mi = 0; mi < 4; mi++) {
            int row = row0 + wm0 + mi * 16 + (lane >> 2);
            float2 v0 = make_float2(acc[mi][ni][0] + bx, acc[mi][ni][1] + by);
            float2 v1 = make_float2(acc[mi][ni][2] + bx, acc[mi][ni][3] + by);
            *reinterpret_cast<float2*>(&C[(size_t)row * ldc + col])       = v0;
            *reinterpret_cast<float2*>(&C[(size_t)(row + 8) * ldc + col]) = v1;
        }
    }
}

// ---------------- tensor-core fused LSTM step --------------------------------
// 128 CTAs x 128 threads. CTA jblk: gate tile = 64 batches x 32 reordered cols
// (rows [32*jblk, +32) of Whh_r = all 4 gates of h-cols [8*jblk, +8)).
// K = 1024 in chunks of 32; 3-pass bf16 hi/lo mma; fused cell update epilogue.
__global__ void __launch_bounds__(128) tc_step(int t)
{
    __shared__ __nv_bfloat16 sAh[64 * SSTR];
    __shared__ __nv_bfloat16 sAl[64 * SSTR];
    __shared__ __nv_bfloat16 sBh[32 * SSTR];
    __shared__ __nv_bfloat16 sBl[32 * SSTR];
    __shared__ float Ssm[64][36];

    const int tid  = threadIdx.x;
    const int wid  = tid >> 5;
    const int lane = tid & 31;
    const int jblk = blockIdx.x;

    const __nv_bfloat16* __restrict__ hbh = g_hbf[t & 1][0];
    const __nv_bfloat16* __restrict__ hbl = g_hbf[t & 1][1];

    const uint32_t baseAh = smem_u32(sAh);
    const uint32_t baseAl = smem_u32(sAl);
    const uint32_t baseBh = smem_u32(sBh);
    const uint32_t baseBl = smem_u32(sBl);

    float acc[4][4];
#pragma unroll
    for (int ni = 0; ni < 4; ni++)
#pragma unroll
        for (int q = 0; q < 4; q++) acc[ni][q] = 0.f;

    // copy slots: A hi/lo 256 uint4 each over 2 sub-slots; B hi/lo 128 each
    uint4 pf[6];
    auto prefetch = [&](int kb) {
#pragma unroll
        for (int s = 0; s < 2; s++) {
            int idx = s * 128 + tid;
            int r = idx >> 2, q = idx & 3;
            size_t ga = (size_t)r * H + kb + q * 8;
            pf[s]     = *reinterpret_cast<const uint4*>(hbh + ga);
            pf[s + 2] = *reinterpret_cast<const uint4*>(hbl + ga);
        }
        {
            int r = tid >> 2, q = tid & 3;
            size_t gb = (size_t)(jblk * 32 + r) * H + kb + q * 8;
            pf[4] = *reinterpret_cast<const uint4*>(g_wrhi + gb);
            pf[5] = *reinterpret_cast<const uint4*>(g_wrlo + gb);
        }
    };

    prefetch(0);

    for (int ch = 0; ch < KDIM / 32; ch++) {
        __syncthreads();
#pragma unroll
        for (int s = 0; s < 2; s++) {
            int idx = s * 128 + tid;
            int r = idx >> 2, q = idx & 3;
            int so = r * SSTR + q * 8;
            *reinterpret_cast<uint4*>(sAh + so) = pf[s];
            *reinterpret_cast<uint4*>(sAl + so) = pf[s + 2];
        }
        {
            int r = tid >> 2, q = tid & 3;
            int so = r * SSTR + q * 8;
            *reinterpret_cast<uint4*>(sBh + so) = pf[4];
            *reinterpret_cast<uint4*>(sBl + so) = pf[5];
        }
        __syncthreads();

        if (ch + 1 < KDIM / 32) prefetch((ch + 1) * 32);

#pragma unroll
        for (int ks = 0; ks < 2; ks++) {
            uint32_t Ah[4], Al[4], Bh[4][2], Bl[4][2];
            {
                int arow = wid * 16 + (lane & 7) + ((lane >> 3) & 1) * 8;
                int acol = ks * 16 + (lane >> 4) * 8;
                uint32_t off = (uint32_t)((arow * SSTR + acol) * 2);
                ldmx4(Ah, baseAh + off);
                ldmx4(Al, baseAl + off);
            }
            {
                int brow = (lane & 7) + ((lane >> 4) & 1) * 8;
                int bcol = ks * 16 + ((lane >> 3) & 1) * 8;
#pragma unroll
                for (int p = 0; p < 2; p++) {
                    uint32_t off = (uint32_t)(((brow + p * 16) * SSTR + bcol) * 2);
                    uint32_t rbh[4], rbl[4];
                    ldmx4(rbh, baseBh + off);
                    ldmx4(rbl, baseBl + off);
                    Bh[2 * p][0] = rbh[0]; Bh[2 * p][1] = rbh[1];
                    Bh[2 * p + 1][0] = rbh[2]; Bh[2 * p + 1][1] = rbh[3];
                    Bl[2 * p][0] = rbl[0]; Bl[2 * p][1] = rbl[1];
                    Bl[2 * p + 1][0] = rbl[2]; Bl[2 * p + 1][1] = rbl[3];
                }
            }
#pragma unroll
            for (int ni = 0; ni < 4; ni++) {
                mma16816(acc[ni], Ah, Bh[ni]);
                mma16816(acc[ni], Ah, Bl[ni]);
                mma16816(acc[ni], Al, Bh[ni]);
            }
        }
    }

    // stage gate tile to smem
    {
        int row = wid * 16 + (lane >> 2);
        int cc  = (lane & 3) * 2;
#pragma unroll
        for (int ni = 0; ni < 4; ni++) {
            int c = ni * 8 + cc;
            Ssm[row][c]         = acc[ni][0];
            Ssm[row][c + 1]     = acc[ni][1];
            Ssm[row + 8][c]     = acc[ni][2];
            Ssm[row + 8][c + 1] = acc[ni][3];
        }
    }
    __syncthreads();

    // cell update: 512 (b, jl) pairs, 4 per thread
    const float* __restrict__ hin  = g_h[t & 1];
    float* __restrict__       hout = g_h[(t + 1) & 1];
    __nv_bfloat16* __restrict__ hbho = g_hbf[(t + 1) & 1][0];
    __nv_bfloat16* __restrict__ hblo = g_hbf[(t + 1) & 1][1];

#pragma unroll
    for (int ii = 0; ii < 4; ii++) {
        int idx = ii * 128 + tid;
        int b = idx >> 3, jl = idx & 7;
        int j = jblk * 8 + jl;
        size_t gr = ((size_t)b * T + t) * G4;
        float iv = Ssm[b][4 * jl + 0] + g_gx[gr + j];
        float fv = Ssm[b][4 * jl + 1] + g_gx[gr + H + j];
        float gv = Ssm[b][4 * jl + 2] + g_gx[gr + 2 * H + j];
        float ov = Ssm[b][4 * jl + 3] + g_gx[gr + 3 * H + j];

        float c_old = g_c[b * H + j];
        float h_old = hin[b * H + j];

        float si = 1.f / (1.f + expf(-iv));
        float sf = 1.f / (1.f + expf(-fv));
        float so = 1.f / (1.f + expf(-ov));
        float cn = fmaf(sf, c_old, si * tanhf(gv));
        float hn = so * tanhf(cn);

        bool ok = t < g_len[b];
        float cw = ok ? cn : c_old;
        float hw = ok ? hn : h_old;
        g_c[b * H + j]  = cw;
        hout[b * H + j] = hw;
        __nv_bfloat16 hh = __float2bfloat16(hw);
        hbho[b * H + j] = hh;
        hblo[b * H + j] = __float2bfloat16(hw - __bfloat162float(hh));
        g_x[((size_t)b * T + t) * E + j] = ok ? hn : 0.f;
    }
}

__global__ void copy_states_kernel(float* __restrict__ hs_out, float* __restrict__ cs_out) {
    int i = blockIdx.x * blockDim.x + threadIdx.x;
    if (i < B * H) {
        hs_out[i] = g_h[0][i];   // T=128 even: final h in buffer 0
        cs_out[i] = g_c[i];
    }
}

// ---------------- launch ------------------------------------------------------
extern "C" void kernel_launch(void* const* d_in, const int* in_sizes, int n_in,
                              void* d_out, int out_size)
{
    const int*   ids  = (const int*)d_in[0];
    const int*   mask = (const int*)d_in[1];
    const float* emb  = (const float*)d_in[2];
    const float* Wih  = (const float*)d_in[3];
    const float* Whh  = (const float*)d_in[4];
    const float* bih  = (const float*)d_in[5];
    const float* bhh  = (const float*)d_in[6];
    const float* fcw  = (const float*)d_in[7];
    const float* fcb  = (const float*)d_in[8];
    float* out = (float*)d_out;

    lengths_kernel<<<B, T>>>(mask);
    embed_kernel<<<B * T, E / 4>>>(ids, emb);

    const size_t HS_OFF = (size_t)B * T * V;
    const size_t CS_OFF = HS_OFF + (size_t)L * B * H;
    const int X4 = B * T * E / 4;

    for (int l = 0; l < L; l++) {
        convert_kernel<<<(X4 + 255) / 256, 256>>>(nullptr, 0, X4);
        const int W4 = G4 * E / 4;
        convert_kernel<<<(W4 + 255) / 256, 256>>>(Wih + (size_t)l * G4 * E, 1, W4);

        mma_gemm<<<dim3(G4 / 128, (B * T) / 128), 256>>>(
            nullptr, bih + (size_t)l * G4, bhh + (size_t)l * G4, G4, G4, /*mode=*/0);

        reorder_whh<<<G4, 256>>>(Whh + (size_t)l * G4 * H);
        zero_hc<<<(B * H + 511) / 512, 512>>>();

        for (int t = 0; t < T; t++)
            tc_step<<<128, 128>>>(t);

        copy_states_kernel<<<(B * H + 511) / 512, 512>>>(
            out + HS_OFF + (size_t)l * B * H,
            out + CS_OFF + (size_t)l * B * H);
    }

    convert_kernel<<<(X4 + 255) / 256, 256>>>(nullptr, 0, X4);
    const int F4 = V * H / 4;
    convert_kernel<<<(F4 + 255) / 256, 256>>>(fcw, 1, F4);

    mma_gemm<<<dim3((V + 127) / 128, (B * T) / 128), 256>>>(
        out, fcb, nullptr, V, V, /*mode=*/1);
}

// round 6
// speedup vs baseline: 5.5673x; 1.1935x over previous
#include <cuda_runtime.h>
#include <cuda_bf16.h>
#include <math.h>
#include <stdint.h>

#define B 64
#define T 128
#define V 10000
#define E 1024
#define H 1024
#define G4 4096
#define L 2
#define KDIM 1024

// ---------------- scratch (device globals) ----------------------------------
__device__ float g_x[(size_t)B * T * E];
__device__ float g_gx[(size_t)B * T * G4];
__device__ float g_h[2][B * H];
__device__ float g_c[B * H];
__device__ int   g_len[B];
__device__ unsigned g_bar;
__device__ __nv_bfloat16 g_xhi[(size_t)B * T * E];
__device__ __nv_bfloat16 g_xlo[(size_t)B * T * E];
__device__ __nv_bfloat16 g_whi[(size_t)V * H];
__device__ __nv_bfloat16 g_wlo[(size_t)V * H];
__device__ __nv_bfloat16 g_hbf[2][2][B * H];          // [pingpong][hi/lo]
__device__ __nv_bfloat16 g_wrhi[(size_t)G4 * H];      // gate-interleaved Whh hi
__device__ __nv_bfloat16 g_wrlo[(size_t)G4 * H];      // gate-interleaved Whh lo

// ---------------- PTX helpers (portable sm_80+ PTX) --------------------------
__device__ __forceinline__ uint32_t smem_u32(const void* p) {
    uint32_t a;
    asm("{ .reg .u64 t; cvta.to.shared.u64 t, %1; cvt.u32.u64 %0, t; }" : "=r"(a) : "l"(p));
    return a;
}
__device__ __forceinline__ void ldmx4(uint32_t r[4], uint32_t addr) {
    asm volatile("ldmatrix.sync.aligned.m8n8.x4.shared.b16 {%0,%1,%2,%3}, [%4];"
                 : "=r"(r[0]), "=r"(r[1]), "=r"(r[2]), "=r"(r[3]) : "r"(addr));
}
__device__ __forceinline__ void mma16816(float d[4], const uint32_t a[4], const uint32_t b[2]) {
    asm volatile("mma.sync.aligned.m16n8k16.row.col.f32.bf16.bf16.f32 "
                 "{%0,%1,%2,%3}, {%4,%5,%6,%7}, {%8,%9}, {%0,%1,%2,%3};"
                 : "+f"(d[0]), "+f"(d[1]), "+f"(d[2]), "+f"(d[3])
                 : "r"(a[0]), "r"(a[1]), "r"(a[2]), "r"(a[3]), "r"(b[0]), "r"(b[1]));
}

// ---------------- small kernels ----------------------------------------------
__global__ void lengths_kernel(const int* __restrict__ mask) {
    int b = blockIdx.x;
    int v = mask[b * T + threadIdx.x];
#pragma unroll
    for (int o = 16; o > 0; o >>= 1) v += __shfl_down_sync(0xffffffffu, v, o);
    __shared__ int sh[4];
    if ((threadIdx.x & 31) == 0) sh[threadIdx.x >> 5] = v;
    __syncthreads();
    if (threadIdx.x == 0) g_len[b] = sh[0] + sh[1] + sh[2] + sh[3];
}

__global__ void embed_kernel(const int* __restrict__ ids, const float* __restrict__ emb) {
    int r = blockIdx.x;
    int id = __ldg(&ids[r]);
    const float4* s = reinterpret_cast<const float4*>(emb) + (size_t)id * (E / 4);
    float4* d = reinterpret_cast<float4*>(g_x) + (size_t)r * (E / 4);
    d[threadIdx.x] = s[threadIdx.x];
}

__global__ void zero_hc() {
    int i = blockIdx.x * blockDim.x + threadIdx.x;
    if (i == 0) g_bar = 0u;
    if (i < B * H) {
        g_h[0][i] = 0.f; g_h[1][i] = 0.f; g_c[i] = 0.f;
        __nv_bfloat16 z = __float2bfloat16(0.f);
        g_hbf[0][0][i] = z; g_hbf[0][1][i] = z;
        g_hbf[1][0][i] = z; g_hbf[1][1][i] = z;
    }
}

// split fp32 -> bf16 hi + lo. mode 0: g_x -> g_xhi/g_xlo; mode 1: W -> g_whi/g_wlo
__global__ void convert_kernel(const float* __restrict__ wsrc, int mode, int n4) {
    int i = blockIdx.x * blockDim.x + threadIdx.x;
    if (i >= n4) return;
    const float* src = (mode == 0) ? g_x : wsrc;
    __nv_bfloat16* hi = (mode == 0) ? g_xhi : g_whi;
    __nv_bfloat16* lo = (mode == 0) ? g_xlo : g_wlo;
    float4 v = reinterpret_cast<const float4*>(src)[i];
    __nv_bfloat16 h0 = __float2bfloat16(v.x), h1 = __float2bfloat16(v.y);
    __nv_bfloat16 h2 = __float2bfloat16(v.z), h3 = __float2bfloat16(v.w);
    __nv_bfloat16 l0 = __float2bfloat16(v.x - __bfloat162float(h0));
    __nv_bfloat16 l1 = __float2bfloat16(v.y - __bfloat162float(h1));
    __nv_bfloat16 l2 = __float2bfloat16(v.z - __bfloat162float(h2));
    __nv_bfloat16 l3 = __float2bfloat16(v.w - __bfloat162float(h3));
    __nv_bfloat162* hp = reinterpret_cast<__nv_bfloat162*>(hi) + 2 * i;
    __nv_bfloat162* lp = reinterpret_cast<__nv_bfloat162*>(lo) + 2 * i;
    hp[0] = __nv_bfloat162(h0, h1); hp[1] = __nv_bfloat162(h2, h3);
    lp[0] = __nv_bfloat162(l0, l1); lp[1] = __nv_bfloat162(l2, l3);
}

// gate-interleave + split Whh: out row 4j+g = Whh[g*H+j], bf16 hi/lo
__global__ void reorder_whh(const float* __restrict__ Whh) {
    int r = blockIdx.x;
    int j = r >> 2, g = r & 3;
    const float4* src = reinterpret_cast<const float4*>(Whh + (size_t)(g * H + j) * H);
    int i = threadIdx.x;
    float4 v = src[i];
    __nv_bfloat16 h0 = __float2bfloat16(v.x), h1 = __float2bfloat16(v.y);
    __nv_bfloat16 h2 = __float2bfloat16(v.z), h3 = __float2bfloat16(v.w);
    __nv_bfloat162* hp = reinterpret_cast<__nv_bfloat162*>(g_wrhi + (size_t)r * H) + 2 * i;
    __nv_bfloat162* lp = reinterpret_cast<__nv_bfloat162*>(g_wrlo + (size_t)r * H) + 2 * i;
    hp[0] = __nv_bfloat162(h0, h1); hp[1] = __nv_bfloat162(h2, h3);
    lp[0] = __nv_bfloat162(__float2bfloat16(v.x - __bfloat162float(h0)),
                           __float2bfloat16(v.y - __bfloat162float(h1)));
    lp[1] = __nv_bfloat162(__float2bfloat16(v.z - __bfloat162float(h2)),
                           __float2bfloat16(v.w - __bfloat162float(h3)));
}

// ---------------- split-bf16 tensor-core GEMM (unchanged, known good) -------
#define SSTR 40
__global__ void __launch_bounds__(256, 1) mma_gemm(
    float* __restrict__ Cout, const float* __restrict__ b1,
    const float* __restrict__ b2, int Ncols, int ldc, int mode)
{
    __shared__ __nv_bfloat16 sAh[128 * SSTR];
    __shared__ __nv_bfloat16 sAl[128 * SSTR];
    __shared__ __nv_bfloat16 sBh[128 * SSTR];
    __shared__ __nv_bfloat16 sBl[128 * SSTR];

    float* __restrict__ C = (mode == 0) ? g_gx : Cout;

    const int tid  = threadIdx.x;
    const int wid  = tid >> 5;
    const int lane = tid & 31;
    const int row0 = blockIdx.y * 128;
    const int col0 = blockIdx.x * 128;
    const int wm0  = (wid >> 2) * 64;
    const int wn0  = (wid & 3) * 32;

    const uint32_t baseAh = smem_u32(sAh);
    const uint32_t baseAl = smem_u32(sAl);
    const uint32_t baseBh = smem_u32(sBh);
    const uint32_t baseBl = smem_u32(sBl);

    float acc[4][4][4];
#pragma unroll
    for (int mi = 0; mi < 4; mi++)
#pragma unroll
        for (int ni = 0; ni < 4; ni++)
#pragma unroll
            for (int q = 0; q < 4; q++) acc[mi][ni][q] = 0.f;

    const int r_s[2] = { (0 * 256 + tid) >> 2, (1 * 256 + tid) >> 2 };
    const int g_s[2] = { tid & 3, tid & 3 };
    const uint4 zero4 = make_uint4(0, 0, 0, 0);

    uint4 pAh[2], pAl[2], pBh[2], pBl[2];

    auto prefetch = [&](int kb) {
#pragma unroll
        for (int s = 0; s < 2; s++) {
            int r = r_s[s], g = g_s[s];
            size_t ga = (size_t)(row0 + r) * KDIM + kb + g * 8;
            pAh[s] = *reinterpret_cast<const uint4*>(g_xhi + ga);
            pAl[s] = *reinterpret_cast<const uint4*>(g_xlo + ga);
            int n = col0 + r;
            if (n < Ncols) {
                size_t gb = (size_t)n * KDIM + kb + g * 8;
                pBh[s] = *reinterpret_cast<const uint4*>(g_whi + gb);
                pBl[s] = *reinterpret_cast<const uint4*>(g_wlo + gb);
            } else { pBh[s] = zero4; pBl[s] = zero4; }
        }
    };

    prefetch(0);

    for (int ch = 0; ch < KDIM / 32; ch++) {
        __syncthreads();
#pragma unroll
        for (int s = 0; s < 2; s++) {
            int r = r_s[s], g = g_s[s];
            int so = r * SSTR + g * 8;
            *reinterpret_cast<uint4*>(sAh + so) = pAh[s];
            *reinterpret_cast<uint4*>(sAl + so) = pAl[s];
            *reinterpret_cast<uint4*>(sBh + so) = pBh[s];
            *reinterpret_cast<uint4*>(sBl + so) = pBl[s];
        }
        __syncthreads();

        if (ch + 1 < KDIM / 32) prefetch((ch + 1) * 32);

#pragma unroll
        for (int ks = 0; ks < 2; ks++) {
            uint32_t Ah[4][4], Al[4][4], Bh[4][2], Bl[4][2];
            {
                int arow = wm0 + (lane & 7) + ((lane >> 3) & 1) * 8;
                int acol = ks * 16 + (lane >> 4) * 8;
#pragma unroll
                for (int mi = 0; mi < 4; mi++) {
                    uint32_t off = (uint32_t)(((arow + mi * 16) * SSTR + acol) * 2);
                    ldmx4(Ah[mi], baseAh + off);
                    ldmx4(Al[mi], baseAl + off);
                }
            }
            {
                int brow = wn0 + (lane & 7) + ((lane >> 4) & 1) * 8;
                int bcol = ks * 16 + ((lane >> 3) & 1) * 8;
#pragma unroll
                for (int p = 0; p < 2; p++) {
                    uint32_t off = (uint32_t)(((brow + p * 16) * SSTR + bcol) * 2);
                    uint32_t rbh[4], rbl[4];
                    ldmx4(rbh, baseBh + off);
                    ldmx4(rbl, baseBl + off);
                    Bh[2 * p][0] = rbh[0]; Bh[2 * p][1] = rbh[1];
                    Bh[2 * p + 1][0] = rbh[2]; Bh[2 * p + 1][1] = rbh[3];
                    Bl[2 * p][0] = rbl[0]; Bl[2 * p][1] = rbl[1];
                    Bl[2 * p + 1][0] = rbl[2]; Bl[2 * p + 1][1] = rbl[3];
                }
            }
#pragma unroll
            for (int mi = 0; mi < 4; mi++)
#pragma unroll
                for (int ni = 0; ni < 4; ni++) {
                    mma16816(acc[mi][ni], Ah[mi], Bh[ni]);
                    mma16816(acc[mi][ni], Ah[mi], Bl[ni]);
                    mma16816(acc[mi][ni], Al[mi], Bh[ni]);
                }
        }
    }

#pragma unroll
    for (int ni = 0; ni < 4; ni++) {
        int col = col0 + wn0 + ni * 8 + (lane & 3) * 2;
        if (col >= Ncols) continue;
        float bx = b1[col], by = b1[col + 1];
        if (b2) { bx += b2[col]; by += b2[col + 1]; }
#pragma unroll
        for (int mi = 0; mi < 4; mi++) {
            int row = row0 + wm0 + mi * 16 + (lane >> 2);
            float2 v0 = make_float2(acc[mi][ni][0] + bx, acc[mi][ni][1] + by);
            float2 v1 = make_float2(acc[mi][ni][2] + bx, acc[mi][ni][3] + by);
            *reinterpret_cast<float2*>(&C[(size_t)row * ldc + col])       = v0;
            *reinterpret_cast<float2*>(&C[(size_t)(row + 8) * ldc + col]) = v1;
        }
    }
}

// ---------------- persistent tensor-core LSTM recurrence --------------------
// One launch per layer: 128 CTAs x 128 threads, all co-resident (1 CTA/SM).
// CTA jblk holds its 32-row Whh_r slice (hi+lo) in smem for all 128 steps.
// Software grid barrier between steps.
#define WSTR 1032                 // W smem row stride (bf16): 2064B = 129x16B, !=0 mod 8
#define OFF_WH 0
#define OFF_WL (32 * WSTR * 2)                    // 66048
#define OFF_AH (OFF_WL + 32 * WSTR * 2)           // 132096
#define OFF_AL (OFF_AH + 64 * SSTR * 2)           // 137216
#define OFF_SS (OFF_AL + 64 * SSTR * 2)           // 142336
#define SMEM_P (OFF_SS + 64 * 36 * 4)             // 151552

__global__ void __launch_bounds__(128, 1) tc_persist()
{
    extern __shared__ char dsm[];
    __nv_bfloat16* sWh = reinterpret_cast<__nv_bfloat16*>(dsm + OFF_WH);
    __nv_bfloat16* sWl = reinterpret_cast<__nv_bfloat16*>(dsm + OFF_WL);
    __nv_bfloat16* sAh = reinterpret_cast<__nv_bfloat16*>(dsm + OFF_AH);
    __nv_bfloat16* sAl = reinterpret_cast<__nv_bfloat16*>(dsm + OFF_AL);
    float (*Ssm)[36]   = reinterpret_cast<float(*)[36]>(dsm + OFF_SS);

    const int tid  = threadIdx.x;
    const int wid  = tid >> 5;
    const int lane = tid & 31;
    const int jblk = blockIdx.x;

    const uint32_t baseAh = smem_u32(sAh);
    const uint32_t baseAl = smem_u32(sAl);
    const uint32_t baseWh = smem_u32(sWh);
    const uint32_t baseWl = smem_u32(sWl);

    // load W slice once: 32 rows x 1024 bf16, hi + lo
    for (int i = tid; i < 32 * 128; i += 128) {
        int r = i >> 7, q = i & 127;
        size_t gb = (size_t)(jblk * 32 + r) * H + q * 8;
        *reinterpret_cast<uint4*>(sWh + r * WSTR + q * 8) = *reinterpret_cast<const uint4*>(g_wrhi + gb);
        *reinterpret_cast<uint4*>(sWl + r * WSTR + q * 8) = *reinterpret_cast<const uint4*>(g_wrlo + gb);
    }
    __syncthreads();

    for (int t = 0; t < T; t++) {
        const __nv_bfloat16* __restrict__ hbh = g_hbf[t & 1][0];
        const __nv_bfloat16* __restrict__ hbl = g_hbf[t & 1][1];

        float acc[4][4];
#pragma unroll
        for (int ni = 0; ni < 4; ni++)
#pragma unroll
            for (int q = 0; q < 4; q++) acc[ni][q] = 0.f;

        uint4 pf[4];
        auto prefetch = [&](int kb) {
#pragma unroll
            for (int s = 0; s < 2; s++) {
                int idx = s * 128 + tid;
                int r = idx >> 2, q = idx & 3;
                size_t ga = (size_t)r * H + kb + q * 8;
                pf[s]     = *reinterpret_cast<const uint4*>(hbh + ga);
                pf[s + 2] = *reinterpret_cast<const uint4*>(hbl + ga);
            }
        };

        prefetch(0);

        for (int ch = 0; ch < KDIM / 32; ch++) {
            __syncthreads();
#pragma unroll
            for (int s = 0; s < 2; s++) {
                int idx = s * 128 + tid;
                int r = idx >> 2, q = idx & 3;
                int so = r * SSTR + q * 8;
                *reinterpret_cast<uint4*>(sAh + so) = pf[s];
                *reinterpret_cast<uint4*>(sAl + so) = pf[s + 2];
            }
            __syncthreads();

            if (ch + 1 < KDIM / 32) prefetch((ch + 1) * 32);

#pragma unroll
            for (int ks = 0; ks < 2; ks++) {
                uint32_t Ah[4], Al[4], Bh[4][2], Bl[4][2];
                {
                    int arow = wid * 16 + (lane & 7) + ((lane >> 3) & 1) * 8;
                    int acol = ks * 16 + (lane >> 4) * 8;
                    uint32_t off = (uint32_t)((arow * SSTR + acol) * 2);
                    ldmx4(Ah, baseAh + off);
                    ldmx4(Al, baseAl + off);
                }
                {
                    int brow = (lane & 7) + ((lane >> 4) & 1) * 8;
                    int bcol = ch * 32 + ks * 16 + ((lane >> 3) & 1) * 8;
#pragma unroll
                    for (int p = 0; p < 2; p++) {
                        uint32_t off = (uint32_t)(((brow + p * 16) * WSTR + bcol) * 2);
                        uint32_t rbh[4], rbl[4];
                        ldmx4(rbh, baseWh + off);
                        ldmx4(rbl, baseWl + off);
                        Bh[2 * p][0] = rbh[0]; Bh[2 * p][1] = rbh[1];
                        Bh[2 * p + 1][0] = rbh[2]; Bh[2 * p + 1][1] = rbh[3];
                        Bl[2 * p][0] = rbl[0]; Bl[2 * p][1] = rbl[1];
                        Bl[2 * p + 1][0] = rbl[2]; Bl[2 * p + 1][1] = rbl[3];
                    }
                }
#pragma unroll
                for (int ni = 0; ni < 4; ni++) {
                    mma16816(acc[ni], Ah, Bh[ni]);
                    mma16816(acc[ni], Ah, Bl[ni]);
                    mma16816(acc[ni], Al, Bh[ni]);
                }
            }
        }

        // stage gate tile to smem
        __syncthreads();
        {
            int row = wid * 16 + (lane >> 2);
            int cc  = (lane & 3) * 2;
#pragma unroll
            for (int ni = 0; ni < 4; ni++) {
                int c = ni * 8 + cc;
                Ssm[row][c]         = acc[ni][0];
                Ssm[row][c + 1]     = acc[ni][1];
                Ssm[row + 8][c]     = acc[ni][2];
                Ssm[row + 8][c + 1] = acc[ni][3];
            }
        }
        __syncthreads();

        // fused cell update
        const float* __restrict__ hin  = g_h[t & 1];
        float* __restrict__       hout = g_h[(t + 1) & 1];
        __nv_bfloat16* __restrict__ hbho = g_hbf[(t + 1) & 1][0];
        __nv_bfloat16* __restrict__ hblo = g_hbf[(t + 1) & 1][1];

#pragma unroll
        for (int ii = 0; ii < 4; ii++) {
            int idx = ii * 128 + tid;
            int b = idx >> 3, jl = idx & 7;
            int j = jblk * 8 + jl;
            size_t gr = ((size_t)b * T + t) * G4;
            float iv = Ssm[b][4 * jl + 0] + g_gx[gr + j];
            float fv = Ssm[b][4 * jl + 1] + g_gx[gr + H + j];
            float gv = Ssm[b][4 * jl + 2] + g_gx[gr + 2 * H + j];
            float ov = Ssm[b][4 * jl + 3] + g_gx[gr + 3 * H + j];

            float c_old = g_c[b * H + j];
            float h_old = hin[b * H + j];

            float si = 1.f / (1.f + expf(-iv));
            float sf = 1.f / (1.f + expf(-fv));
            float so = 1.f / (1.f + expf(-ov));
            float cn = fmaf(sf, c_old, si * tanhf(gv));
            float hn = so * tanhf(cn);

            bool ok = t < g_len[b];
            float cw = ok ? cn : c_old;
            float hw = ok ? hn : h_old;
            g_c[b * H + j]  = cw;
            hout[b * H + j] = hw;
            __nv_bfloat16 hh = __float2bfloat16(hw);
            hbho[b * H + j] = hh;
            hblo[b * H + j] = __float2bfloat16(hw - __bfloat162float(hh));
            g_x[((size_t)b * T + t) * E + j] = ok ? hn : 0.f;
        }

        // grid barrier (skip after the last step)
        if (t + 1 < T) {
            __syncthreads();
            if (tid == 0) {
                __threadfence();
                atomicAdd(&g_bar, 1u);
                unsigned tgt = (unsigned)(t + 1) * gridDim.x;
                unsigned v;
                do {
                    asm volatile("ld.acquire.gpu.u32 %0, [%1];" : "=r"(v) : "l"(&g_bar));
                    if (v >= tgt) break;
                    __nanosleep(64);
                } while (true);
            }
            __syncthreads();
        }
    }
}

__global__ void copy_states_kernel(float* __restrict__ hs_out, float* __restrict__ cs_out) {
    int i = blockIdx.x * blockDim.x + threadIdx.x;
    if (i < B * H) {
        hs_out[i] = g_h[0][i];   // T=128 even: final h in buffer 0
        cs_out[i] = g_c[i];
    }
}

// ---------------- launch ------------------------------------------------------
extern "C" void kernel_launch(void* const* d_in, const int* in_sizes, int n_in,
                              void* d_out, int out_size)
{
    const int*   ids  = (const int*)d_in[0];
    const int*   mask = (const int*)d_in[1];
    const float* emb  = (const float*)d_in[2];
    const float* Wih  = (const float*)d_in[3];
    const float* Whh  = (const float*)d_in[4];
    const float* bih  = (const float*)d_in[5];
    const float* bhh  = (const float*)d_in[6];
    const float* fcw  = (const float*)d_in[7];
    const float* fcb  = (const float*)d_in[8];
    float* out = (float*)d_out;

    cudaFuncSetAttribute(tc_persist, cudaFuncAttributeMaxDynamicSharedMemorySize, SMEM_P);

    lengths_kernel<<<B, T>>>(mask);
    embed_kernel<<<B * T, E / 4>>>(ids, emb);

    const size_t HS_OFF = (size_t)B * T * V;
    const size_t CS_OFF = HS_OFF + (size_t)L * B * H;
    const int X4 = B * T * E / 4;

    for (int l = 0; l < L; l++) {
        convert_kernel<<<(X4 + 255) / 256, 256>>>(nullptr, 0, X4);
        const int W4 = G4 * E / 4;
        convert_kernel<<<(W4 + 255) / 256, 256>>>(Wih + (size_t)l * G4 * E, 1, W4);

        mma_gemm<<<dim3(G4 / 128, (B * T) / 128), 256>>>(
            nullptr, bih + (size_t)l * G4, bhh + (size_t)l * G4, G4, G4, /*mode=*/0);

        reorder_whh<<<G4, 256>>>(Whh + (size_t)l * G4 * H);
        zero_hc<<<(B * H + 511) / 512, 512>>>();

        tc_persist<<<128, 128, SMEM_P>>>();

        copy_states_kernel<<<(B * H + 511) / 512, 512>>>(
            out + HS_OFF + (size_t)l * B * H,
            out + CS_OFF + (size_t)l * B * H);
    }

    convert_kernel<<<(X4 + 255) / 256, 256>>>(nullptr, 0, X4);
    const int F4 = V * H / 4;
    convert_kernel<<<(F4 + 255) / 256, 256>>>(fcw, 1, F4);

    mma_gemm<<<dim3((V + 127) / 128, (B * T) / 128), 256>>>(
        out, fcb, nullptr, V, V, /*mode=*/1);
}

// round 7
// speedup vs baseline: 5.7136x; 1.0263x over previous
#include <cuda_runtime.h>
#include <cuda_bf16.h>
#include <math.h>
#include <stdint.h>

#define B 64
#define T 128
#define V 10000
#define E 1024
#define H 1024
#define G4 4096
#define L 2
#define KDIM 1024

// ---------------- scratch (device globals) ----------------------------------
__device__ float g_x[(size_t)B * T * E];
__device__ float g_gx[(size_t)B * T * G4];
__device__ float g_h[2][B * H];
__device__ float g_c[B * H];
__device__ int   g_len[B];
__device__ unsigned g_bar;
__device__ __nv_bfloat16 g_xhi[(size_t)B * T * E];
__device__ __nv_bfloat16 g_xlo[(size_t)B * T * E];
__device__ __nv_bfloat16 g_whi[(size_t)V * H];
__device__ __nv_bfloat16 g_wlo[(size_t)V * H];
__device__ __nv_bfloat16 g_hbf[2][2][B * H];          // [pingpong][hi/lo]
__device__ __nv_bfloat16 g_wrhi[(size_t)G4 * H];      // gate-interleaved Whh hi
__device__ __nv_bfloat16 g_wrlo[(size_t)G4 * H];      // gate-interleaved Whh lo

// ---------------- PTX helpers (portable sm_80+ PTX) --------------------------
__device__ __forceinline__ uint32_t smem_u32(const void* p) {
    uint32_t a;
    asm("{ .reg .u64 t; cvta.to.shared.u64 t, %1; cvt.u32.u64 %0, t; }" : "=r"(a) : "l"(p));
    return a;
}
__device__ __forceinline__ void ldmx4(uint32_t r[4], uint32_t addr) {
    asm volatile("ldmatrix.sync.aligned.m8n8.x4.shared.b16 {%0,%1,%2,%3}, [%4];"
                 : "=r"(r[0]), "=r"(r[1]), "=r"(r[2]), "=r"(r[3]) : "r"(addr));
}
__device__ __forceinline__ void mma16816(float d[4], const uint32_t a[4], const uint32_t b[2]) {
    asm volatile("mma.sync.aligned.m16n8k16.row.col.f32.bf16.bf16.f32 "
                 "{%0,%1,%2,%3}, {%4,%5,%6,%7}, {%8,%9}, {%0,%1,%2,%3};"
                 : "+f"(d[0]), "+f"(d[1]), "+f"(d[2]), "+f"(d[3])
                 : "r"(a[0]), "r"(a[1]), "r"(a[2]), "r"(a[3]), "r"(b[0]), "r"(b[1]));
}
__device__ __forceinline__ void cp16(uint32_t saddr, const void* gaddr) {
    asm volatile("cp.async.ca.shared.global [%0], [%1], 16;" :: "r"(saddr), "l"(gaddr));
}
__device__ __forceinline__ void cp16z(uint32_t saddr, const void* gaddr, int nbytes) {
    asm volatile("cp.async.ca.shared.global [%0], [%1], 16, %2;"
                 :: "r"(saddr), "l"(gaddr), "r"(nbytes));
}
__device__ __forceinline__ void cp_commit() {
    asm volatile("cp.async.commit_group;" ::: "memory");
}
template <int N>
__device__ __forceinline__ void cp_wait() {
    asm volatile("cp.async.wait_group %0;" :: "n"(N) : "memory");
}

// ---------------- small kernels ----------------------------------------------
__global__ void lengths_kernel(const int* __restrict__ mask) {
    int b = blockIdx.x;
    int v = mask[b * T + threadIdx.x];
#pragma unroll
    for (int o = 16; o > 0; o >>= 1) v += __shfl_down_sync(0xffffffffu, v, o);
    __shared__ int sh[4];
    if ((threadIdx.x & 31) == 0) sh[threadIdx.x >> 5] = v;
    __syncthreads();
    if (threadIdx.x == 0) g_len[b] = sh[0] + sh[1] + sh[2] + sh[3];
}

__global__ void embed_kernel(const int* __restrict__ ids, const float* __restrict__ emb) {
    int r = blockIdx.x;
    int id = __ldg(&ids[r]);
    const float4* s = reinterpret_cast<const float4*>(emb) + (size_t)id * (E / 4);
    float4* d = reinterpret_cast<float4*>(g_x) + (size_t)r * (E / 4);
    d[threadIdx.x] = s[threadIdx.x];
}

__global__ void zero_hc() {
    int i = blockIdx.x * blockDim.x + threadIdx.x;
    if (i == 0) g_bar = 0u;
    if (i < B * H) {
        g_h[0][i] = 0.f; g_h[1][i] = 0.f; g_c[i] = 0.f;
        __nv_bfloat16 z = __float2bfloat16(0.f);
        g_hbf[0][0][i] = z; g_hbf[0][1][i] = z;
        g_hbf[1][0][i] = z; g_hbf[1][1][i] = z;
    }
}

// split fp32 -> bf16 hi + lo. mode 0: g_x -> g_xhi/g_xlo; mode 1: W -> g_whi/g_wlo
__global__ void convert_kernel(const float* __restrict__ wsrc, int mode, int n4) {
    int i = blockIdx.x * blockDim.x + threadIdx.x;
    if (i >= n4) return;
    const float* src = (mode == 0) ? g_x : wsrc;
    __nv_bfloat16* hi = (mode == 0) ? g_xhi : g_whi;
    __nv_bfloat16* lo = (mode == 0) ? g_xlo : g_wlo;
    float4 v = reinterpret_cast<const float4*>(src)[i];
    __nv_bfloat16 h0 = __float2bfloat16(v.x), h1 = __float2bfloat16(v.y);
    __nv_bfloat16 h2 = __float2bfloat16(v.z), h3 = __float2bfloat16(v.w);
    __nv_bfloat16 l0 = __float2bfloat16(v.x - __bfloat162float(h0));
    __nv_bfloat16 l1 = __float2bfloat16(v.y - __bfloat162float(h1));
    __nv_bfloat16 l2 = __float2bfloat16(v.z - __bfloat162float(h2));
    __nv_bfloat16 l3 = __float2bfloat16(v.w - __bfloat162float(h3));
    __nv_bfloat162* hp = reinterpret_cast<__nv_bfloat162*>(hi) + 2 * i;
    __nv_bfloat162* lp = reinterpret_cast<__nv_bfloat162*>(lo) + 2 * i;
    hp[0] = __nv_bfloat162(h0, h1); hp[1] = __nv_bfloat162(h2, h3);
    lp[0] = __nv_bfloat162(l0, l1); lp[1] = __nv_bfloat162(l2, l3);
}

// gate-interleave + split Whh: out row 4j+g = Whh[g*H+j], bf16 hi/lo
__global__ void reorder_whh(const float* __restrict__ Whh) {
    int r = blockIdx.x;
    int j = r >> 2, g = r & 3;
    const float4* src = reinterpret_cast<const float4*>(Whh + (size_t)(g * H + j) * H);
    int i = threadIdx.x;
    float4 v = src[i];
    __nv_bfloat16 h0 = __float2bfloat16(v.x), h1 = __float2bfloat16(v.y);
    __nv_bfloat16 h2 = __float2bfloat16(v.z), h3 = __float2bfloat16(v.w);
    __nv_bfloat162* hp = reinterpret_cast<__nv_bfloat162*>(g_wrhi + (size_t)r * H) + 2 * i;
    __nv_bfloat162* lp = reinterpret_cast<__nv_bfloat162*>(g_wrlo + (size_t)r * H) + 2 * i;
    hp[0] = __nv_bfloat162(h0, h1); hp[1] = __nv_bfloat162(h2, h3);
    lp[0] = __nv_bfloat162(__float2bfloat16(v.x - __bfloat162float(h0)),
                           __float2bfloat16(v.y - __bfloat162float(h1)));
    lp[1] = __nv_bfloat162(__float2bfloat16(v.z - __bfloat162float(h2)),
                           __float2bfloat16(v.w - __bfloat162float(h3)));
}

// ---------------- split-bf16 tensor-core GEMM, 3-stage cp.async pipeline ----
// C = x @ W^T + b1 (+ b2). CTA 128x128, 256 threads = 8 warps (2m x 4n).
// K chunks of 32; stages rotate through dynamic smem; ONE barrier per chunk.
#define SSTR 40                         // conflict-free ldmatrix stride (bf16)
#define MAT_BYTES (128 * SSTR * 2)      // 10240 B per matrix
#define STG_BYTES (4 * MAT_BYTES)       // Ah|Al|Bh|Bl = 40960 B per stage
#define NSTAGE 3
#define GEMM_SMEM (NSTAGE * STG_BYTES)  // 122880 B

__global__ void __launch_bounds__(256, 1) mma_gemm(
    float* __restrict__ Cout, const float* __restrict__ b1,
    const float* __restrict__ b2, int Ncols, int ldc, int mode)
{
    extern __shared__ char dsm[];
    float* __restrict__ C = (mode == 0) ? g_gx : Cout;

    const int tid  = threadIdx.x;
    const int wid  = tid >> 5;
    const int lane = tid & 31;
    const int row0 = blockIdx.y * 128;
    const int col0 = blockIdx.x * 128;
    const int wm0  = (wid >> 2) * 64;
    const int wn0  = (wid & 3) * 32;

    const uint32_t smem0 = smem_u32(dsm);

    // per-thread copy mapping: 2 sub-slots, r = row (0..127), q = 16B group
    const int r0t = tid >> 2, r1t = (256 + tid) >> 2;
    const int qt  = tid & 3;

    auto issue = [&](int ch) {
        const int st = ch % NSTAGE;
        const uint32_t sb = smem0 + st * STG_BYTES;
        const int kb = ch * 32;
#pragma unroll
        for (int s = 0; s < 2; s++) {
            int r = (s == 0) ? r0t : r1t;
            uint32_t so = (uint32_t)((r * SSTR + qt * 8) * 2);
            size_t ga = (size_t)(row0 + r) * KDIM + kb + qt * 8;
            cp16(sb + so,             g_xhi + ga);
            cp16(sb + MAT_BYTES + so, g_xlo + ga);
            int n = col0 + r;
            int ok = (n < Ncols) ? 16 : 0;
            size_t gb = (size_t)(ok ? n : 0) * KDIM + kb + qt * 8;
            cp16z(sb + 2 * MAT_BYTES + so, g_whi + gb, ok);
            cp16z(sb + 3 * MAT_BYTES + so, g_wlo + gb, ok);
        }
        cp_commit();
    };

    float acc[4][4][4];
#pragma unroll
    for (int mi = 0; mi < 4; mi++)
#pragma unroll
        for (int ni = 0; ni < 4; ni++)
#pragma unroll
            for (int q = 0; q < 4; q++) acc[mi][ni][q] = 0.f;

    const int NCH = KDIM / 32;
    issue(0);
    issue(1);

    for (int ch = 0; ch < NCH; ch++) {
        cp_wait<1>();          // stage ch data landed
        __syncthreads();       // all warps see it; stage ch+2's target is free

        if (ch + 2 < NCH) issue(ch + 2);

        const uint32_t sb = smem0 + (ch % NSTAGE) * STG_BYTES;
        const uint32_t baseAh = sb;
        const uint32_t baseAl = sb + MAT_BYTES;
        const uint32_t baseBh = sb + 2 * MAT_BYTES;
        const uint32_t baseBl = sb + 3 * MAT_BYTES;

#pragma unroll
        for (int ks = 0; ks < 2; ks++) {
            uint32_t Ah[4][4], Al[4][4], Bh[4][2], Bl[4][2];
            {
                int arow = wm0 + (lane & 7) + ((lane >> 3) & 1) * 8;
                int acol = ks * 16 + (lane >> 4) * 8;
#pragma unroll
                for (int mi = 0; mi < 4; mi++) {
                    uint32_t off = (uint32_t)(((arow + mi * 16) * SSTR + acol) * 2);
                    ldmx4(Ah[mi], baseAh + off);
                    ldmx4(Al[mi], baseAl + off);
                }
            }
            {
                int brow = wn0 + (lane & 7) + ((lane >> 4) & 1) * 8;
                int bcol = ks * 16 + ((lane >> 3) & 1) * 8;
#pragma unroll
                for (int p = 0; p < 2; p++) {
                    uint32_t off = (uint32_t)(((brow + p * 16) * SSTR + bcol) * 2);
                    uint32_t rbh[4], rbl[4];
                    ldmx4(rbh, baseBh + off);
                    ldmx4(rbl, baseBl + off);
                    Bh[2 * p][0] = rbh[0]; Bh[2 * p][1] = rbh[1];
                    Bh[2 * p + 1][0] = rbh[2]; Bh[2 * p + 1][1] = rbh[3];
                    Bl[2 * p][0] = rbl[0]; Bl[2 * p][1] = rbl[1];
                    Bl[2 * p + 1][0] = rbl[2]; Bl[2 * p + 1][1] = rbl[3];
                }
            }
#pragma unroll
            for (int mi = 0; mi < 4; mi++)
#pragma unroll
                for (int ni = 0; ni < 4; ni++) {
                    mma16816(acc[mi][ni], Ah[mi], Bh[ni]);
                    mma16816(acc[mi][ni], Ah[mi], Bl[ni]);
                    mma16816(acc[mi][ni], Al[mi], Bh[ni]);
                }
        }
        __syncthreads();       // done reading stage ch before it is re-filled
    }

#pragma unroll
    for (int ni = 0; ni < 4; ni++) {
        int col = col0 + wn0 + ni * 8 + (lane & 3) * 2;
        if (col >= Ncols) continue;
        float bx = b1[col], by = b1[col + 1];
        if (b2) { bx += b2[col]; by += b2[col + 1]; }
#pragma unroll
        for (int mi = 0; mi < 4; mi++) {
            int row = row0 + wm0 + mi * 16 + (lane >> 2);
            float2 v0 = make_float2(acc[mi][ni][0] + bx, acc[mi][ni][1] + by);
            float2 v1 = make_float2(acc[mi][ni][2] + bx, acc[mi][ni][3] + by);
            *reinterpret_cast<float2*>(&C[(size_t)row * ldc + col])       = v0;
            *reinterpret_cast<float2*>(&C[(size_t)(row + 8) * ldc + col]) = v1;
        }
    }
}

// ---------------- persistent tensor-core LSTM recurrence (unchanged) --------
#define WSTR 1032
#define OFF_WH 0
#define OFF_WL (32 * WSTR * 2)
#define OFF_AH (OFF_WL + 32 * WSTR * 2)
#define OFF_AL (OFF_AH + 64 * SSTR * 2)
#define OFF_SS (OFF_AL + 64 * SSTR * 2)
#define SMEM_P (OFF_SS + 64 * 36 * 4)

__global__ void __launch_bounds__(128, 1) tc_persist()
{
    extern __shared__ char dsm[];
    __nv_bfloat16* sWh = reinterpret_cast<__nv_bfloat16*>(dsm + OFF_WH);
    __nv_bfloat16* sWl = reinterpret_cast<__nv_bfloat16*>(dsm + OFF_WL);
    __nv_bfloat16* sAh = reinterpret_cast<__nv_bfloat16*>(dsm + OFF_AH);
    __nv_bfloat16* sAl = reinterpret_cast<__nv_bfloat16*>(dsm + OFF_AL);
    float (*Ssm)[36]   = reinterpret_cast<float(*)[36]>(dsm + OFF_SS);

    const int tid  = threadIdx.x;
    const int wid  = tid >> 5;
    const int lane = tid & 31;
    const int jblk = blockIdx.x;

    const uint32_t baseAh = smem_u32(sAh);
    const uint32_t baseAl = smem_u32(sAl);
    const uint32_t baseWh = smem_u32(sWh);
    const uint32_t baseWl = smem_u32(sWl);

    for (int i = tid; i < 32 * 128; i += 128) {
        int r = i >> 7, q = i & 127;
        size_t gb = (size_t)(jblk * 32 + r) * H + q * 8;
        *reinterpret_cast<uint4*>(sWh + r * WSTR + q * 8) = *reinterpret_cast<const uint4*>(g_wrhi + gb);
        *reinterpret_cast<uint4*>(sWl + r * WSTR + q * 8) = *reinterpret_cast<const uint4*>(g_wrlo + gb);
    }
    __syncthreads();

    for (int t = 0; t < T; t++) {
        const __nv_bfloat16* __restrict__ hbh = g_hbf[t & 1][0];
        const __nv_bfloat16* __restrict__ hbl = g_hbf[t & 1][1];

        float acc[4][4];
#pragma unroll
        for (int ni = 0; ni < 4; ni++)
#pragma unroll
            for (int q = 0; q < 4; q++) acc[ni][q] = 0.f;

        uint4 pf[4];
        auto prefetch = [&](int kb) {
#pragma unroll
            for (int s = 0; s < 2; s++) {
                int idx = s * 128 + tid;
                int r = idx >> 2, q = idx & 3;
                size_t ga = (size_t)r * H + kb + q * 8;
                pf[s]     = *reinterpret_cast<const uint4*>(hbh + ga);
                pf[s + 2] = *reinterpret_cast<const uint4*>(hbl + ga);
            }
        };

        prefetch(0);

        for (int ch = 0; ch < KDIM / 32; ch++) {
            __syncthreads();
#pragma unroll
            for (int s = 0; s < 2; s++) {
                int idx = s * 128 + tid;
                int r = idx >> 2, q = idx & 3;
                int so = r * SSTR + q * 8;
                *reinterpret_cast<uint4*>(sAh + so) = pf[s];
                *reinterpret_cast<uint4*>(sAl + so) = pf[s + 2];
            }
            __syncthreads();

            if (ch + 1 < KDIM / 32) prefetch((ch + 1) * 32);

#pragma unroll
            for (int ks = 0; ks < 2; ks++) {
                uint32_t Ah[4], Al[4], Bh[4][2], Bl[4][2];
                {
                    int arow = wid * 16 + (lane & 7) + ((lane >> 3) & 1) * 8;
                    int acol = ks * 16 + (lane >> 4) * 8;
                    uint32_t off = (uint32_t)((arow * SSTR + acol) * 2);
                    ldmx4(Ah, baseAh + off);
                    ldmx4(Al, baseAl + off);
                }
                {
                    int brow = (lane & 7) + ((lane >> 4) & 1) * 8;
                    int bcol = ch * 32 + ks * 16 + ((lane >> 3) & 1) * 8;
#pragma unroll
                    for (int p = 0; p < 2; p++) {
                        uint32_t off = (uint32_t)(((brow + p * 16) * WSTR + bcol) * 2);
                        uint32_t rbh[4], rbl[4];
                        ldmx4(rbh, baseWh + off);
                        ldmx4(rbl, baseWl + off);
                        Bh[2 * p][0] = rbh[0]; Bh[2 * p][1] = rbh[1];
                        Bh[2 * p + 1][0] = rbh[2]; Bh[2 * p + 1][1] = rbh[3];
                        Bl[2 * p][0] = rbl[0]; Bl[2 * p][1] = rbl[1];
                        Bl[2 * p + 1][0] = rbl[2]; Bl[2 * p + 1][1] = rbl[3];
                    }
                }
#pragma unroll
                for (int ni = 0; ni < 4; ni++) {
                    mma16816(acc[ni], Ah, Bh[ni]);
                    mma16816(acc[ni], Ah, Bl[ni]);
                    mma16816(acc[ni], Al, Bh[ni]);
                }
            }
        }

        __syncthreads();
        {
            int row = wid * 16 + (lane >> 2);
            int cc  = (lane & 3) * 2;
#pragma unroll
            for (int ni = 0; ni < 4; ni++) {
                int c = ni * 8 + cc;
                Ssm[row][c]         = acc[ni][0];
                Ssm[row][c + 1]     = acc[ni][1];
                Ssm[row + 8][c]     = acc[ni][2];
                Ssm[row + 8][c + 1] = acc[ni][3];
            }
        }
        __syncthreads();

        const float* __restrict__ hin  = g_h[t & 1];
        float* __restrict__       hout = g_h[(t + 1) & 1];
        __nv_bfloat16* __restrict__ hbho = g_hbf[(t + 1) & 1][0];
        __nv_bfloat16* __restrict__ hblo = g_hbf[(t + 1) & 1][1];

#pragma unroll
        for (int ii = 0; ii < 4; ii++) {
            int idx = ii * 128 + tid;
            int b = idx >> 3, jl = idx & 7;
            int j = jblk * 8 + jl;
            size_t gr = ((size_t)b * T + t) * G4;
            float iv = Ssm[b][4 * jl + 0] + g_gx[gr + j];
            float fv = Ssm[b][4 * jl + 1] + g_gx[gr + H + j];
            float gv = Ssm[b][4 * jl + 2] + g_gx[gr + 2 * H + j];
            float ov = Ssm[b][4 * jl + 3] + g_gx[gr + 3 * H + j];

            float c_old = g_c[b * H + j];
            float h_old = hin[b * H + j];

            float si = 1.f / (1.f + expf(-iv));
            float sf = 1.f / (1.f + expf(-fv));
            float so = 1.f / (1.f + expf(-ov));
            float cn = fmaf(sf, c_old, si * tanhf(gv));
            float hn = so * tanhf(cn);

            bool ok = t < g_len[b];
            float cw = ok ? cn : c_old;
            float hw = ok ? hn : h_old;
            g_c[b * H + j]  = cw;
            hout[b * H + j] = hw;
            __nv_bfloat16 hh = __float2bfloat16(hw);
            hbho[b * H + j] = hh;
            hblo[b * H + j] = __float2bfloat16(hw - __bfloat162float(hh));
            g_x[((size_t)b * T + t) * E + j] = ok ? hn : 0.f;
        }

        if (t + 1 < T) {
            __syncthreads();
            if (tid == 0) {
                __threadfence();
                atomicAdd(&g_bar, 1u);
                unsigned tgt = (unsigned)(t + 1) * gridDim.x;
                unsigned v;
                do {
                    asm volatile("ld.acquire.gpu.u32 %0, [%1];" : "=r"(v) : "l"(&g_bar));
                    if (v >= tgt) break;
                    __nanosleep(64);
                } while (true);
            }
            __syncthreads();
        }
    }
}

__global__ void copy_states_kernel(float* __restrict__ hs_out, float* __restrict__ cs_out) {
    int i = blockIdx.x * blockDim.x + threadIdx.x;
    if (i < B * H) {
        hs_out[i] = g_h[0][i];
        cs_out[i] = g_c[i];
    }
}

// ---------------- launch ------------------------------------------------------
extern "C" void kernel_launch(void* const* d_in, const int* in_sizes, int n_in,
                              void* d_out, int out_size)
{
    const int*   ids  = (const int*)d_in[0];
    const int*   mask = (const int*)d_in[1];
    const float* emb  = (const float*)d_in[2];
    const float* Wih  = (const float*)d_in[3];
    const float* Whh  = (const float*)d_in[4];
    const float* bih  = (const float*)d_in[5];
    const float* bhh  = (const float*)d_in[6];
    const float* fcw  = (const float*)d_in[7];
    const float* fcb  = (const float*)d_in[8];
    float* out = (float*)d_out;

    cudaFuncSetAttribute(tc_persist, cudaFuncAttributeMaxDynamicSharedMemorySize, SMEM_P);
    cudaFuncSetAttribute(mma_gemm, cudaFuncAttributeMaxDynamicSharedMemorySize, GEMM_SMEM);

    lengths_kernel<<<B, T>>>(mask);
    embed_kernel<<<B * T, E / 4>>>(ids, emb);

    const size_t HS_OFF = (size_t)B * T * V;
    const size_t CS_OFF = HS_OFF + (size_t)L * B * H;
    const int X4 = B * T * E / 4;

    for (int l = 0; l < L; l++) {
        convert_kernel<<<(X4 + 255) / 256, 256>>>(nullptr, 0, X4);
        const int W4 = G4 * E / 4;
        convert_kernel<<<(W4 + 255) / 256, 256>>>(Wih + (size_t)l * G4 * E, 1, W4);

        mma_gemm<<<dim3(G4 / 128, (B * T) / 128), 256, GEMM_SMEM>>>(
            nullptr, bih + (size_t)l * G4, bhh + (size_t)l * G4, G4, G4, /*mode=*/0);

        reorder_whh<<<G4, 256>>>(Whh + (size_t)l * G4 * H);
        zero_hc<<<(B * H + 511) / 512, 512>>>();

        tc_persist<<<128, 128, SMEM_P>>>();

        copy_states_kernel<<<(B * H + 511) / 512, 512>>>(
            out + HS_OFF + (size_t)l * B * H,
            out + CS_OFF + (size_t)l * B * H);
    }

    convert_kernel<<<(X4 + 255) / 256, 256>>>(nullptr, 0, X4);
    const int F4 = V * H / 4;
    convert_kernel<<<(F4 + 255) / 256, 256>>>(fcw, 1, F4);

    mma_gemm<<<dim3((V + 127) / 128, (B * T) / 128), 256, GEMM_SMEM>>>(
        out, fcb, nullptr, V, V, /*mode=*/1);
}

// round 9
// speedup vs baseline: 6.0516x; 1.0591x over previous
#include <cuda_runtime.h>
#include <cuda_bf16.h>
#include <math.h>
#include <stdint.h>

#define B 64
#define T 128
#define V 10000
#define E 1024
#define H 1024
#define G4 4096
#define L 2
#define KDIM 1024

// ---------------- scratch (device globals) ----------------------------------
__device__ float g_x[(size_t)B * T * E];
__device__ float g_gx[(size_t)B * T * G4];
__device__ float g_h[2][B * H];
__device__ float g_c[B * H];
__device__ int   g_len[B];
__device__ unsigned g_bar;
__device__ __nv_bfloat16 g_xhi[(size_t)B * T * E];
__device__ __nv_bfloat16 g_xlo[(size_t)B * T * E];
__device__ __nv_bfloat16 g_whi[(size_t)V * H];
__device__ __nv_bfloat16 g_wlo[(size_t)V * H];
__device__ __nv_bfloat16 g_hbf[2][2][B * H];
__device__ __nv_bfloat16 g_wrhi[(size_t)G4 * H];
__device__ __nv_bfloat16 g_wrlo[(size_t)G4 * H];

// ---------------- PTX helpers (portable sm_80+ PTX) --------------------------
__device__ __forceinline__ uint32_t smem_u32(const void* p) {
    uint32_t a;
    asm("{ .reg .u64 t; cvta.to.shared.u64 t, %1; cvt.u32.u64 %0, t; }" : "=r"(a) : "l"(p));
    return a;
}
__device__ __forceinline__ void ldmx4(uint32_t r[4], uint32_t addr) {
    asm volatile("ldmatrix.sync.aligned.m8n8.x4.shared.b16 {%0,%1,%2,%3}, [%4];"
                 : "=r"(r[0]), "=r"(r[1]), "=r"(r[2]), "=r"(r[3]) : "r"(addr));
}
__device__ __forceinline__ void mma16816(float d[4], const uint32_t a[4], const uint32_t b[2]) {
    asm volatile("mma.sync.aligned.m16n8k16.row.col.f32.bf16.bf16.f32 "
                 "{%0,%1,%2,%3}, {%4,%5,%6,%7}, {%8,%9}, {%0,%1,%2,%3};"
                 : "+f"(d[0]), "+f"(d[1]), "+f"(d[2]), "+f"(d[3])
                 : "r"(a[0]), "r"(a[1]), "r"(a[2]), "r"(a[3]), "r"(b[0]), "r"(b[1]));
}
__device__ __forceinline__ void cp16(uint32_t saddr, const void* gaddr) {
    asm volatile("cp.async.cg.shared.global [%0], [%1], 16;" :: "r"(saddr), "l"(gaddr));
}
__device__ __forceinline__ void cp16z(uint32_t saddr, const void* gaddr, int nbytes) {
    asm volatile("cp.async.cg.shared.global [%0], [%1], 16, %2;"
                 :: "r"(saddr), "l"(gaddr), "r"(nbytes));
}
__device__ __forceinline__ void cp_commit() {
    asm volatile("cp.async.commit_group;" ::: "memory");
}
template <int N>
__device__ __forceinline__ void cp_wait() {
    asm volatile("cp.async.wait_group %0;" :: "n"(N) : "memory");
}

// ---------------- small kernels ----------------------------------------------
__global__ void lengths_kernel(const int* __restrict__ mask) {
    int b = blockIdx.x;
    int v = mask[b * T + threadIdx.x];
#pragma unroll
    for (int o = 16; o > 0; o >>= 1) v += __shfl_down_sync(0xffffffffu, v, o);
    __shared__ int sh[4];
    if ((threadIdx.x & 31) == 0) sh[threadIdx.x >> 5] = v;
    __syncthreads();
    if (threadIdx.x == 0) g_len[b] = sh[0] + sh[1] + sh[2] + sh[3];
}

__global__ void embed_kernel(const int* __restrict__ ids, const float* __restrict__ emb) {
    int r = blockIdx.x;
    int id = __ldg(&ids[r]);
    const float4* s = reinterpret_cast<const float4*>(emb) + (size_t)id * (E / 4);
    float4* d = reinterpret_cast<float4*>(g_x) + (size_t)r * (E / 4);
    d[threadIdx.x] = s[threadIdx.x];
}

__global__ void zero_hc() {
    int i = blockIdx.x * blockDim.x + threadIdx.x;
    if (i == 0) g_bar = 0u;
    if (i < B * H) {
        g_h[0][i] = 0.f; g_h[1][i] = 0.f; g_c[i] = 0.f;
        __nv_bfloat16 z = __float2bfloat16(0.f);
        g_hbf[0][0][i] = z; g_hbf[0][1][i] = z;
        g_hbf[1][0][i] = z; g_hbf[1][1][i] = z;
    }
}

__global__ void convert_kernel(const float* __restrict__ wsrc, int mode, int n4) {
    int i = blockIdx.x * blockDim.x + threadIdx.x;
    if (i >= n4) return;
    const float* src = (mode == 0) ? g_x : wsrc;
    __nv_bfloat16* hi = (mode == 0) ? g_xhi : g_whi;
    __nv_bfloat16* lo = (mode == 0) ? g_xlo : g_wlo;
    float4 v = reinterpret_cast<const float4*>(src)[i];
    __nv_bfloat16 h0 = __float2bfloat16(v.x), h1 = __float2bfloat16(v.y);
    __nv_bfloat16 h2 = __float2bfloat16(v.z), h3 = __float2bfloat16(v.w);
    __nv_bfloat16 l0 = __float2bfloat16(v.x - __bfloat162float(h0));
    __nv_bfloat16 l1 = __float2bfloat16(v.y - __bfloat162float(h1));
    __nv_bfloat16 l2 = __float2bfloat16(v.z - __bfloat162float(h2));
    __nv_bfloat16 l3 = __float2bfloat16(v.w - __bfloat162float(h3));
    __nv_bfloat162* hp = reinterpret_cast<__nv_bfloat162*>(hi) + 2 * i;
    __nv_bfloat162* lp = reinterpret_cast<__nv_bfloat162*>(lo) + 2 * i;
    hp[0] = __nv_bfloat162(h0, h1); hp[1] = __nv_bfloat162(h2, h3);
    lp[0] = __nv_bfloat162(l0, l1); lp[1] = __nv_bfloat162(l2, l3);
}

__global__ void reorder_whh(const float* __restrict__ Whh) {
    int r = blockIdx.x;
    int j = r >> 2, g = r & 3;
    const float4* src = reinterpret_cast<const float4*>(Whh + (size_t)(g * H + j) * H);
    int i = threadIdx.x;
    float4 v = src[i];
    __nv_bfloat16 h0 = __float2bfloat16(v.x), h1 = __float2bfloat16(v.y);
    __nv_bfloat16 h2 = __float2bfloat16(v.z), h3 = __float2bfloat16(v.w);
    __nv_bfloat162* hp = reinterpret_cast<__nv_bfloat162*>(g_wrhi + (size_t)r * H) + 2 * i;
    __nv_bfloat162* lp = reinterpret_cast<__nv_bfloat162*>(g_wrlo + (size_t)r * H) + 2 * i;
    hp[0] = __nv_bfloat162(h0, h1); hp[1] = __nv_bfloat162(h2, h3);
    lp[0] = __nv_bfloat162(__float2bfloat16(v.x - __bfloat162float(h0)),
                           __float2bfloat16(v.y - __bfloat162float(h1)));
    lp[1] = __nv_bfloat162(__float2bfloat16(v.z - __bfloat162float(h2)),
                           __float2bfloat16(v.w - __bfloat162float(h3)));
}

// ---------------- split-bf16 tensor-core GEMM, 2-stage cp.async, occ=2 ------
#define SSTR 40
#define MAT_BYTES (128 * SSTR * 2)      // 10240 B
#define STG_BYTES (4 * MAT_BYTES)       // 40960 B
#define NSTAGE 2
#define GEMM_SMEM (NSTAGE * STG_BYTES)  // 81920 B

__global__ void __launch_bounds__(256, 2) mma_gemm(
    float* __restrict__ Cout, const float* __restrict__ b1,
    const float* __restrict__ b2, int Ncols, int ldc, int mode)
{
    extern __shared__ char dsm[];
    float* __restrict__ C = (mode == 0) ? g_gx : Cout;

    const int tid  = threadIdx.x;
    const int wid  = tid >> 5;
    const int lane = tid & 31;
    const int row0 = blockIdx.y * 128;
    const int col0 = blockIdx.x * 128;
    const int wm0  = (wid >> 2) * 64;
    const int wn0  = (wid & 3) * 32;

    const uint32_t smem0 = smem_u32(dsm);

    const int r0t = tid >> 2, r1t = (256 + tid) >> 2;
    const int qt  = tid & 3;

    auto issue = [&](int ch) {
        const uint32_t sb = smem0 + (ch & 1) * STG_BYTES;
        const int kb = ch * 32;
#pragma unroll
        for (int s = 0; s < 2; s++) {
            int r = (s == 0) ? r0t : r1t;
            uint32_t so = (uint32_t)((r * SSTR + qt * 8) * 2);
            size_t ga = (size_t)(row0 + r) * KDIM + kb + qt * 8;
            cp16(sb + so,             g_xhi + ga);
            cp16(sb + MAT_BYTES + so, g_xlo + ga);
            int n = col0 + r;
            int ok = (n < Ncols) ? 16 : 0;
            size_t gb = (size_t)(ok ? n : 0) * KDIM + kb + qt * 8;
            cp16z(sb + 2 * MAT_BYTES + so, g_whi + gb, ok);
            cp16z(sb + 3 * MAT_BYTES + so, g_wlo + gb, ok);
        }
        cp_commit();
    };

    float acc[4][4][4];
#pragma unroll
    for (int mi = 0; mi < 4; mi++)
#pragma unroll
        for (int ni = 0; ni < 4; ni++)
#pragma unroll
            for (int q = 0; q < 4; q++) acc[mi][ni][q] = 0.f;

    const int NCH = KDIM / 32;
    issue(0);
    issue(1);

    // fragment addresses (constant per thread)
    const int arow = wm0 + (lane & 7) + ((lane >> 3) & 1) * 8;
    const int acol0 = (lane >> 4) * 8;
    const int brow = wn0 + (lane & 7) + ((lane >> 4) & 1) * 8;
    const int bcol0 = ((lane >> 3) & 1) * 8;

    for (int ch = 0; ch < NCH; ch++) {
        cp_wait<1>();
        __syncthreads();

        const uint32_t sb = smem0 + (ch & 1) * STG_BYTES;

#pragma unroll
        for (int ks = 0; ks < 2; ks++) {
            uint32_t A[4][4], Bq[4], Bh[4][2], Bx[4][2];
            // pass 1: Ah . Bh
#pragma unroll
            for (int mi = 0; mi < 4; mi++)
                ldmx4(A[mi], sb + (uint32_t)(((arow + mi * 16) * SSTR + ks * 16 + acol0) * 2));
#pragma unroll
            for (int p = 0; p < 2; p++) {
                ldmx4(Bq, sb + 2 * MAT_BYTES +
                      (uint32_t)(((brow + p * 16) * SSTR + ks * 16 + bcol0) * 2));
                Bh[2 * p][0] = Bq[0]; Bh[2 * p][1] = Bq[1];
                Bh[2 * p + 1][0] = Bq[2]; Bh[2 * p + 1][1] = Bq[3];
            }
#pragma unroll
            for (int mi = 0; mi < 4; mi++)
#pragma unroll
                for (int ni = 0; ni < 4; ni++)
                    mma16816(acc[mi][ni], A[mi], Bh[ni]);

            // pass 2: Ah . Bl
#pragma unroll
            for (int p = 0; p < 2; p++) {
                ldmx4(Bq, sb + 3 * MAT_BYTES +
                      (uint32_t)(((brow + p * 16) * SSTR + ks * 16 + bcol0) * 2));
                Bx[2 * p][0] = Bq[0]; Bx[2 * p][1] = Bq[1];
                Bx[2 * p + 1][0] = Bq[2]; Bx[2 * p + 1][1] = Bq[3];
            }
#pragma unroll
            for (int mi = 0; mi < 4; mi++)
#pragma unroll
                for (int ni = 0; ni < 4; ni++)
                    mma16816(acc[mi][ni], A[mi], Bx[ni]);

            // pass 3: Al . Bh
#pragma unroll
            for (int mi = 0; mi < 4; mi++)
                ldmx4(A[mi], sb + MAT_BYTES +
                      (uint32_t)(((arow + mi * 16) * SSTR + ks * 16 + acol0) * 2));
#pragma unroll
            for (int mi = 0; mi < 4; mi++)
#pragma unroll
                for (int ni = 0; ni < 4; ni++)
                    mma16816(acc[mi][ni], A[mi], Bh[ni]);
        }
        __syncthreads();             // readers done before stage is re-filled

        if (ch + 2 < NCH) issue(ch + 2);
    }

#pragma unroll
    for (int ni = 0; ni < 4; ni++) {
        int col = col0 + wn0 + ni * 8 + (lane & 3) * 2;
        if (col >= Ncols) continue;
        float bx = b1[col], by = b1[col + 1];
        if (b2) { bx += b2[col]; by += b2[col + 1]; }
#pragma unroll
        for (int mi = 0; mi < 4; mi++) {
            int row = row0 + wm0 + mi * 16 + (lane >> 2);
            float2 v0 = make_float2(acc[mi][ni][0] + bx, acc[mi][ni][1] + by);
            float2 v1 = make_float2(acc[mi][ni][2] + bx, acc[mi][ni][3] + by);
            *reinterpret_cast<float2*>(&C[(size_t)row * ldc + col])       = v0;
            *reinterpret_cast<float2*>(&C[(size_t)(row + 8) * ldc + col]) = v1;
        }
    }
}

// ---------------- persistent tensor-core LSTM recurrence (unchanged) --------
#define WSTR 1032
#define OFF_WH 0
#define OFF_WL (32 * WSTR * 2)
#define OFF_AH (OFF_WL + 32 * WSTR * 2)
#define OFF_AL (OFF_AH + 64 * SSTR * 2)
#define OFF_SS (OFF_AL + 64 * SSTR * 2)
#define SMEM_P (OFF_SS + 64 * 36 * 4)

__global__ void __launch_bounds__(128, 1) tc_persist()
{
    extern __shared__ char dsm[];
    __nv_bfloat16* sWh = reinterpret_cast<__nv_bfloat16*>(dsm + OFF_WH);
    __nv_bfloat16* sWl = reinterpret_cast<__nv_bfloat16*>(dsm + OFF_WL);
    __nv_bfloat16* sAh = reinterpret_cast<__nv_bfloat16*>(dsm + OFF_AH);
    __nv_bfloat16* sAl = reinterpret_cast<__nv_bfloat16*>(dsm + OFF_AL);
    float (*Ssm)[36]   = reinterpret_cast<float(*)[36]>(dsm + OFF_SS);

    const int tid  = threadIdx.x;
    const int wid  = tid >> 5;
    const int lane = tid & 31;
    const int jblk = blockIdx.x;

    const uint32_t baseAh = smem_u32(sAh);
    const uint32_t baseAl = smem_u32(sAl);
    const uint32_t baseWh = smem_u32(sWh);
    const uint32_t baseWl = smem_u32(sWl);

    for (int i = tid; i < 32 * 128; i += 128) {
        int r = i >> 7, q = i & 127;
        size_t gb = (size_t)(jblk * 32 + r) * H + q * 8;
        *reinterpret_cast<uint4*>(sWh + r * WSTR + q * 8) = *reinterpret_cast<const uint4*>(g_wrhi + gb);
        *reinterpret_cast<uint4*>(sWl + r * WSTR + q * 8) = *reinterpret_cast<const uint4*>(g_wrlo + gb);
    }
    __syncthreads();

    for (int t = 0; t < T; t++) {
        const __nv_bfloat16* __restrict__ hbh = g_hbf[t & 1][0];
        const __nv_bfloat16* __restrict__ hbl = g_hbf[t & 1][1];

        float acc[4][4];
#pragma unroll
        for (int ni = 0; ni < 4; ni++)
#pragma unroll
            for (int q = 0; q < 4; q++) acc[ni][q] = 0.f;

        uint4 pf[4];
        auto prefetch = [&](int kb) {
#pragma unroll
            for (int s = 0; s < 2; s++) {
                int idx = s * 128 + tid;
                int r = idx >> 2, q = idx & 3;
                size_t ga = (size_t)r * H + kb + q * 8;
                pf[s]     = *reinterpret_cast<const uint4*>(hbh + ga);
                pf[s + 2] = *reinterpret_cast<const uint4*>(hbl + ga);
            }
        };

        prefetch(0);

        for (int ch = 0; ch < KDIM / 32; ch++) {
            __syncthreads();
#pragma unroll
            for (int s = 0; s < 2; s++) {
                int idx = s * 128 + tid;
                int r = idx >> 2, q = idx & 3;
                int so = r * SSTR + q * 8;
                *reinterpret_cast<uint4*>(sAh + so) = pf[s];
                *reinterpret_cast<uint4*>(sAl + so) = pf[s + 2];
            }
            __syncthreads();

            if (ch + 1 < KDIM / 32) prefetch((ch + 1) * 32);

#pragma unroll
            for (int ks = 0; ks < 2; ks++) {
                uint32_t Ah[4], Al[4], Bh[4][2], Bl[4][2];
                {
                    int arow = wid * 16 + (lane & 7) + ((lane >> 3) & 1) * 8;
                    int acol = ks * 16 + (lane >> 4) * 8;
                    uint32_t off = (uint32_t)((arow * SSTR + acol) * 2);
                    ldmx4(Ah, baseAh + off);
                    ldmx4(Al, baseAl + off);
                }
                {
                    int brow = (lane & 7) + ((lane >> 4) & 1) * 8;
                    int bcol = ch * 32 + ks * 16 + ((lane >> 3) & 1) * 8;
#pragma unroll
                    for (int p = 0; p < 2; p++) {
                        uint32_t off = (uint32_t)(((brow + p * 16) * WSTR + bcol) * 2);
                        uint32_t rbh[4], rbl[4];
                        ldmx4(rbh, baseWh + off);
                        ldmx4(rbl, baseWl + off);
                        Bh[2 * p][0] = rbh[0]; Bh[2 * p][1] = rbh[1];
                        Bh[2 * p + 1][0] = rbh[2]; Bh[2 * p + 1][1] = rbh[3];
                        Bl[2 * p][0] = rbl[0]; Bl[2 * p][1] = rbl[1];
                        Bl[2 * p + 1][0] = rbl[2]; Bl[2 * p + 1][1] = rbl[3];
                    }
                }
#pragma unroll
                for (int ni = 0; ni < 4; ni++) {
                    mma16816(acc[ni], Ah, Bh[ni]);
                    mma16816(acc[ni], Ah, Bl[ni]);
                    mma16816(acc[ni], Al, Bh[ni]);
                }
            }
        }

        __syncthreads();
        {
            int row = wid * 16 + (lane >> 2);
            int cc  = (lane & 3) * 2;
#pragma unroll
            for (int ni = 0; ni < 4; ni++) {
                int c = ni * 8 + cc;
                Ssm[row][c]         = acc[ni][0];
                Ssm[row][c + 1]     = acc[ni][1];
                Ssm[row + 8][c]     = acc[ni][2];
                Ssm[row + 8][c + 1] = acc[ni][3];
            }
        }
        __syncthreads();

        const float* __restrict__ hin  = g_h[t & 1];
        float* __restrict__       hout = g_h[(t + 1) & 1];
        __nv_bfloat16* __restrict__ hbho = g_hbf[(t + 1) & 1][0];
        __nv_bfloat16* __restrict__ hblo = g_hbf[(t + 1) & 1][1];

#pragma unroll
        for (int ii = 0; ii < 4; ii++) {
            int idx = ii * 128 + tid;
            int b = idx >> 3, jl = idx & 7;
            int j = jblk * 8 + jl;
            size_t gr = ((size_t)b * T + t) * G4;
            float iv = Ssm[b][4 * jl + 0] + g_gx[gr + j];
            float fv = Ssm[b][4 * jl + 1] + g_gx[gr + H + j];
            float gv = Ssm[b][4 * jl + 2] + g_gx[gr + 2 * H + j];
            float ov = Ssm[b][4 * jl + 3] + g_gx[gr + 3 * H + j];

            float c_old = g_c[b * H + j];
            float h_old = hin[b * H + j];

            float si = 1.f / (1.f + expf(-iv));
            float sf = 1.f / (1.f + expf(-fv));
            float so = 1.f / (1.f + expf(-ov));
            float cn = fmaf(sf, c_old, si * tanhf(gv));
            float hn = so * tanhf(cn);

            bool ok = t < g_len[b];
            float cw = ok ? cn : c_old;
            float hw = ok ? hn : h_old;
            g_c[b * H + j]  = cw;
            hout[b * H + j] = hw;
            __nv_bfloat16 hh = __float2bfloat16(hw);
            hbho[b * H + j] = hh;
            hblo[b * H + j] = __float2bfloat16(hw - __bfloat162float(hh));
            g_x[((size_t)b * T + t) * E + j] = ok ? hn : 0.f;
        }

        if (t + 1 < T) {
            __syncthreads();
            if (tid == 0) {
                __threadfence();
                atomicAdd(&g_bar, 1u);
                unsigned tgt = (unsigned)(t + 1) * gridDim.x;
                unsigned v;
                do {
                    asm volatile("ld.acquire.gpu.u32 %0, [%1];" : "=r"(v) : "l"(&g_bar));
                    if (v >= tgt) break;
                    __nanosleep(64);
                } while (true);
            }
            __syncthreads();
        }
    }
}

__global__ void copy_states_kernel(float* __restrict__ hs_out, float* __restrict__ cs_out) {
    int i = blockIdx.x * blockDim.x + threadIdx.x;
    if (i < B * H) {
        hs_out[i] = g_h[0][i];
        cs_out[i] = g_c[i];
    }
}

// ---------------- launch ------------------------------------------------------
extern "C" void kernel_launch(void* const* d_in, const int* in_sizes, int n_in,
                              void* d_out, int out_size)
{
    const int*   ids  = (const int*)d_in[0];
    const int*   mask = (const int*)d_in[1];
    const float* emb  = (const float*)d_in[2];
    const float* Wih  = (const float*)d_in[3];
    const float* Whh  = (const float*)d_in[4];
    const float* bih  = (const float*)d_in[5];
    const float* bhh  = (const float*)d_in[6];
    const float* fcw  = (const float*)d_in[7];
    const float* fcb  = (const float*)d_in[8];
    float* out = (float*)d_out;

    cudaFuncSetAttribute(tc_persist, cudaFuncAttributeMaxDynamicSharedMemorySize, SMEM_P);
    cudaFuncSetAttribute(mma_gemm, cudaFuncAttributeMaxDynamicSharedMemorySize, GEMM_SMEM);

    lengths_kernel<<<B, T>>>(mask);
    embed_kernel<<<B * T, E / 4>>>(ids, emb);

    const size_t HS_OFF = (size_t)B * T * V;
    const size_t CS_OFF = HS_OFF + (size_t)L * B * H;
    const int X4 = B * T * E / 4;

    for (int l = 0; l < L; l++) {
        convert_kernel<<<(X4 + 255) / 256, 256>>>(nullptr, 0, X4);
        const int W4 = G4 * E / 4;
        convert_kernel<<<(W4 + 255) / 256, 256>>>(Wih + (size_t)l * G4 * E, 1, W4);

        mma_gemm<<<dim3(G4 / 128, (B * T) / 128), 256, GEMM_SMEM>>>(
            nullptr, bih + (size_t)l * G4, bhh + (size_t)l * G4, G4, G4, /*mode=*/0);

        reorder_whh<<<G4, 256>>>(Whh + (size_t)l * G4 * H);
        zero_hc<<<(B * H + 511) / 512, 512>>>();

        tc_persist<<<128, 128, SMEM_P>>>();

        copy_states_kernel<<<(B * H + 511) / 512, 512>>>(
            out + HS_OFF + (size_t)l * B * H,
            out + CS_OFF + (size_t)l * B * H);
    }

    convert_kernel<<<(X4 + 255) / 256, 256>>>(nullptr, 0, X4);
    const int F4 = V * H / 4;
    convert_kernel<<<(F4 + 255) / 256, 256>>>(fcw, 1, F4);

    mma_gemm<<<dim3((V + 127) / 128, (B * T) / 128), 256, GEMM_SMEM>>>(
        out, fcb, nullptr, V, V, /*mode=*/1);
}

// round 10
// speedup vs baseline: 6.4103x; 1.0593x over previous
#include <cuda_runtime.h>
#include <cuda_bf16.h>
#include <cuda_fp16.h>
#include <math.h>
#include <stdint.h>

#define B 64
#define T 128
#define V 10000
#define E 1024
#define H 1024
#define G4 4096
#define L 2
#define KDIM 1024

// ---------------- scratch (device globals) ----------------------------------
__device__ float g_x[(size_t)B * T * E];
__device__ float g_gx[(size_t)B * T * G4];
__device__ float g_h[2][B * H];
__device__ float g_c[B * H];
__device__ int   g_len[B];
__device__ unsigned g_bar;
__device__ __nv_bfloat16 g_xhi[(size_t)B * T * E];   // also used as fp16 for FC
__device__ __nv_bfloat16 g_xlo[(size_t)B * T * E];
__device__ __nv_bfloat16 g_whi[(size_t)V * H];       // also used as fp16 for FC
__device__ __nv_bfloat16 g_wlo[(size_t)V * H];
__device__ __nv_bfloat16 g_hbf[2][2][B * H];
__device__ __nv_bfloat16 g_wrhi[(size_t)G4 * H];
__device__ __nv_bfloat16 g_wrlo[(size_t)G4 * H];

// ---------------- PTX helpers (portable sm_80+ PTX) --------------------------
__device__ __forceinline__ uint32_t smem_u32(const void* p) {
    uint32_t a;
    asm("{ .reg .u64 t; cvta.to.shared.u64 t, %1; cvt.u32.u64 %0, t; }" : "=r"(a) : "l"(p));
    return a;
}
__device__ __forceinline__ void ldmx4(uint32_t r[4], uint32_t addr) {
    asm volatile("ldmatrix.sync.aligned.m8n8.x4.shared.b16 {%0,%1,%2,%3}, [%4];"
                 : "=r"(r[0]), "=r"(r[1]), "=r"(r[2]), "=r"(r[3]) : "r"(addr));
}
__device__ __forceinline__ void mma16816(float d[4], const uint32_t a[4], const uint32_t b[2]) {
    asm volatile("mma.sync.aligned.m16n8k16.row.col.f32.bf16.bf16.f32 "
                 "{%0,%1,%2,%3}, {%4,%5,%6,%7}, {%8,%9}, {%0,%1,%2,%3};"
                 : "+f"(d[0]), "+f"(d[1]), "+f"(d[2]), "+f"(d[3])
                 : "r"(a[0]), "r"(a[1]), "r"(a[2]), "r"(a[3]), "r"(b[0]), "r"(b[1]));
}
__device__ __forceinline__ void mma16816h(float d[4], const uint32_t a[4], const uint32_t b[2]) {
    asm volatile("mma.sync.aligned.m16n8k16.row.col.f32.f16.f16.f32 "
                 "{%0,%1,%2,%3}, {%4,%5,%6,%7}, {%8,%9}, {%0,%1,%2,%3};"
                 : "+f"(d[0]), "+f"(d[1]), "+f"(d[2]), "+f"(d[3])
                 : "r"(a[0]), "r"(a[1]), "r"(a[2]), "r"(a[3]), "r"(b[0]), "r"(b[1]));
}
__device__ __forceinline__ void cp16(uint32_t saddr, const void* gaddr) {
    asm volatile("cp.async.cg.shared.global [%0], [%1], 16;" :: "r"(saddr), "l"(gaddr));
}
__device__ __forceinline__ void cp16z(uint32_t saddr, const void* gaddr, int nbytes) {
    asm volatile("cp.async.cg.shared.global [%0], [%1], 16, %2;"
                 :: "r"(saddr), "l"(gaddr), "r"(nbytes));
}
__device__ __forceinline__ void cp_commit() {
    asm volatile("cp.async.commit_group;" ::: "memory");
}
template <int N>
__device__ __forceinline__ void cp_wait() {
    asm volatile("cp.async.wait_group %0;" :: "n"(N) : "memory");
}

// ---------------- small kernels ----------------------------------------------
__global__ void lengths_kernel(const int* __restrict__ mask) {
    int b = blockIdx.x;
    int v = mask[b * T + threadIdx.x];
#pragma unroll
    for (int o = 16; o > 0; o >>= 1) v += __shfl_down_sync(0xffffffffu, v, o);
    __shared__ int sh[4];
    if ((threadIdx.x & 31) == 0) sh[threadIdx.x >> 5] = v;
    __syncthreads();
    if (threadIdx.x == 0) g_len[b] = sh[0] + sh[1] + sh[2] + sh[3];
}

__global__ void embed_kernel(const int* __restrict__ ids, const float* __restrict__ emb) {
    int r = blockIdx.x;
    int id = __ldg(&ids[r]);
    const float4* s = reinterpret_cast<const float4*>(emb) + (size_t)id * (E / 4);
    float4* d = reinterpret_cast<float4*>(g_x) + (size_t)r * (E / 4);
    d[threadIdx.x] = s[threadIdx.x];
}

__global__ void zero_hc() {
    int i = blockIdx.x * blockDim.x + threadIdx.x;
    if (i == 0) g_bar = 0u;
    if (i < B * H) {
        g_h[0][i] = 0.f; g_h[1][i] = 0.f; g_c[i] = 0.f;
        __nv_bfloat16 z = __float2bfloat16(0.f);
        g_hbf[0][0][i] = z; g_hbf[0][1][i] = z;
        g_hbf[1][0][i] = z; g_hbf[1][1][i] = z;
    }
}

// split fp32 -> hi + lo. mode 0: g_x->bf16; 1: wsrc->bf16; 2: g_x->fp16; 3: wsrc->fp16
__global__ void convert_kernel(const float* __restrict__ wsrc, int mode, int n4) {
    int i = blockIdx.x * blockDim.x + threadIdx.x;
    if (i >= n4) return;
    bool isx = (mode == 0) || (mode == 2);
    const float* src = isx ? g_x : wsrc;
    void* hi = isx ? (void*)g_xhi : (void*)g_whi;
    void* lo = isx ? (void*)g_xlo : (void*)g_wlo;
    float4 v = reinterpret_cast<const float4*>(src)[i];
    if (mode < 2) {
        __nv_bfloat16 h0 = __float2bfloat16(v.x), h1 = __float2bfloat16(v.y);
        __nv_bfloat16 h2 = __float2bfloat16(v.z), h3 = __float2bfloat16(v.w);
        __nv_bfloat162* hp = reinterpret_cast<__nv_bfloat162*>(hi) + 2 * i;
        __nv_bfloat162* lp = reinterpret_cast<__nv_bfloat162*>(lo) + 2 * i;
        hp[0] = __nv_bfloat162(h0, h1); hp[1] = __nv_bfloat162(h2, h3);
        lp[0] = __nv_bfloat162(__float2bfloat16(v.x - __bfloat162float(h0)),
                               __float2bfloat16(v.y - __bfloat162float(h1)));
        lp[1] = __nv_bfloat162(__float2bfloat16(v.z - __bfloat162float(h2)),
                               __float2bfloat16(v.w - __bfloat162float(h3)));
    } else {
        __half h0 = __float2half_rn(v.x), h1 = __float2half_rn(v.y);
        __half h2 = __float2half_rn(v.z), h3 = __float2half_rn(v.w);
        __half2* hp = reinterpret_cast<__half2*>(hi) + 2 * i;
        __half2* lp = reinterpret_cast<__half2*>(lo) + 2 * i;
        hp[0] = __half2(h0, h1); hp[1] = __half2(h2, h3);
        lp[0] = __half2(__float2half_rn(v.x - __half2float(h0)),
                        __float2half_rn(v.y - __half2float(h1)));
        lp[1] = __half2(__float2half_rn(v.z - __half2float(h2)),
                        __float2half_rn(v.w - __half2float(h3)));
    }
}

__global__ void reorder_whh(const float* __restrict__ Whh) {
    int r = blockIdx.x;
    int j = r >> 2, g = r & 3;
    const float4* src = reinterpret_cast<const float4*>(Whh + (size_t)(g * H + j) * H);
    int i = threadIdx.x;
    float4 v = src[i];
    __nv_bfloat16 h0 = __float2bfloat16(v.x), h1 = __float2bfloat16(v.y);
    __nv_bfloat16 h2 = __float2bfloat16(v.z), h3 = __float2bfloat16(v.w);
    __nv_bfloat162* hp = reinterpret_cast<__nv_bfloat162*>(g_wrhi + (size_t)r * H) + 2 * i;
    __nv_bfloat162* lp = reinterpret_cast<__nv_bfloat162*>(g_wrlo + (size_t)r * H) + 2 * i;
    hp[0] = __nv_bfloat162(h0, h1); hp[1] = __nv_bfloat162(h2, h3);
    lp[0] = __nv_bfloat162(__float2bfloat16(v.x - __bfloat162float(h0)),
                           __float2bfloat16(v.y - __bfloat162float(h1)));
    lp[1] = __nv_bfloat162(__float2bfloat16(v.z - __bfloat162float(h2)),
                           __float2bfloat16(v.w - __bfloat162float(h3)));
}

// ---------------- tensor-core GEMM, 2-stage cp.async, occ=2 -----------------
// PASSES==3: bf16 3-pass (Ah.Bh + Ah.Bl + Al.Bh).
// PASSES==2: fp16 2-pass (Ah.Bh + Ah.Bl) — no A-lo loads at all.
#define SSTR 40
#define MAT_BYTES (128 * SSTR * 2)      // 10240 B
#define STG_BYTES (4 * MAT_BYTES)       // 40960 B
#define NSTAGE 2
#define GEMM_SMEM (NSTAGE * STG_BYTES)  // 81920 B

template <int PASSES>
__global__ void __launch_bounds__(256, 2) mma_gemm(
    float* __restrict__ Cout, const float* __restrict__ b1,
    const float* __restrict__ b2, int Ncols, int ldc, int mode)
{
    extern __shared__ char dsm[];
    float* __restrict__ C = (mode == 0) ? g_gx : Cout;

    const int tid  = threadIdx.x;
    const int wid  = tid >> 5;
    const int lane = tid & 31;
    const int row0 = blockIdx.y * 128;
    const int col0 = blockIdx.x * 128;
    const int wm0  = (wid >> 2) * 64;
    const int wn0  = (wid & 3) * 32;

    const uint32_t smem0 = smem_u32(dsm);

    const int r0t = tid >> 2, r1t = (256 + tid) >> 2;
    const int qt  = tid & 3;

    auto issue = [&](int ch) {
        const uint32_t sb = smem0 + (ch & 1) * STG_BYTES;
        const int kb = ch * 32;
#pragma unroll
        for (int s = 0; s < 2; s++) {
            int r = (s == 0) ? r0t : r1t;
            uint32_t so = (uint32_t)((r * SSTR + qt * 8) * 2);
            size_t ga = (size_t)(row0 + r) * KDIM + kb + qt * 8;
            cp16(sb + so, g_xhi + ga);
            if (PASSES == 3) cp16(sb + MAT_BYTES + so, g_xlo + ga);
            int n = col0 + r;
            int ok = (n < Ncols) ? 16 : 0;
            size_t gb = (size_t)(ok ? n : 0) * KDIM + kb + qt * 8;
            cp16z(sb + 2 * MAT_BYTES + so, g_whi + gb, ok);
            cp16z(sb + 3 * MAT_BYTES + so, g_wlo + gb, ok);
        }
        cp_commit();
    };

    float acc[4][4][4];
#pragma unroll
    for (int mi = 0; mi < 4; mi++)
#pragma unroll
        for (int ni = 0; ni < 4; ni++)
#pragma unroll
            for (int q = 0; q < 4; q++) acc[mi][ni][q] = 0.f;

    const int NCH = KDIM / 32;
    issue(0);
    issue(1);

    const int arow = wm0 + (lane & 7) + ((lane >> 3) & 1) * 8;
    const int acol0 = (lane >> 4) * 8;
    const int brow = wn0 + (lane & 7) + ((lane >> 4) & 1) * 8;
    const int bcol0 = ((lane >> 3) & 1) * 8;

    for (int ch = 0; ch < NCH; ch++) {
        cp_wait<1>();
        __syncthreads();

        const uint32_t sb = smem0 + (ch & 1) * STG_BYTES;

#pragma unroll
        for (int ks = 0; ks < 2; ks++) {
            uint32_t A[4][4], Bq[4], Bh[4][2], Bx[4][2];
            // pass 1: Ah . Bh
#pragma unroll
            for (int mi = 0; mi < 4; mi++)
                ldmx4(A[mi], sb + (uint32_t)(((arow + mi * 16) * SSTR + ks * 16 + acol0) * 2));
#pragma unroll
            for (int p = 0; p < 2; p++) {
                ldmx4(Bq, sb + 2 * MAT_BYTES +
                      (uint32_t)(((brow + p * 16) * SSTR + ks * 16 + bcol0) * 2));
                Bh[2 * p][0] = Bq[0]; Bh[2 * p][1] = Bq[1];
                Bh[2 * p + 1][0] = Bq[2]; Bh[2 * p + 1][1] = Bq[3];
            }
#pragma unroll
            for (int mi = 0; mi < 4; mi++)
#pragma unroll
                for (int ni = 0; ni < 4; ni++) {
                    if (PASSES == 3) mma16816(acc[mi][ni], A[mi], Bh[ni]);
                    else             mma16816h(acc[mi][ni], A[mi], Bh[ni]);
                }

            // pass 2: Ah . Bl
#pragma unroll
            for (int p = 0; p < 2; p++) {
                ldmx4(Bq, sb + 3 * MAT_BYTES +
                      (uint32_t)(((brow + p * 16) * SSTR + ks * 16 + bcol0) * 2));
                Bx[2 * p][0] = Bq[0]; Bx[2 * p][1] = Bq[1];
                Bx[2 * p + 1][0] = Bq[2]; Bx[2 * p + 1][1] = Bq[3];
            }
#pragma unroll
            for (int mi = 0; mi < 4; mi++)
#pragma unroll
                for (int ni = 0; ni < 4; ni++) {
                    if (PASSES == 3) mma16816(acc[mi][ni], A[mi], Bx[ni]);
                    else             mma16816h(acc[mi][ni], A[mi], Bx[ni]);
                }

            // pass 3 (bf16 only): Al . Bh
            if (PASSES == 3) {
#pragma unroll
                for (int mi = 0; mi < 4; mi++)
                    ldmx4(A[mi], sb + MAT_BYTES +
                          (uint32_t)(((arow + mi * 16) * SSTR + ks * 16 + acol0) * 2));
#pragma unroll
                for (int mi = 0; mi < 4; mi++)
#pragma unroll
                    for (int ni = 0; ni < 4; ni++)
                        mma16816(acc[mi][ni], A[mi], Bh[ni]);
            }
        }
        __syncthreads();

        if (ch + 2 < NCH) issue(ch + 2);
    }

#pragma unroll
    for (int ni = 0; ni < 4; ni++) {
        int col = col0 + wn0 + ni * 8 + (lane & 3) * 2;
        if (col >= Ncols) continue;
        float bx = b1[col], by = b1[col + 1];
        if (b2) { bx += b2[col]; by += b2[col + 1]; }
#pragma unroll
        for (int mi = 0; mi < 4; mi++) {
            int row = row0 + wm0 + mi * 16 + (lane >> 2);
            float2 v0 = make_float2(acc[mi][ni][0] + bx, acc[mi][ni][1] + by);
            float2 v1 = make_float2(acc[mi][ni][2] + bx, acc[mi][ni][3] + by);
            *reinterpret_cast<float2*>(&C[(size_t)row * ldc + col])       = v0;
            *reinterpret_cast<float2*>(&C[(size_t)(row + 8) * ldc + col]) = v1;
        }
    }
}

// ---------------- persistent tensor-core LSTM recurrence (unchanged) --------
#define WSTR 1032
#define OFF_WH 0
#define OFF_WL (32 * WSTR * 2)
#define OFF_AH (OFF_WL + 32 * WSTR * 2)
#define OFF_AL (OFF_AH + 64 * SSTR * 2)
#define OFF_SS (OFF_AL + 64 * SSTR * 2)
#define SMEM_P (OFF_SS + 64 * 36 * 4)

__global__ void __launch_bounds__(128, 1) tc_persist()
{
    extern __shared__ char dsm[];
    __nv_bfloat16* sWh = reinterpret_cast<__nv_bfloat16*>(dsm + OFF_WH);
    __nv_bfloat16* sWl = reinterpret_cast<__nv_bfloat16*>(dsm + OFF_WL);
    __nv_bfloat16* sAh = reinterpret_cast<__nv_bfloat16*>(dsm + OFF_AH);
    __nv_bfloat16* sAl = reinterpret_cast<__nv_bfloat16*>(dsm + OFF_AL);
    float (*Ssm)[36]   = reinterpret_cast<float(*)[36]>(dsm + OFF_SS);

    const int tid  = threadIdx.x;
    const int wid  = tid >> 5;
    const int lane = tid & 31;
    const int jblk = blockIdx.x;

    const uint32_t baseAh = smem_u32(sAh);
    const uint32_t baseAl = smem_u32(sAl);
    const uint32_t baseWh = smem_u32(sWh);
    const uint32_t baseWl = smem_u32(sWl);

    for (int i = tid; i < 32 * 128; i += 128) {
        int r = i >> 7, q = i & 127;
        size_t gb = (size_t)(jblk * 32 + r) * H + q * 8;
        *reinterpret_cast<uint4*>(sWh + r * WSTR + q * 8) = *reinterpret_cast<const uint4*>(g_wrhi + gb);
        *reinterpret_cast<uint4*>(sWl + r * WSTR + q * 8) = *reinterpret_cast<const uint4*>(g_wrlo + gb);
    }
    __syncthreads();

    for (int t = 0; t < T; t++) {
        const __nv_bfloat16* __restrict__ hbh = g_hbf[t & 1][0];
        const __nv_bfloat16* __restrict__ hbl = g_hbf[t & 1][1];

        float acc[4][4];
#pragma unroll
        for (int ni = 0; ni < 4; ni++)
#pragma unroll
            for (int q = 0; q < 4; q++) acc[ni][q] = 0.f;

        uint4 pf[4];
        auto prefetch = [&](int kb) {
#pragma unroll
            for (int s = 0; s < 2; s++) {
                int idx = s * 128 + tid;
                int r = idx >> 2, q = idx & 3;
                size_t ga = (size_t)r * H + kb + q * 8;
                pf[s]     = *reinterpret_cast<const uint4*>(hbh + ga);
                pf[s + 2] = *reinterpret_cast<const uint4*>(hbl + ga);
            }
        };

        prefetch(0);

        for (int ch = 0; ch < KDIM / 32; ch++) {
            __syncthreads();
#pragma unroll
            for (int s = 0; s < 2; s++) {
                int idx = s * 128 + tid;
                int r = idx >> 2, q = idx & 3;
                int so = r * SSTR + q * 8;
                *reinterpret_cast<uint4*>(sAh + so) = pf[s];
                *reinterpret_cast<uint4*>(sAl + so) = pf[s + 2];
            }
            __syncthreads();

            if (ch + 1 < KDIM / 32) prefetch((ch + 1) * 32);

#pragma unroll
            for (int ks = 0; ks < 2; ks++) {
                uint32_t Ah[4], Al[4], Bh[4][2], Bl[4][2];
                {
                    int arow = wid * 16 + (lane & 7) + ((lane >> 3) & 1) * 8;
                    int acol = ks * 16 + (lane >> 4) * 8;
                    uint32_t off = (uint32_t)((arow * SSTR + acol) * 2);
                    ldmx4(Ah, baseAh + off);
                    ldmx4(Al, baseAl + off);
                }
                {
                    int brow = (lane & 7) + ((lane >> 4) & 1) * 8;
                    int bcol = ch * 32 + ks * 16 + ((lane >> 3) & 1) * 8;
#pragma unroll
                    for (int p = 0; p < 2; p++) {
                        uint32_t off = (uint32_t)(((brow + p * 16) * WSTR + bcol) * 2);
                        uint32_t rbh[4], rbl[4];
                        ldmx4(rbh, baseWh + off);
                        ldmx4(rbl, baseWl + off);
                        Bh[2 * p][0] = rbh[0]; Bh[2 * p][1] = rbh[1];
                        Bh[2 * p + 1][0] = rbh[2]; Bh[2 * p + 1][1] = rbh[3];
                        Bl[2 * p][0] = rbl[0]; Bl[2 * p][1] = rbl[1];
                        Bl[2 * p + 1][0] = rbl[2]; Bl[2 * p + 1][1] = rbl[3];
                    }
                }
#pragma unroll
                for (int ni = 0; ni < 4; ni++) {
                    mma16816(acc[ni], Ah, Bh[ni]);
                    mma16816(acc[ni], Ah, Bl[ni]);
                    mma16816(acc[ni], Al, Bh[ni]);
                }
            }
        }

        __syncthreads();
        {
            int row = wid * 16 + (lane >> 2);
            int cc  = (lane & 3) * 2;
#pragma unroll
            for (int ni = 0; ni < 4; ni++) {
                int c = ni * 8 + cc;
                Ssm[row][c]         = acc[ni][0];
                Ssm[row][c + 1]     = acc[ni][1];
                Ssm[row + 8][c]     = acc[ni][2];
                Ssm[row + 8][c + 1] = acc[ni][3];
            }
        }
        __syncthreads();

        const float* __restrict__ hin  = g_h[t & 1];
        float* __restrict__       hout = g_h[(t + 1) & 1];
        __nv_bfloat16* __restrict__ hbho = g_hbf[(t + 1) & 1][0];
        __nv_bfloat16* __restrict__ hblo = g_hbf[(t + 1) & 1][1];

#pragma unroll
        for (int ii = 0; ii < 4; ii++) {
            int idx = ii * 128 + tid;
            int b = idx >> 3, jl = idx & 7;
            int j = jblk * 8 + jl;
            size_t gr = ((size_t)b * T + t) * G4;
            float iv = Ssm[b][4 * jl + 0] + g_gx[gr + j];
            float fv = Ssm[b][4 * jl + 1] + g_gx[gr + H + j];
            float gv = Ssm[b][4 * jl + 2] + g_gx[gr + 2 * H + j];
            float ov = Ssm[b][4 * jl + 3] + g_gx[gr + 3 * H + j];

            float c_old = g_c[b * H + j];
            float h_old = hin[b * H + j];

            float si = 1.f / (1.f + expf(-iv));
            float sf = 1.f / (1.f + expf(-fv));
            float so = 1.f / (1.f + expf(-ov));
            float cn = fmaf(sf, c_old, si * tanhf(gv));
            float hn = so * tanhf(cn);

            bool ok = t < g_len[b];
            float cw = ok ? cn : c_old;
            float hw = ok ? hn : h_old;
            g_c[b * H + j]  = cw;
            hout[b * H + j] = hw;
            __nv_bfloat16 hh = __float2bfloat16(hw);
            hbho[b * H + j] = hh;
            hblo[b * H + j] = __float2bfloat16(hw - __bfloat162float(hh));
            g_x[((size_t)b * T + t) * E + j] = ok ? hn : 0.f;
        }

        if (t + 1 < T) {
            __syncthreads();
            if (tid == 0) {
                __threadfence();
                atomicAdd(&g_bar, 1u);
                unsigned tgt = (unsigned)(t + 1) * gridDim.x;
                unsigned v;
                do {
                    asm volatile("ld.acquire.gpu.u32 %0, [%1];" : "=r"(v) : "l"(&g_bar));
                    if (v >= tgt) break;
                    __nanosleep(64);
                } while (true);
            }
            __syncthreads();
        }
    }
}

__global__ void copy_states_kernel(float* __restrict__ hs_out, float* __restrict__ cs_out) {
    int i = blockIdx.x * blockDim.x + threadIdx.x;
    if (i < B * H) {
        hs_out[i] = g_h[0][i];
        cs_out[i] = g_c[i];
    }
}

// ---------------- launch ------------------------------------------------------
extern "C" void kernel_launch(void* const* d_in, const int* in_sizes, int n_in,
                              void* d_out, int out_size)
{
    const int*   ids  = (const int*)d_in[0];
    const int*   mask = (const int*)d_in[1];
    const float* emb  = (const float*)d_in[2];
    const float* Wih  = (const float*)d_in[3];
    const float* Whh  = (const float*)d_in[4];
    const float* bih  = (const float*)d_in[5];
    const float* bhh  = (const float*)d_in[6];
    const float* fcw  = (const float*)d_in[7];
    const float* fcb  = (const float*)d_in[8];
    float* out = (float*)d_out;

    cudaFuncSetAttribute(tc_persist, cudaFuncAttributeMaxDynamicSharedMemorySize, SMEM_P);
    cudaFuncSetAttribute(mma_gemm<3>, cudaFuncAttributeMaxDynamicSharedMemorySize, GEMM_SMEM);
    cudaFuncSetAttribute(mma_gemm<2>, cudaFuncAttributeMaxDynamicSharedMemorySize, GEMM_SMEM);

    lengths_kernel<<<B, T>>>(mask);
    embed_kernel<<<B * T, E / 4>>>(ids, emb);

    const size_t HS_OFF = (size_t)B * T * V;
    const size_t CS_OFF = HS_OFF + (size_t)L * B * H;
    const int X4 = B * T * E / 4;

    for (int l = 0; l < L; l++) {
        convert_kernel<<<(X4 + 255) / 256, 256>>>(nullptr, 0, X4);
        const int W4 = G4 * E / 4;
        convert_kernel<<<(W4 + 255) / 256, 256>>>(Wih + (size_t)l * G4 * E, 1, W4);

        mma_gemm<3><<<dim3(G4 / 128, (B * T) / 128), 256, GEMM_SMEM>>>(
            nullptr, bih + (size_t)l * G4, bhh + (size_t)l * G4, G4, G4, /*mode=*/0);

        reorder_whh<<<G4, 256>>>(Whh + (size_t)l * G4 * H);
        zero_hc<<<(B * H + 511) / 512, 512>>>();

        tc_persist<<<128, 128, SMEM_P>>>();

        copy_states_kernel<<<(B * H + 511) / 512, 512>>>(
            out + HS_OFF + (size_t)l * B * H,
            out + CS_OFF + (size_t)l * B * H);
    }

    // FC in fp16 2-pass: logits error ~1.4e-4, no compounding
    convert_kernel<<<(X4 + 255) / 256, 256>>>(nullptr, 2, X4);
    const int F4 = V * H / 4;
    convert_kernel<<<(F4 + 255) / 256, 256>>>(fcw, 3, F4);

    mma_gemm<2><<<dim3((V + 127) / 128, (B * T) / 128), 256, GEMM_SMEM>>>(
        out, fcb, nullptr, V, V, /*mode=*/1);
}

// round 11
// speedup vs baseline: 7.4652x; 1.1646x over previous
#include <cuda_runtime.h>
#include <cuda_bf16.h>
#include <cuda_fp16.h>
#include <math.h>
#include <stdint.h>

#define B 64
#define T 128
#define V 10000
#define E 1024
#define H 1024
#define G4 4096
#define L 2
#define KDIM 1024

// ---------------- scratch (device globals) ----------------------------------
__device__ float g_x[(size_t)B * T * E];
__device__ float g_gx[(size_t)B * T * G4];
__device__ float g_h[2][B * H];
__device__ float g_c[B * H];
__device__ int   g_len[B];
__device__ unsigned g_bar;
__device__ __half g_xhi[(size_t)B * T * E];
__device__ __half g_whi[(size_t)V * H];
__device__ __half g_wlo[(size_t)V * H];
__device__ __half g_hbf[2][B * H];               // fp16 hidden state (pingpong)
__device__ __half g_wrhi[(size_t)G4 * H];        // gate-interleaved Whh hi
__device__ __half g_wrlo[(size_t)G4 * H];        // gate-interleaved Whh lo

// ---------------- PTX helpers (portable sm_80+ PTX) --------------------------
__device__ __forceinline__ uint32_t smem_u32(const void* p) {
    uint32_t a;
    asm("{ .reg .u64 t; cvta.to.shared.u64 t, %1; cvt.u32.u64 %0, t; }" : "=r"(a) : "l"(p));
    return a;
}
__device__ __forceinline__ void ldmx4(uint32_t r[4], uint32_t addr) {
    asm volatile("ldmatrix.sync.aligned.m8n8.x4.shared.b16 {%0,%1,%2,%3}, [%4];"
                 : "=r"(r[0]), "=r"(r[1]), "=r"(r[2]), "=r"(r[3]) : "r"(addr));
}
__device__ __forceinline__ void mma16816h(float d[4], const uint32_t a[4], const uint32_t b[2]) {
    asm volatile("mma.sync.aligned.m16n8k16.row.col.f32.f16.f16.f32 "
                 "{%0,%1,%2,%3}, {%4,%5,%6,%7}, {%8,%9}, {%0,%1,%2,%3};"
                 : "+f"(d[0]), "+f"(d[1]), "+f"(d[2]), "+f"(d[3])
                 : "r"(a[0]), "r"(a[1]), "r"(a[2]), "r"(a[3]), "r"(b[0]), "r"(b[1]));
}
__device__ __forceinline__ void cp16(uint32_t saddr, const void* gaddr) {
    asm volatile("cp.async.cg.shared.global [%0], [%1], 16;" :: "r"(saddr), "l"(gaddr));
}
__device__ __forceinline__ void cp16z(uint32_t saddr, const void* gaddr, int nbytes) {
    asm volatile("cp.async.cg.shared.global [%0], [%1], 16, %2;"
                 :: "r"(saddr), "l"(gaddr), "r"(nbytes));
}
__device__ __forceinline__ void cp_commit() {
    asm volatile("cp.async.commit_group;" ::: "memory");
}
template <int N>
__device__ __forceinline__ void cp_wait() {
    asm volatile("cp.async.wait_group %0;" :: "n"(N) : "memory");
}

// ---------------- small kernels ----------------------------------------------
__global__ void lengths_kernel(const int* __restrict__ mask) {
    int b = blockIdx.x;
    int v = mask[b * T + threadIdx.x];
#pragma unroll
    for (int o = 16; o > 0; o >>= 1) v += __shfl_down_sync(0xffffffffu, v, o);
    __shared__ int sh[4];
    if ((threadIdx.x & 31) == 0) sh[threadIdx.x >> 5] = v;
    __syncthreads();
    if (threadIdx.x == 0) g_len[b] = sh[0] + sh[1] + sh[2] + sh[3];
}

__global__ void embed_kernel(const int* __restrict__ ids, const float* __restrict__ emb) {
    int r = blockIdx.x;
    int id = __ldg(&ids[r]);
    const float4* s = reinterpret_cast<const float4*>(emb) + (size_t)id * (E / 4);
    float4* d = reinterpret_cast<float4*>(g_x) + (size_t)r * (E / 4);
    d[threadIdx.x] = s[threadIdx.x];
}

__global__ void zero_hc() {
    int i = blockIdx.x * blockDim.x + threadIdx.x;
    if (i == 0) g_bar = 0u;
    if (i < B * H) {
        g_h[0][i] = 0.f; g_h[1][i] = 0.f; g_c[i] = 0.f;
        __half z = __float2half_rn(0.f);
        g_hbf[0][i] = z; g_hbf[1][i] = z;
    }
}

// mode 0: g_x -> g_xhi (fp16 hi only). mode 1: wsrc -> g_whi/g_wlo (fp16 hi+lo)
__global__ void convert_kernel(const float* __restrict__ wsrc, int mode, int n4) {
    int i = blockIdx.x * blockDim.x + threadIdx.x;
    if (i >= n4) return;
    if (mode == 0) {
        float4 v = reinterpret_cast<const float4*>(g_x)[i];
        __half2* hp = reinterpret_cast<__half2*>(g_xhi) + 2 * i;
        hp[0] = __half2(__float2half_rn(v.x), __float2half_rn(v.y));
        hp[1] = __half2(__float2half_rn(v.z), __float2half_rn(v.w));
    } else {
        float4 v = reinterpret_cast<const float4*>(wsrc)[i];
        __half h0 = __float2half_rn(v.x), h1 = __float2half_rn(v.y);
        __half h2 = __float2half_rn(v.z), h3 = __float2half_rn(v.w);
        __half2* hp = reinterpret_cast<__half2*>(g_whi) + 2 * i;
        __half2* lp = reinterpret_cast<__half2*>(g_wlo) + 2 * i;
        hp[0] = __half2(h0, h1); hp[1] = __half2(h2, h3);
        lp[0] = __half2(__float2half_rn(v.x - __half2float(h0)),
                        __float2half_rn(v.y - __half2float(h1)));
        lp[1] = __half2(__float2half_rn(v.z - __half2float(h2)),
                        __float2half_rn(v.w - __half2float(h3)));
    }
}

// gate-interleave + split Whh into fp16 hi/lo: out row 4j+g = Whh[g*H+j]
__global__ void reorder_whh(const float* __restrict__ Whh) {
    int r = blockIdx.x;
    int j = r >> 2, g = r & 3;
    const float4* src = reinterpret_cast<const float4*>(Whh + (size_t)(g * H + j) * H);
    int i = threadIdx.x;
    float4 v = src[i];
    __half h0 = __float2half_rn(v.x), h1 = __float2half_rn(v.y);
    __half h2 = __float2half_rn(v.z), h3 = __float2half_rn(v.w);
    __half2* hp = reinterpret_cast<__half2*>(g_wrhi + (size_t)r * H) + 2 * i;
    __half2* lp = reinterpret_cast<__half2*>(g_wrlo + (size_t)r * H) + 2 * i;
    hp[0] = __half2(h0, h1); hp[1] = __half2(h2, h3);
    lp[0] = __half2(__float2half_rn(v.x - __half2float(h0)),
                    __float2half_rn(v.y - __half2float(h1)));
    lp[1] = __half2(__float2half_rn(v.z - __half2float(h2)),
                    __float2half_rn(v.w - __half2float(h3)));
}

// ---------------- fp16 2-pass tensor-core GEMM, 2-stage cp.async, occ=2 -----
// C = x @ W^T + b1 (+ b2) = xh.Wh + xh.Wl (fp32 accum)
#define SSTR 40
#define MAT_BYTES (128 * SSTR * 2)      // 10240 B
#define STG_BYTES (3 * MAT_BYTES)       // Ah|Bh|Bl = 30720 B per stage
#define NSTAGE 2
#define GEMM_SMEM (NSTAGE * STG_BYTES)  // 61440 B

__global__ void __launch_bounds__(256, 2) mma_gemm(
    float* __restrict__ Cout, const float* __restrict__ b1,
    const float* __restrict__ b2, int Ncols, int ldc, int mode)
{
    extern __shared__ char dsm[];
    float* __restrict__ C = (mode == 0) ? g_gx : Cout;

    const int tid  = threadIdx.x;
    const int wid  = tid >> 5;
    const int lane = tid & 31;
    const int row0 = blockIdx.y * 128;
    const int col0 = blockIdx.x * 128;
    const int wm0  = (wid >> 2) * 64;
    const int wn0  = (wid & 3) * 32;

    const uint32_t smem0 = smem_u32(dsm);

    const int r0t = tid >> 2, r1t = (256 + tid) >> 2;
    const int qt  = tid & 3;

    auto issue = [&](int ch) {
        const uint32_t sb = smem0 + (ch & 1) * STG_BYTES;
        const int kb = ch * 32;
#pragma unroll
        for (int s = 0; s < 2; s++) {
            int r = (s == 0) ? r0t : r1t;
            uint32_t so = (uint32_t)((r * SSTR + qt * 8) * 2);
            size_t ga = (size_t)(row0 + r) * KDIM + kb + qt * 8;
            cp16(sb + so, g_xhi + ga);
            int n = col0 + r;
            int ok = (n < Ncols) ? 16 : 0;
            size_t gb = (size_t)(ok ? n : 0) * KDIM + kb + qt * 8;
            cp16z(sb + MAT_BYTES + so,     g_whi + gb, ok);
            cp16z(sb + 2 * MAT_BYTES + so, g_wlo + gb, ok);
        }
        cp_commit();
    };

    float acc[4][4][4];
#pragma unroll
    for (int mi = 0; mi < 4; mi++)
#pragma unroll
        for (int ni = 0; ni < 4; ni++)
#pragma unroll
            for (int q = 0; q < 4; q++) acc[mi][ni][q] = 0.f;

    const int NCH = KDIM / 32;
    issue(0);
    issue(1);

    const int arow = wm0 + (lane & 7) + ((lane >> 3) & 1) * 8;
    const int acol0 = (lane >> 4) * 8;
    const int brow = wn0 + (lane & 7) + ((lane >> 4) & 1) * 8;
    const int bcol0 = ((lane >> 3) & 1) * 8;

    for (int ch = 0; ch < NCH; ch++) {
        cp_wait<1>();
        __syncthreads();

        const uint32_t sb = smem0 + (ch & 1) * STG_BYTES;

#pragma unroll
        for (int ks = 0; ks < 2; ks++) {
            uint32_t A[4][4], Bq[4], Bh[4][2], Bx[4][2];
#pragma unroll
            for (int mi = 0; mi < 4; mi++)
                ldmx4(A[mi], sb + (uint32_t)(((arow + mi * 16) * SSTR + ks * 16 + acol0) * 2));
#pragma unroll
            for (int p = 0; p < 2; p++) {
                ldmx4(Bq, sb + MAT_BYTES +
                      (uint32_t)(((brow + p * 16) * SSTR + ks * 16 + bcol0) * 2));
                Bh[2 * p][0] = Bq[0]; Bh[2 * p][1] = Bq[1];
                Bh[2 * p + 1][0] = Bq[2]; Bh[2 * p + 1][1] = Bq[3];
            }
#pragma unroll
            for (int mi = 0; mi < 4; mi++)
#pragma unroll
                for (int ni = 0; ni < 4; ni++)
                    mma16816h(acc[mi][ni], A[mi], Bh[ni]);

#pragma unroll
            for (int p = 0; p < 2; p++) {
                ldmx4(Bq, sb + 2 * MAT_BYTES +
                      (uint32_t)(((brow + p * 16) * SSTR + ks * 16 + bcol0) * 2));
                Bx[2 * p][0] = Bq[0]; Bx[2 * p][1] = Bq[1];
                Bx[2 * p + 1][0] = Bq[2]; Bx[2 * p + 1][1] = Bq[3];
            }
#pragma unroll
            for (int mi = 0; mi < 4; mi++)
#pragma unroll
                for (int ni = 0; ni < 4; ni++)
                    mma16816h(acc[mi][ni], A[mi], Bx[ni]);
        }
        __syncthreads();

        if (ch + 2 < NCH) issue(ch + 2);
    }

#pragma unroll
    for (int ni = 0; ni < 4; ni++) {
        int col = col0 + wn0 + ni * 8 + (lane & 3) * 2;
        if (col >= Ncols) continue;
        float bx = b1[col], by = b1[col + 1];
        if (b2) { bx += b2[col]; by += b2[col + 1]; }
#pragma unroll
        for (int mi = 0; mi < 4; mi++) {
            int row = row0 + wm0 + mi * 16 + (lane >> 2);
            float2 v0 = make_float2(acc[mi][ni][0] + bx, acc[mi][ni][1] + by);
            float2 v1 = make_float2(acc[mi][ni][2] + bx, acc[mi][ni][3] + by);
            *reinterpret_cast<float2*>(&C[(size_t)row * ldc + col])       = v0;
            *reinterpret_cast<float2*>(&C[(size_t)(row + 8) * ldc + col]) = v1;
        }
    }
}

// ---------------- persistent fp16 2-pass LSTM recurrence --------------------
#define WSTR 1032
#define OFF_WH 0
#define OFF_WL (32 * WSTR * 2)                    // 66048
#define OFF_AH (OFF_WL + 32 * WSTR * 2)           // 132096
#define OFF_SS (OFF_AH + 64 * SSTR * 2)           // 137216
#define SMEM_P (OFF_SS + 64 * 36 * 4)             // 146432

__global__ void __launch_bounds__(128, 1) tc_persist()
{
    extern __shared__ char dsm[];
    __half* sWh = reinterpret_cast<__half*>(dsm + OFF_WH);
    __half* sWl = reinterpret_cast<__half*>(dsm + OFF_WL);
    __half* sAh = reinterpret_cast<__half*>(dsm + OFF_AH);
    float (*Ssm)[36] = reinterpret_cast<float(*)[36]>(dsm + OFF_SS);

    const int tid  = threadIdx.x;
    const int wid  = tid >> 5;
    const int lane = tid & 31;
    const int jblk = blockIdx.x;

    const uint32_t baseAh = smem_u32(sAh);
    const uint32_t baseWh = smem_u32(sWh);
    const uint32_t baseWl = smem_u32(sWl);

    // load W slice once: 32 rows x 1024 fp16, hi + lo
    for (int i = tid; i < 32 * 128; i += 128) {
        int r = i >> 7, q = i & 127;
        size_t gb = (size_t)(jblk * 32 + r) * H + q * 8;
        *reinterpret_cast<uint4*>(sWh + r * WSTR + q * 8) = *reinterpret_cast<const uint4*>(g_wrhi + gb);
        *reinterpret_cast<uint4*>(sWl + r * WSTR + q * 8) = *reinterpret_cast<const uint4*>(g_wrlo + gb);
    }
    __syncthreads();

    for (int t = 0; t < T; t++) {
        const __half* __restrict__ hbh = g_hbf[t & 1];

        float acc[4][4];
#pragma unroll
        for (int ni = 0; ni < 4; ni++)
#pragma unroll
            for (int q = 0; q < 4; q++) acc[ni][q] = 0.f;

        uint4 pf[2];
        auto prefetch = [&](int kb) {
#pragma unroll
            for (int s = 0; s < 2; s++) {
                int idx = s * 128 + tid;
                int r = idx >> 2, q = idx & 3;
                pf[s] = *reinterpret_cast<const uint4*>(hbh + (size_t)r * H + kb + q * 8);
            }
        };

        prefetch(0);

        for (int ch = 0; ch < KDIM / 32; ch++) {
            __syncthreads();
#pragma unroll
            for (int s = 0; s < 2; s++) {
                int idx = s * 128 + tid;
                int r = idx >> 2, q = idx & 3;
                *reinterpret_cast<uint4*>(sAh + r * SSTR + q * 8) = pf[s];
            }
            __syncthreads();

            if (ch + 1 < KDIM / 32) prefetch((ch + 1) * 32);

#pragma unroll
            for (int ks = 0; ks < 2; ks++) {
                uint32_t Ah[4], Bq[4], Bh[4][2], Bl[4][2];
                {
                    int arow = wid * 16 + (lane & 7) + ((lane >> 3) & 1) * 8;
                    int acol = ks * 16 + (lane >> 4) * 8;
                    ldmx4(Ah, baseAh + (uint32_t)((arow * SSTR + acol) * 2));
                }
                {
                    int brow = (lane & 7) + ((lane >> 4) & 1) * 8;
                    int bcol = ch * 32 + ks * 16 + ((lane >> 3) & 1) * 8;
#pragma unroll
                    for (int p = 0; p < 2; p++) {
                        uint32_t off = (uint32_t)(((brow + p * 16) * WSTR + bcol) * 2);
                        ldmx4(Bq, baseWh + off);
                        Bh[2 * p][0] = Bq[0]; Bh[2 * p][1] = Bq[1];
                        Bh[2 * p + 1][0] = Bq[2]; Bh[2 * p + 1][1] = Bq[3];
                        ldmx4(Bq, baseWl + off);
                        Bl[2 * p][0] = Bq[0]; Bl[2 * p][1] = Bq[1];
                        Bl[2 * p + 1][0] = Bq[2]; Bl[2 * p + 1][1] = Bq[3];
                    }
                }
#pragma unroll
                for (int ni = 0; ni < 4; ni++) {
                    mma16816h(acc[ni], Ah, Bh[ni]);
                    mma16816h(acc[ni], Ah, Bl[ni]);
                }
            }
        }

        __syncthreads();
        {
            int row = wid * 16 + (lane >> 2);
            int cc  = (lane & 3) * 2;
#pragma unroll
            for (int ni = 0; ni < 4; ni++) {
                int c = ni * 8 + cc;
                Ssm[row][c]         = acc[ni][0];
                Ssm[row][c + 1]     = acc[ni][1];
                Ssm[row + 8][c]     = acc[ni][2];
                Ssm[row + 8][c + 1] = acc[ni][3];
            }
        }
        __syncthreads();

        const float* __restrict__ hin  = g_h[t & 1];
        float* __restrict__       hout = g_h[(t + 1) & 1];
        __half* __restrict__      hbho = g_hbf[(t + 1) & 1];

#pragma unroll
        for (int ii = 0; ii < 4; ii++) {
            int idx = ii * 128 + tid;
            int b = idx >> 3, jl = idx & 7;
            int j = jblk * 8 + jl;
            size_t gr = ((size_t)b * T + t) * G4;
            float iv = Ssm[b][4 * jl + 0] + g_gx[gr + j];
            float fv = Ssm[b][4 * jl + 1] + g_gx[gr + H + j];
            float gv = Ssm[b][4 * jl + 2] + g_gx[gr + 2 * H + j];
            float ov = Ssm[b][4 * jl + 3] + g_gx[gr + 3 * H + j];

            float c_old = g_c[b * H + j];
            float h_old = hin[b * H + j];

            float si = 1.f / (1.f + expf(-iv));
            float sf = 1.f / (1.f + expf(-fv));
            float so = 1.f / (1.f + expf(-ov));
            float cn = fmaf(sf, c_old, si * tanhf(gv));
            float hn = so * tanhf(cn);

            bool ok = t < g_len[b];
            float cw = ok ? cn : c_old;
            float hw = ok ? hn : h_old;
            g_c[b * H + j]  = cw;
            hout[b * H + j] = hw;
            hbho[b * H + j] = __float2half_rn(hw);
            g_x[((size_t)b * T + t) * E + j] = ok ? hn : 0.f;
        }

        if (t + 1 < T) {
            __syncthreads();
            if (tid == 0) {
                __threadfence();
                atomicAdd(&g_bar, 1u);
                unsigned tgt = (unsigned)(t + 1) * gridDim.x;
                unsigned v;
                do {
                    asm volatile("ld.acquire.gpu.u32 %0, [%1];" : "=r"(v) : "l"(&g_bar));
                    if (v >= tgt) break;
                    __nanosleep(64);
                } while (true);
            }
            __syncthreads();
        }
    }
}

__global__ void copy_states_kernel(float* __restrict__ hs_out, float* __restrict__ cs_out) {
    int i = blockIdx.x * blockDim.x + threadIdx.x;
    if (i < B * H) {
        hs_out[i] = g_h[0][i];
        cs_out[i] = g_c[i];
    }
}

// ---------------- launch ------------------------------------------------------
extern "C" void kernel_launch(void* const* d_in, const int* in_sizes, int n_in,
                              void* d_out, int out_size)
{
    const int*   ids  = (const int*)d_in[0];
    const int*   mask = (const int*)d_in[1];
    const float* emb  = (const float*)d_in[2];
    const float* Wih  = (const float*)d_in[3];
    const float* Whh  = (const float*)d_in[4];
    const float* bih  = (const float*)d_in[5];
    const float* bhh  = (const float*)d_in[6];
    const float* fcw  = (const float*)d_in[7];
    const float* fcb  = (const float*)d_in[8];
    float* out = (float*)d_out;

    cudaFuncSetAttribute(tc_persist, cudaFuncAttributeMaxDynamicSharedMemorySize, SMEM_P);
    cudaFuncSetAttribute(mma_gemm, cudaFuncAttributeMaxDynamicSharedMemorySize, GEMM_SMEM);

    lengths_kernel<<<B, T>>>(mask);
    embed_kernel<<<B * T, E / 4>>>(ids, emb);

    const size_t HS_OFF = (size_t)B * T * V;
    const size_t CS_OFF = HS_OFF + (size_t)L * B * H;
    const int X4 = B * T * E / 4;

    for (int l = 0; l < L; l++) {
        convert_kernel<<<(X4 + 255) / 256, 256>>>(nullptr, 0, X4);
        const int W4 = G4 * E / 4;
        convert_kernel<<<(W4 + 255) / 256, 256>>>(Wih + (size_t)l * G4 * E, 1, W4);

        mma_gemm<<<dim3(G4 / 128, (B * T) / 128), 256, GEMM_SMEM>>>(
            nullptr, bih + (size_t)l * G4, bhh + (size_t)l * G4, G4, G4, /*mode=*/0);

        reorder_whh<<<G4, 256>>>(Whh + (size_t)l * G4 * H);
        zero_hc<<<(B * H + 511) / 512, 512>>>();

        tc_persist<<<128, 128, SMEM_P>>>();

        copy_states_kernel<<<(B * H + 511) / 512, 512>>>(
            out + HS_OFF + (size_t)l * B * H,
            out + CS_OFF + (size_t)l * B * H);
    }

    convert_kernel<<<(X4 + 255) / 256, 256>>>(nullptr, 0, X4);
    const int F4 = V * H / 4;
    convert_kernel<<<(F4 + 255) / 256, 256>>>(fcw, 1, F4);

    mma_gemm<<<dim3((V + 127) / 128, (B * T) / 128), 256, GEMM_SMEM>>>(
        out, fcb, nullptr, V, V, /*mode=*/1);
}

// round 12
// speedup vs baseline: 8.6015x; 1.1522x over previous
#include <cuda_runtime.h>
#include <cuda_fp16.h>
#include <math.h>
#include <stdint.h>

#define B 64
#define T 128
#define V 10000
#define E 1024
#define H 1024
#define G4 4096
#define L 2
#define KDIM 1024

// ---------------- scratch (device globals) ----------------------------------
__device__ float g_x[(size_t)B * T * E];
__device__ float g_gx[(size_t)B * T * G4];
__device__ float g_h[2][B * H];
__device__ float g_c[B * H];
__device__ int   g_len[B];
__device__ unsigned g_bar;
__device__ __half g_xhi[(size_t)B * T * E];
__device__ __half g_whi[(size_t)V * H];
__device__ __half g_hbf[2][B * H];               // fp16 hidden state (pingpong)
__device__ __half g_wrhi[(size_t)G4 * H];        // gate-interleaved Whh (fp16)

// ---------------- PTX helpers (portable sm_80+ PTX) --------------------------
__device__ __forceinline__ uint32_t smem_u32(const void* p) {
    uint32_t a;
    asm("{ .reg .u64 t; cvta.to.shared.u64 t, %1; cvt.u32.u64 %0, t; }" : "=r"(a) : "l"(p));
    return a;
}
__device__ __forceinline__ void ldmx4(uint32_t r[4], uint32_t addr) {
    asm volatile("ldmatrix.sync.aligned.m8n8.x4.shared.b16 {%0,%1,%2,%3}, [%4];"
                 : "=r"(r[0]), "=r"(r[1]), "=r"(r[2]), "=r"(r[3]) : "r"(addr));
}
__device__ __forceinline__ void mma16816h(float d[4], const uint32_t a[4], const uint32_t b[2]) {
    asm volatile("mma.sync.aligned.m16n8k16.row.col.f32.f16.f16.f32 "
                 "{%0,%1,%2,%3}, {%4,%5,%6,%7}, {%8,%9}, {%0,%1,%2,%3};"
                 : "+f"(d[0]), "+f"(d[1]), "+f"(d[2]), "+f"(d[3])
                 : "r"(a[0]), "r"(a[1]), "r"(a[2]), "r"(a[3]), "r"(b[0]), "r"(b[1]));
}
__device__ __forceinline__ void cp16(uint32_t saddr, const void* gaddr) {
    asm volatile("cp.async.cg.shared.global [%0], [%1], 16;" :: "r"(saddr), "l"(gaddr));
}
__device__ __forceinline__ void cp16z(uint32_t saddr, const void* gaddr, int nbytes) {
    asm volatile("cp.async.cg.shared.global [%0], [%1], 16, %2;"
                 :: "r"(saddr), "l"(gaddr), "r"(nbytes));
}
__device__ __forceinline__ void cp_commit() {
    asm volatile("cp.async.commit_group;" ::: "memory");
}
template <int N>
__device__ __forceinline__ void cp_wait() {
    asm volatile("cp.async.wait_group %0;" :: "n"(N) : "memory");
}

// ---------------- small kernels ----------------------------------------------
__global__ void lengths_kernel(const int* __restrict__ mask) {
    int b = blockIdx.x;
    int v = mask[b * T + threadIdx.x];
#pragma unroll
    for (int o = 16; o > 0; o >>= 1) v += __shfl_down_sync(0xffffffffu, v, o);
    __shared__ int sh[4];
    if ((threadIdx.x & 31) == 0) sh[threadIdx.x >> 5] = v;
    __syncthreads();
    if (threadIdx.x == 0) g_len[b] = sh[0] + sh[1] + sh[2] + sh[3];
}

__global__ void embed_kernel(const int* __restrict__ ids, const float* __restrict__ emb) {
    int r = blockIdx.x;
    int id = __ldg(&ids[r]);
    const float4* s = reinterpret_cast<const float4*>(emb) + (size_t)id * (E / 4);
    float4* d = reinterpret_cast<float4*>(g_x) + (size_t)r * (E / 4);
    float4 v = s[threadIdx.x];
    d[threadIdx.x] = v;
    __half2* hp = reinterpret_cast<__half2*>(g_xhi) + (size_t)r * (E / 2) + 2 * threadIdx.x;
    hp[0] = __half2(__float2half_rn(v.x), __float2half_rn(v.y));
    hp[1] = __half2(__float2half_rn(v.z), __float2half_rn(v.w));
}

__global__ void zero_hc() {
    int i = blockIdx.x * blockDim.x + threadIdx.x;
    if (i == 0) g_bar = 0u;
    if (i < B * H) {
        g_h[0][i] = 0.f; g_h[1][i] = 0.f; g_c[i] = 0.f;
        __half z = __float2half_rn(0.f);
        g_hbf[0][i] = z; g_hbf[1][i] = z;
    }
}

// wsrc -> g_whi (fp16)
__global__ void convert_w(const float* __restrict__ wsrc, int n4) {
    int i = blockIdx.x * blockDim.x + threadIdx.x;
    if (i >= n4) return;
    float4 v = reinterpret_cast<const float4*>(wsrc)[i];
    __half2* hp = reinterpret_cast<__half2*>(g_whi) + 2 * i;
    hp[0] = __half2(__float2half_rn(v.x), __float2half_rn(v.y));
    hp[1] = __half2(__float2half_rn(v.z), __float2half_rn(v.w));
}

// gate-interleave Whh into fp16: out row 4j+g = Whh[g*H+j]
__global__ void reorder_whh(const float* __restrict__ Whh) {
    int r = blockIdx.x;
    int j = r >> 2, g = r & 3;
    const float4* src = reinterpret_cast<const float4*>(Whh + (size_t)(g * H + j) * H);
    int i = threadIdx.x;
    float4 v = src[i];
    __half2* hp = reinterpret_cast<__half2*>(g_wrhi + (size_t)r * H) + 2 * i;
    hp[0] = __half2(__float2half_rn(v.x), __float2half_rn(v.y));
    hp[1] = __half2(__float2half_rn(v.z), __float2half_rn(v.w));
}

// ---------------- fp16 1-pass tensor-core GEMM, 2-stage cp.async, occ=2 -----
#define SSTR 40
#define MAT_BYTES (128 * SSTR * 2)      // 10240 B
#define STG_BYTES (2 * MAT_BYTES)       // A|W = 20480 B per stage
#define NSTAGE 2
#define GEMM_SMEM (NSTAGE * STG_BYTES)  // 40960 B

__global__ void __launch_bounds__(256, 2) mma_gemm(
    float* __restrict__ Cout, const float* __restrict__ b1,
    const float* __restrict__ b2, int Ncols, int ldc, int mode)
{
    extern __shared__ char dsm[];
    float* __restrict__ C = (mode == 0) ? g_gx : Cout;

    const int tid  = threadIdx.x;
    const int wid  = tid >> 5;
    const int lane = tid & 31;
    const int row0 = blockIdx.y * 128;
    const int col0 = blockIdx.x * 128;
    const int wm0  = (wid >> 2) * 64;
    const int wn0  = (wid & 3) * 32;

    const uint32_t smem0 = smem_u32(dsm);

    const int r0t = tid >> 2, r1t = (256 + tid) >> 2;
    const int qt  = tid & 3;

    auto issue = [&](int ch) {
        const uint32_t sb = smem0 + (ch & 1) * STG_BYTES;
        const int kb = ch * 32;
#pragma unroll
        for (int s = 0; s < 2; s++) {
            int r = (s == 0) ? r0t : r1t;
            uint32_t so = (uint32_t)((r * SSTR + qt * 8) * 2);
            size_t ga = (size_t)(row0 + r) * KDIM + kb + qt * 8;
            cp16(sb + so, g_xhi + ga);
            int n = col0 + r;
            int ok = (n < Ncols) ? 16 : 0;
            size_t gb = (size_t)(ok ? n : 0) * KDIM + kb + qt * 8;
            cp16z(sb + MAT_BYTES + so, g_whi + gb, ok);
        }
        cp_commit();
    };

    float acc[4][4][4];
#pragma unroll
    for (int mi = 0; mi < 4; mi++)
#pragma unroll
        for (int ni = 0; ni < 4; ni++)
#pragma unroll
            for (int q = 0; q < 4; q++) acc[mi][ni][q] = 0.f;

    const int NCH = KDIM / 32;
    issue(0);
    issue(1);

    const int arow = wm0 + (lane & 7) + ((lane >> 3) & 1) * 8;
    const int acol0 = (lane >> 4) * 8;
    const int brow = wn0 + (lane & 7) + ((lane >> 4) & 1) * 8;
    const int bcol0 = ((lane >> 3) & 1) * 8;

    for (int ch = 0; ch < NCH; ch++) {
        cp_wait<1>();
        __syncthreads();

        const uint32_t sb = smem0 + (ch & 1) * STG_BYTES;

#pragma unroll
        for (int ks = 0; ks < 2; ks++) {
            uint32_t A[4][4], Bq[4], Bh[4][2];
#pragma unroll
            for (int mi = 0; mi < 4; mi++)
                ldmx4(A[mi], sb + (uint32_t)(((arow + mi * 16) * SSTR + ks * 16 + acol0) * 2));
#pragma unroll
            for (int p = 0; p < 2; p++) {
                ldmx4(Bq, sb + MAT_BYTES +
                      (uint32_t)(((brow + p * 16) * SSTR + ks * 16 + bcol0) * 2));
                Bh[2 * p][0] = Bq[0]; Bh[2 * p][1] = Bq[1];
                Bh[2 * p + 1][0] = Bq[2]; Bh[2 * p + 1][1] = Bq[3];
            }
#pragma unroll
            for (int mi = 0; mi < 4; mi++)
#pragma unroll
                for (int ni = 0; ni < 4; ni++)
                    mma16816h(acc[mi][ni], A[mi], Bh[ni]);
        }
        __syncthreads();

        if (ch + 2 < NCH) issue(ch + 2);
    }

#pragma unroll
    for (int ni = 0; ni < 4; ni++) {
        int col = col0 + wn0 + ni * 8 + (lane & 3) * 2;
        if (col >= Ncols) continue;
        float bx = b1[col], by = b1[col + 1];
        if (b2) { bx += b2[col]; by += b2[col + 1]; }
#pragma unroll
        for (int mi = 0; mi < 4; mi++) {
            int row = row0 + wm0 + mi * 16 + (lane >> 2);
            float2 v0 = make_float2(acc[mi][ni][0] + bx, acc[mi][ni][1] + by);
            float2 v1 = make_float2(acc[mi][ni][2] + bx, acc[mi][ni][3] + by);
            *reinterpret_cast<float2*>(&C[(size_t)row * ldc + col])       = v0;
            *reinterpret_cast<float2*>(&C[(size_t)(row + 8) * ldc + col]) = v1;
        }
    }
}

// ---------------- persistent fp16 1-pass LSTM recurrence --------------------
#define WSTR 1032
#define OFF_WH 0
#define OFF_AH (32 * WSTR * 2)                    // 66048
#define OFF_SS (OFF_AH + 64 * SSTR * 2)           // 71168
#define SMEM_P (OFF_SS + 64 * 36 * 4)             // 80384

__global__ void __launch_bounds__(128, 1) tc_persist(int layer)
{
    extern __shared__ char dsm[];
    __half* sWh = reinterpret_cast<__half*>(dsm + OFF_WH);
    __half* sAh = reinterpret_cast<__half*>(dsm + OFF_AH);
    float (*Ssm)[36] = reinterpret_cast<float(*)[36]>(dsm + OFF_SS);

    const int tid  = threadIdx.x;
    const int wid  = tid >> 5;
    const int lane = tid & 31;
    const int jblk = blockIdx.x;

    const uint32_t baseAh = smem_u32(sAh);
    const uint32_t baseWh = smem_u32(sWh);

    // load W slice once: 32 rows x 1024 fp16
    for (int i = tid; i < 32 * 128; i += 128) {
        int r = i >> 7, q = i & 127;
        size_t gb = (size_t)(jblk * 32 + r) * H + q * 8;
        *reinterpret_cast<uint4*>(sWh + r * WSTR + q * 8) = *reinterpret_cast<const uint4*>(g_wrhi + gb);
    }
    __syncthreads();

    for (int t = 0; t < T; t++) {
        const __half* __restrict__ hbh = g_hbf[t & 1];

        float acc[4][4];
#pragma unroll
        for (int ni = 0; ni < 4; ni++)
#pragma unroll
            for (int q = 0; q < 4; q++) acc[ni][q] = 0.f;

        uint4 pf[2];
        auto prefetch = [&](int kb) {
#pragma unroll
            for (int s = 0; s < 2; s++) {
                int idx = s * 128 + tid;
                int r = idx >> 2, q = idx & 3;
                pf[s] = *reinterpret_cast<const uint4*>(hbh + (size_t)r * H + kb + q * 8);
            }
        };

        prefetch(0);

        for (int ch = 0; ch < KDIM / 32; ch++) {
            __syncthreads();
#pragma unroll
            for (int s = 0; s < 2; s++) {
                int idx = s * 128 + tid;
                int r = idx >> 2, q = idx & 3;
                *reinterpret_cast<uint4*>(sAh + r * SSTR + q * 8) = pf[s];
            }
            __syncthreads();

            if (ch + 1 < KDIM / 32) prefetch((ch + 1) * 32);

#pragma unroll
            for (int ks = 0; ks < 2; ks++) {
                uint32_t Ah[4], Bq[4], Bh[4][2];
                {
                    int arow = wid * 16 + (lane & 7) + ((lane >> 3) & 1) * 8;
                    int acol = ks * 16 + (lane >> 4) * 8;
                    ldmx4(Ah, baseAh + (uint32_t)((arow * SSTR + acol) * 2));
                }
                {
                    int brow = (lane & 7) + ((lane >> 4) & 1) * 8;
                    int bcol = ch * 32 + ks * 16 + ((lane >> 3) & 1) * 8;
#pragma unroll
                    for (int p = 0; p < 2; p++) {
                        uint32_t off = (uint32_t)(((brow + p * 16) * WSTR + bcol) * 2);
                        ldmx4(Bq, baseWh + off);
                        Bh[2 * p][0] = Bq[0]; Bh[2 * p][1] = Bq[1];
                        Bh[2 * p + 1][0] = Bq[2]; Bh[2 * p + 1][1] = Bq[3];
                    }
                }
#pragma unroll
                for (int ni = 0; ni < 4; ni++)
                    mma16816h(acc[ni], Ah, Bh[ni]);
            }
        }

        __syncthreads();
        {
            int row = wid * 16 + (lane >> 2);
            int cc  = (lane & 3) * 2;
#pragma unroll
            for (int ni = 0; ni < 4; ni++) {
                int c = ni * 8 + cc;
                Ssm[row][c]         = acc[ni][0];
                Ssm[row][c + 1]     = acc[ni][1];
                Ssm[row + 8][c]     = acc[ni][2];
                Ssm[row + 8][c + 1] = acc[ni][3];
            }
        }
        __syncthreads();

        const float* __restrict__ hin  = g_h[t & 1];
        float* __restrict__       hout = g_h[(t + 1) & 1];
        __half* __restrict__      hbho = g_hbf[(t + 1) & 1];

#pragma unroll
        for (int ii = 0; ii < 4; ii++) {
            int idx = ii * 128 + tid;
            int b = idx >> 3, jl = idx & 7;
            int j = jblk * 8 + jl;
            size_t gr = ((size_t)b * T + t) * G4;
            float iv = Ssm[b][4 * jl + 0] + g_gx[gr + j];
            float fv = Ssm[b][4 * jl + 1] + g_gx[gr + H + j];
            float gv = Ssm[b][4 * jl + 2] + g_gx[gr + 2 * H + j];
            float ov = Ssm[b][4 * jl + 3] + g_gx[gr + 3 * H + j];

            float c_old = g_c[b * H + j];
            float h_old = hin[b * H + j];

            float si = 1.f / (1.f + expf(-iv));
            float sf = 1.f / (1.f + expf(-fv));
            float so = 1.f / (1.f + expf(-ov));
            float cn = fmaf(sf, c_old, si * tanhf(gv));
            float hn = so * tanhf(cn);

            bool ok = t < g_len[b];
            float cw = ok ? cn : c_old;
            float hw = ok ? hn : h_old;
            g_c[b * H + j]  = cw;
            hout[b * H + j] = hw;
            hbho[b * H + j] = __float2half_rn(hw);
            float xo = ok ? hn : 0.f;
            g_x[((size_t)b * T + t) * E + j]   = xo;
            g_xhi[((size_t)b * T + t) * E + j] = __float2half_rn(xo);
        }

        if (t + 1 < T) {
            __syncthreads();
            if (tid == 0) {
                __threadfence();
                atomicAdd(&g_bar, 1u);
                unsigned tgt = (unsigned)(t + 1) * gridDim.x + (unsigned)layer;
                unsigned v;
                do {
                    asm volatile("ld.acquire.gpu.u32 %0, [%1];" : "=r"(v) : "l"(&g_bar));
                    if (v >= tgt) break;
                    __nanosleep(64);
                } while (true);
            }
            __syncthreads();
        }
    }
}

__global__ void copy_states_kernel(float* __restrict__ hs_out, float* __restrict__ cs_out) {
    int i = blockIdx.x * blockDim.x + threadIdx.x;
    if (i < B * H) {
        hs_out[i] = g_h[0][i];
        cs_out[i] = g_c[i];
    }
}

// ---------------- launch ------------------------------------------------------
extern "C" void kernel_launch(void* const* d_in, const int* in_sizes, int n_in,
                              void* d_out, int out_size)
{
    const int*   ids  = (const int*)d_in[0];
    const int*   mask = (const int*)d_in[1];
    const float* emb  = (const float*)d_in[2];
    const float* Wih  = (const float*)d_in[3];
    const float* Whh  = (const float*)d_in[4];
    const float* bih  = (const float*)d_in[5];
    const float* bhh  = (const float*)d_in[6];
    const float* fcw  = (const float*)d_in[7];
    const float* fcb  = (const float*)d_in[8];
    float* out = (float*)d_out;

    cudaFuncSetAttribute(tc_persist, cudaFuncAttributeMaxDynamicSharedMemorySize, SMEM_P);
    cudaFuncSetAttribute(mma_gemm, cudaFuncAttributeMaxDynamicSharedMemorySize, GEMM_SMEM);

    lengths_kernel<<<B, T>>>(mask);
    embed_kernel<<<B * T, E / 4>>>(ids, emb);   // writes g_x AND g_xhi

    const size_t HS_OFF = (size_t)B * T * V;
    const size_t CS_OFF = HS_OFF + (size_t)L * B * H;

    for (int l = 0; l < L; l++) {
        const int W4 = G4 * E / 4;
        convert_w<<<(W4 + 255) / 256, 256>>>(Wih + (size_t)l * G4 * E, W4);

        mma_gemm<<<dim3(G4 / 128, (B * T) / 128), 256, GEMM_SMEM>>>(
            nullptr, bih + (size_t)l * G4, bhh + (size_t)l * G4, G4, G4, /*mode=*/0);

        reorder_whh<<<G4, 256>>>(Whh + (size_t)l * G4 * H);
        zero_hc<<<(B * H + 511) / 512, 512>>>();

        tc_persist<<<128, 128, SMEM_P>>>(0);

        copy_states_kernel<<<(B * H + 511) / 512, 512>>>(
            out + HS_OFF + (size_t)l * B * H,
            out + CS_OFF + (size_t)l * B * H);
    }

    const int F4 = V * H / 4;
    convert_w<<<(F4 + 255) / 256, 256>>>(fcw, F4);

    mma_gemm<<<dim3((V + 127) / 128, (B * T) / 128), 256, GEMM_SMEM>>>(
        out, fcb, nullptr, V, V, /*mode=*/1);
}

// round 13
// speedup vs baseline: 13.5998x; 1.5811x over previous
#include <cuda_runtime.h>
#include <cuda_fp16.h>
#include <math.h>
#include <stdint.h>

#define B 64
#define T 128
#define V 10000
#define E 1024
#define H 1024
#define G4 4096
#define L 2
#define KDIM 1024

// ---------------- scratch (device globals) ----------------------------------
__device__ float g_gx[(size_t)B * T * G4];
__device__ float g_h[2][B * H];
__device__ float g_c[B * H];
__device__ int   g_len[B];
__device__ unsigned g_bar;
__device__ __half g_xhi[(size_t)B * T * E];
__device__ __half g_whi[(size_t)V * H];
__device__ __half g_hbf[2][B * H];               // fp16 hidden state (pingpong)
__device__ __half g_wrhi[(size_t)G4 * H];        // gate-interleaved Whh (fp16)

// ---------------- PTX helpers (portable sm_80+ PTX) --------------------------
__device__ __forceinline__ uint32_t smem_u32(const void* p) {
    uint32_t a;
    asm("{ .reg .u64 t; cvta.to.shared.u64 t, %1; cvt.u32.u64 %0, t; }" : "=r"(a) : "l"(p));
    return a;
}
__device__ __forceinline__ void ldmx4(uint32_t r[4], uint32_t addr) {
    asm volatile("ldmatrix.sync.aligned.m8n8.x4.shared.b16 {%0,%1,%2,%3}, [%4];"
                 : "=r"(r[0]), "=r"(r[1]), "=r"(r[2]), "=r"(r[3]) : "r"(addr));
}
__device__ __forceinline__ void mma16816h(float d[4], const uint32_t a[4], const uint32_t b[2]) {
    asm volatile("mma.sync.aligned.m16n8k16.row.col.f32.f16.f16.f32 "
                 "{%0,%1,%2,%3}, {%4,%5,%6,%7}, {%8,%9}, {%0,%1,%2,%3};"
                 : "+f"(d[0]), "+f"(d[1]), "+f"(d[2]), "+f"(d[3])
                 : "r"(a[0]), "r"(a[1]), "r"(a[2]), "r"(a[3]), "r"(b[0]), "r"(b[1]));
}
__device__ __forceinline__ void cp16(uint32_t saddr, const void* gaddr) {
    asm volatile("cp.async.cg.shared.global [%0], [%1], 16;" :: "r"(saddr), "l"(gaddr));
}
__device__ __forceinline__ void cp16z(uint32_t saddr, const void* gaddr, int nbytes) {
    asm volatile("cp.async.cg.shared.global [%0], [%1], 16, %2;"
                 :: "r"(saddr), "l"(gaddr), "r"(nbytes));
}
__device__ __forceinline__ void cp_commit() {
    asm volatile("cp.async.commit_group;" ::: "memory");
}
template <int N>
__device__ __forceinline__ void cp_wait() {
    asm volatile("cp.async.wait_group %0;" :: "n"(N) : "memory");
}

// ---------------- small kernels ----------------------------------------------
__global__ void lengths_kernel(const int* __restrict__ mask) {
    int b = blockIdx.x;
    int v = mask[b * T + threadIdx.x];
#pragma unroll
    for (int o = 16; o > 0; o >>= 1) v += __shfl_down_sync(0xffffffffu, v, o);
    __shared__ int sh[4];
    if ((threadIdx.x & 31) == 0) sh[threadIdx.x >> 5] = v;
    __syncthreads();
    if (threadIdx.x == 0) g_len[b] = sh[0] + sh[1] + sh[2] + sh[3];
}

__global__ void embed_kernel(const int* __restrict__ ids, const float* __restrict__ emb) {
    int r = blockIdx.x;
    int id = __ldg(&ids[r]);
    const float4* s = reinterpret_cast<const float4*>(emb) + (size_t)id * (E / 4);
    float4 v = s[threadIdx.x];
    __half2* hp = reinterpret_cast<__half2*>(g_xhi) + (size_t)r * (E / 2) + 2 * threadIdx.x;
    hp[0] = __half2(__float2half_rn(v.x), __float2half_rn(v.y));
    hp[1] = __half2(__float2half_rn(v.z), __float2half_rn(v.w));
}

__global__ void zero_hc() {
    int i = blockIdx.x * blockDim.x + threadIdx.x;
    if (i == 0) g_bar = 0u;
    if (i < B * H) {
        g_h[0][i] = 0.f; g_h[1][i] = 0.f; g_c[i] = 0.f;
        __half z = __float2half_rn(0.f);
        g_hbf[0][i] = z; g_hbf[1][i] = z;
    }
}

__global__ void convert_w(const float* __restrict__ wsrc, int n4) {
    int i = blockIdx.x * blockDim.x + threadIdx.x;
    if (i >= n4) return;
    float4 v = reinterpret_cast<const float4*>(wsrc)[i];
    __half2* hp = reinterpret_cast<__half2*>(g_whi) + 2 * i;
    hp[0] = __half2(__float2half_rn(v.x), __float2half_rn(v.y));
    hp[1] = __half2(__float2half_rn(v.z), __float2half_rn(v.w));
}

__global__ void reorder_whh(const float* __restrict__ Whh) {
    int r = blockIdx.x;
    int j = r >> 2, g = r & 3;
    const float4* src = reinterpret_cast<const float4*>(Whh + (size_t)(g * H + j) * H);
    int i = threadIdx.x;
    float4 v = src[i];
    __half2* hp = reinterpret_cast<__half2*>(g_wrhi + (size_t)r * H) + 2 * i;
    hp[0] = __half2(__float2half_rn(v.x), __float2half_rn(v.y));
    hp[1] = __half2(__float2half_rn(v.z), __float2half_rn(v.w));
}

// ---------------- fp16 1-pass GEMM, 3-stage cp.async, 1 sync/chunk, occ=2 ---
#define SSTR 40
#define MAT_BYTES (128 * SSTR * 2)      // 10240 B
#define STG_BYTES (2 * MAT_BYTES)       // A|W = 20480 B per stage
#define NSTAGE 3
#define GEMM_SMEM (NSTAGE * STG_BYTES)  // 61440 B

__global__ void __launch_bounds__(256, 2) mma_gemm(
    float* __restrict__ Cout, const float* __restrict__ b1,
    const float* __restrict__ b2, int Ncols, int ldc, int mode)
{
    extern __shared__ char dsm[];
    float* __restrict__ C = (mode == 0) ? g_gx : Cout;

    const int tid  = threadIdx.x;
    const int wid  = tid >> 5;
    const int lane = tid & 31;
    const int row0 = blockIdx.y * 128;
    const int col0 = blockIdx.x * 128;
    const int wm0  = (wid >> 2) * 64;
    const int wn0  = (wid & 3) * 32;

    const uint32_t smem0 = smem_u32(dsm);

    const int r0t = tid >> 2, r1t = (256 + tid) >> 2;
    const int qt  = tid & 3;

    auto issue = [&](int ch) {
        const uint32_t sb = smem0 + (ch % NSTAGE) * STG_BYTES;
        const int kb = ch * 32;
#pragma unroll
        for (int s = 0; s < 2; s++) {
            int r = (s == 0) ? r0t : r1t;
            uint32_t so = (uint32_t)((r * SSTR + qt * 8) * 2);
            size_t ga = (size_t)(row0 + r) * KDIM + kb + qt * 8;
            cp16(sb + so, g_xhi + ga);
            int n = col0 + r;
            int ok = (n < Ncols) ? 16 : 0;
            size_t gb = (size_t)(ok ? n : 0) * KDIM + kb + qt * 8;
            cp16z(sb + MAT_BYTES + so, g_whi + gb, ok);
        }
        cp_commit();
    };

    float acc[4][4][4];
#pragma unroll
    for (int mi = 0; mi < 4; mi++)
#pragma unroll
        for (int ni = 0; ni < 4; ni++)
#pragma unroll
            for (int q = 0; q < 4; q++) acc[mi][ni][q] = 0.f;

    const int NCH = KDIM / 32;
    issue(0);
    issue(1);

    const int arow = wm0 + (lane & 7) + ((lane >> 3) & 1) * 8;
    const int acol0 = (lane >> 4) * 8;
    const int brow = wn0 + (lane & 7) + ((lane >> 4) & 1) * 8;
    const int bcol0 = ((lane >> 3) & 1) * 8;

    for (int ch = 0; ch < NCH; ch++) {
        cp_wait<1>();
        __syncthreads();     // data for ch visible; all warps done reading ch-1

        if (ch + 2 < NCH) issue(ch + 2);   // overwrites stage read at ch-1

        const uint32_t sb = smem0 + (ch % NSTAGE) * STG_BYTES;

#pragma unroll
        for (int ks = 0; ks < 2; ks++) {
            uint32_t A[4][4], Bq[4], Bh[4][2];
#pragma unroll
            for (int mi = 0; mi < 4; mi++)
                ldmx4(A[mi], sb + (uint32_t)(((arow + mi * 16) * SSTR + ks * 16 + acol0) * 2));
#pragma unroll
            for (int p = 0; p < 2; p++) {
                ldmx4(Bq, sb + MAT_BYTES +
                      (uint32_t)(((brow + p * 16) * SSTR + ks * 16 + bcol0) * 2));
                Bh[2 * p][0] = Bq[0]; Bh[2 * p][1] = Bq[1];
                Bh[2 * p + 1][0] = Bq[2]; Bh[2 * p + 1][1] = Bq[3];
            }
#pragma unroll
            for (int mi = 0; mi < 4; mi++)
#pragma unroll
                for (int ni = 0; ni < 4; ni++)
                    mma16816h(acc[mi][ni], A[mi], Bh[ni]);
        }
    }

#pragma unroll
    for (int ni = 0; ni < 4; ni++) {
        int col = col0 + wn0 + ni * 8 + (lane & 3) * 2;
        if (col >= Ncols) continue;
        float bx = b1[col], by = b1[col + 1];
        if (b2) { bx += b2[col]; by += b2[col + 1]; }
#pragma unroll
        for (int mi = 0; mi < 4; mi++) {
            int row = row0 + wm0 + mi * 16 + (lane >> 2);
            float2 v0 = make_float2(acc[mi][ni][0] + bx, acc[mi][ni][1] + by);
            float2 v1 = make_float2(acc[mi][ni][2] + bx, acc[mi][ni][3] + by);
            *reinterpret_cast<float2*>(&C[(size_t)row * ldc + col])       = v0;
            *reinterpret_cast<float2*>(&C[(size_t)(row + 8) * ldc + col]) = v1;
        }
    }
}

// ---------------- persistent fp16 LSTM recurrence: whole h in smem ----------
// Per step: cp.async the full 64x1024 fp16 h tile (128 KB) in 4 commit groups,
// then 4 MMA blocks (256 k-cols each) with ONE sync per block.
#define WSTR 1032
#define ASTR 1032
#define OFF_WH 0
#define OFF_AH (32 * WSTR * 2)                    // 66048
#define OFF_SS (OFF_AH + 64 * ASTR * 2)           // 198144
#define SMEM_P (OFF_SS + 64 * 36 * 4)             // 207360

__global__ void __launch_bounds__(128, 1) tc_persist()
{
    extern __shared__ char dsm[];
    __half* sWh = reinterpret_cast<__half*>(dsm + OFF_WH);
    __half* sAh = reinterpret_cast<__half*>(dsm + OFF_AH);
    float (*Ssm)[36] = reinterpret_cast<float(*)[36]>(dsm + OFF_SS);

    const int tid  = threadIdx.x;
    const int wid  = tid >> 5;
    const int lane = tid & 31;
    const int jblk = blockIdx.x;

    const uint32_t baseAh = smem_u32(sAh);
    const uint32_t baseWh = smem_u32(sWh);

    // load W slice once: 32 rows x 1024 fp16
    for (int i = tid; i < 32 * 128; i += 128) {
        int r = i >> 7, q = i & 127;
        size_t gb = (size_t)(jblk * 32 + r) * H + q * 8;
        *reinterpret_cast<uint4*>(sWh + r * WSTR + q * 8) = *reinterpret_cast<const uint4*>(g_wrhi + gb);
    }
    __syncthreads();

    const int arow = wid * 16 + (lane & 7) + ((lane >> 3) & 1) * 8;
    const int acol0 = (lane >> 4) * 8;
    const int brow = (lane & 7) + ((lane >> 4) & 1) * 8;
    const int bcol0 = ((lane >> 3) & 1) * 8;

    for (int t = 0; t < T; t++) {
        const __half* __restrict__ hbh = g_hbf[t & 1];

        // issue full h load: 4 commit groups x 256 k-cols (32 KB each)
#pragma unroll
        for (int g = 0; g < 4; g++) {
#pragma unroll
            for (int i = 0; i < 16; i++) {
                int idx = i * 128 + tid;          // 0..2047
                int r = idx >> 5, q = idx & 31;
                uint32_t so = (uint32_t)((r * ASTR + g * 256 + q * 8) * 2);
                cp16(baseAh + so, hbh + (size_t)r * H + g * 256 + q * 8);
            }
            cp_commit();
        }

        float acc[4][4];
#pragma unroll
        for (int ni = 0; ni < 4; ni++)
#pragma unroll
            for (int q = 0; q < 4; q++) acc[ni][q] = 0.f;

#pragma unroll
        for (int g = 0; g < 4; g++) {
            if (g == 0) cp_wait<3>();
            else if (g == 1) cp_wait<2>();
            else if (g == 2) cp_wait<1>();
            else cp_wait<0>();
            __syncthreads();

#pragma unroll
            for (int ks = 0; ks < 16; ks++) {
                int kc = g * 256 + ks * 16;
                uint32_t Ah[4], Bq[4], Bh[4][2];
                ldmx4(Ah, baseAh + (uint32_t)((arow * ASTR + kc + acol0) * 2));
#pragma unroll
                for (int p = 0; p < 2; p++) {
                    uint32_t off = (uint32_t)(((brow + p * 16) * WSTR + kc + bcol0) * 2);
                    ldmx4(Bq, baseWh + off);
                    Bh[2 * p][0] = Bq[0]; Bh[2 * p][1] = Bq[1];
                    Bh[2 * p + 1][0] = Bq[2]; Bh[2 * p + 1][1] = Bq[3];
                }
#pragma unroll
                for (int ni = 0; ni < 4; ni++)
                    mma16816h(acc[ni], Ah, Bh[ni]);
            }
        }

        __syncthreads();
        {
            int row = wid * 16 + (lane >> 2);
            int cc  = (lane & 3) * 2;
#pragma unroll
            for (int ni = 0; ni < 4; ni++) {
                int c = ni * 8 + cc;
                Ssm[row][c]         = acc[ni][0];
                Ssm[row][c + 1]     = acc[ni][1];
                Ssm[row + 8][c]     = acc[ni][2];
                Ssm[row + 8][c + 1] = acc[ni][3];
            }
        }
        __syncthreads();

        const float* __restrict__ hin  = g_h[t & 1];
        float* __restrict__       hout = g_h[(t + 1) & 1];
        __half* __restrict__      hbho = g_hbf[(t + 1) & 1];

#pragma unroll
        for (int ii = 0; ii < 4; ii++) {
            int idx = ii * 128 + tid;
            int b = idx >> 3, jl = idx & 7;
            int j = jblk * 8 + jl;
            size_t gr = ((size_t)b * T + t) * G4;
            float iv = Ssm[b][4 * jl + 0] + g_gx[gr + j];
            float fv = Ssm[b][4 * jl + 1] + g_gx[gr + H + j];
            float gv = Ssm[b][4 * jl + 2] + g_gx[gr + 2 * H + j];
            float ov = Ssm[b][4 * jl + 3] + g_gx[gr + 3 * H + j];

            float c_old = g_c[b * H + j];
            float h_old = hin[b * H + j];

            float si = 1.f / (1.f + expf(-iv));
            float sf = 1.f / (1.f + expf(-fv));
            float so = 1.f / (1.f + expf(-ov));
            float cn = fmaf(sf, c_old, si * tanhf(gv));
            float hn = so * tanhf(cn);

            bool ok = t < g_len[b];
            float cw = ok ? cn : c_old;
            float hw = ok ? hn : h_old;
            g_c[b * H + j]  = cw;
            hout[b * H + j] = hw;
            hbho[b * H + j] = __float2half_rn(hw);
            g_xhi[((size_t)b * T + t) * E + j] = __float2half_rn(ok ? hn : 0.f);
        }

        if (t + 1 < T) {
            __syncthreads();
            if (tid == 0) {
                __threadfence();
                atomicAdd(&g_bar, 1u);
                unsigned tgt = (unsigned)(t + 1) * gridDim.x;
                unsigned v;
                do {
                    asm volatile("ld.acquire.gpu.u32 %0, [%1];" : "=r"(v) : "l"(&g_bar));
                    if (v >= tgt) break;
                    __nanosleep(64);
                } while (true);
            }
            __syncthreads();
        }
    }
}

__global__ void copy_states_kernel(float* __restrict__ hs_out, float* __restrict__ cs_out) {
    int i = blockIdx.x * blockDim.x + threadIdx.x;
    if (i < B * H) {
        hs_out[i] = g_h[0][i];
        cs_out[i] = g_c[i];
    }
}

// ---------------- launch ------------------------------------------------------
extern "C" void kernel_launch(void* const* d_in, const int* in_sizes, int n_in,
                              void* d_out, int out_size)
{
    const int*   ids  = (const int*)d_in[0];
    const int*   mask = (const int*)d_in[1];
    const float* emb  = (const float*)d_in[2];
    const float* Wih  = (const float*)d_in[3];
    const float* Whh  = (const float*)d_in[4];
    const float* bih  = (const float*)d_in[5];
    const float* bhh  = (const float*)d_in[6];
    const float* fcw  = (const float*)d_in[7];
    const float* fcb  = (const float*)d_in[8];
    float* out = (float*)d_out;

    cudaFuncSetAttribute(tc_persist, cudaFuncAttributeMaxDynamicSharedMemorySize, SMEM_P);
    cudaFuncSetAttribute(mma_gemm, cudaFuncAttributeMaxDynamicSharedMemorySize, GEMM_SMEM);

    lengths_kernel<<<B, T>>>(mask);
    embed_kernel<<<B * T, E / 4>>>(ids, emb);

    const size_t HS_OFF = (size_t)B * T * V;
    const size_t CS_OFF = HS_OFF + (size_t)L * B * H;

    for (int l = 0; l < L; l++) {
        const int W4 = G4 * E / 4;
        convert_w<<<(W4 + 255) / 256, 256>>>(Wih + (size_t)l * G4 * E, W4);

        mma_gemm<<<dim3(G4 / 128, (B * T) / 128), 256, GEMM_SMEM>>>(
            nullptr, bih + (size_t)l * G4, bhh + (size_t)l * G4, G4, G4, /*mode=*/0);

        reorder_whh<<<G4, 256>>>(Whh + (size_t)l * G4 * H);
        zero_hc<<<(B * H + 511) / 512, 512>>>();

        tc_persist<<<128, 128, SMEM_P>>>();

        copy_states_kernel<<<(B * H + 511) / 512, 512>>>(
            out + HS_OFF + (size_t)l * B * H,
            out + CS_OFF + (size_t)l * B * H);
    }

    const int F4 = V * H / 4;
    convert_w<<<(F4 + 255) / 256, 256>>>(fcw, F4);

    mma_gemm<<<dim3((V + 127) / 128, (B * T) / 128), 256, GEMM_SMEM>>>(
        out, fcb, nullptr, V, V, /*mode=*/1);
}

// round 14
// speedup vs baseline: 15.2320x; 1.1200x over previous
#include <cuda_runtime.h>
#include <cuda_fp16.h>
#include <math.h>
#include <stdint.h>

#define B 64
#define T 128
#define V 10000
#define E 1024
#define H 1024
#define G4 4096
#define L 2
#define KDIM 1024

// ---------------- scratch (device globals) ----------------------------------
__device__ float g_gx[(size_t)B * T * G4];
__device__ float g_h[2][B * H];
__device__ float g_c[B * H];
__device__ int   g_len[B];
__device__ unsigned g_bar;
__device__ __half g_xhi[(size_t)B * T * E];
__device__ __half g_whi[(size_t)V * H];
__device__ __half g_hbf[2][B * H];               // fp16 hidden state (pingpong)
__device__ __half g_wrhi[(size_t)G4 * H];        // gate-interleaved Whh (fp16)

// ---------------- PTX helpers (portable sm_80+ PTX) --------------------------
__device__ __forceinline__ uint32_t smem_u32(const void* p) {
    uint32_t a;
    asm("{ .reg .u64 t; cvta.to.shared.u64 t, %1; cvt.u32.u64 %0, t; }" : "=r"(a) : "l"(p));
    return a;
}
__device__ __forceinline__ void ldmx4(uint32_t r[4], uint32_t addr) {
    asm volatile("ldmatrix.sync.aligned.m8n8.x4.shared.b16 {%0,%1,%2,%3}, [%4];"
                 : "=r"(r[0]), "=r"(r[1]), "=r"(r[2]), "=r"(r[3]) : "r"(addr));
}
__device__ __forceinline__ void mma16816h(float d[4], const uint32_t a[4], const uint32_t b[2]) {
    asm volatile("mma.sync.aligned.m16n8k16.row.col.f32.f16.f16.f32 "
                 "{%0,%1,%2,%3}, {%4,%5,%6,%7}, {%8,%9}, {%0,%1,%2,%3};"
                 : "+f"(d[0]), "+f"(d[1]), "+f"(d[2]), "+f"(d[3])
                 : "r"(a[0]), "r"(a[1]), "r"(a[2]), "r"(a[3]), "r"(b[0]), "r"(b[1]));
}
__device__ __forceinline__ void cp16(uint32_t saddr, const void* gaddr) {
    asm volatile("cp.async.cg.shared.global [%0], [%1], 16;" :: "r"(saddr), "l"(gaddr));
}
__device__ __forceinline__ void cp16z(uint32_t saddr, const void* gaddr, int nbytes) {
    asm volatile("cp.async.cg.shared.global [%0], [%1], 16, %2;"
                 :: "r"(saddr), "l"(gaddr), "r"(nbytes));
}
__device__ __forceinline__ void cp_commit() {
    asm volatile("cp.async.commit_group;" ::: "memory");
}
template <int N>
__device__ __forceinline__ void cp_wait() {
    asm volatile("cp.async.wait_group %0;" :: "n"(N) : "memory");
}

// ---------------- small kernels ----------------------------------------------
__global__ void lengths_kernel(const int* __restrict__ mask) {
    int b = blockIdx.x;
    int v = mask[b * T + threadIdx.x];
#pragma unroll
    for (int o = 16; o > 0; o >>= 1) v += __shfl_down_sync(0xffffffffu, v, o);
    __shared__ int sh[4];
    if ((threadIdx.x & 31) == 0) sh[threadIdx.x >> 5] = v;
    __syncthreads();
    if (threadIdx.x == 0) g_len[b] = sh[0] + sh[1] + sh[2] + sh[3];
}

__global__ void embed_kernel(const int* __restrict__ ids, const float* __restrict__ emb) {
    int r = blockIdx.x;
    int id = __ldg(&ids[r]);
    const float4* s = reinterpret_cast<const float4*>(emb) + (size_t)id * (E / 4);
    float4 v = s[threadIdx.x];
    __half2* hp = reinterpret_cast<__half2*>(g_xhi) + (size_t)r * (E / 2) + 2 * threadIdx.x;
    hp[0] = __half2(__float2half_rn(v.x), __float2half_rn(v.y));
    hp[1] = __half2(__float2half_rn(v.z), __float2half_rn(v.w));
}

__global__ void zero_hc() {
    int i = blockIdx.x * blockDim.x + threadIdx.x;
    if (i == 0) g_bar = 0u;
    if (i < B * H) {
        g_h[0][i] = 0.f; g_h[1][i] = 0.f; g_c[i] = 0.f;
        __half z = __float2half_rn(0.f);
        g_hbf[0][i] = z; g_hbf[1][i] = z;
    }
}

__global__ void convert_w(const float* __restrict__ wsrc, int n4) {
    int i = blockIdx.x * blockDim.x + threadIdx.x;
    if (i >= n4) return;
    float4 v = reinterpret_cast<const float4*>(wsrc)[i];
    __half2* hp = reinterpret_cast<__half2*>(g_whi) + 2 * i;
    hp[0] = __half2(__float2half_rn(v.x), __float2half_rn(v.y));
    hp[1] = __half2(__float2half_rn(v.z), __float2half_rn(v.w));
}

__global__ void reorder_whh(const float* __restrict__ Whh) {
    int r = blockIdx.x;
    int j = r >> 2, g = r & 3;
    const float4* src = reinterpret_cast<const float4*>(Whh + (size_t)(g * H + j) * H);
    int i = threadIdx.x;
    float4 v = src[i];
    __half2* hp = reinterpret_cast<__half2*>(g_wrhi + (size_t)r * H) + 2 * i;
    hp[0] = __half2(__float2half_rn(v.x), __float2half_rn(v.y));
    hp[1] = __half2(__float2half_rn(v.z), __float2half_rn(v.w));
}

// ---------------- fp16 1-pass GEMM, 3-stage cp.async, 1 sync/chunk, occ=2 ---
#define SSTR 40
#define MAT_BYTES (128 * SSTR * 2)      // 10240 B
#define STG_BYTES (2 * MAT_BYTES)       // A|W = 20480 B per stage
#define NSTAGE 3
#define GEMM_SMEM (NSTAGE * STG_BYTES)  // 61440 B

__global__ void __launch_bounds__(256, 2) mma_gemm(
    float* __restrict__ Cout, const float* __restrict__ b1,
    const float* __restrict__ b2, int Ncols, int ldc, int mode)
{
    extern __shared__ char dsm[];
    float* __restrict__ C = (mode == 0) ? g_gx : Cout;

    const int tid  = threadIdx.x;
    const int wid  = tid >> 5;
    const int lane = tid & 31;
    const int row0 = blockIdx.y * 128;
    const int col0 = blockIdx.x * 128;
    const int wm0  = (wid >> 2) * 64;
    const int wn0  = (wid & 3) * 32;

    const uint32_t smem0 = smem_u32(dsm);

    const int r0t = tid >> 2, r1t = (256 + tid) >> 2;
    const int qt  = tid & 3;

    auto issue = [&](int ch) {
        const uint32_t sb = smem0 + (ch % NSTAGE) * STG_BYTES;
        const int kb = ch * 32;
#pragma unroll
        for (int s = 0; s < 2; s++) {
            int r = (s == 0) ? r0t : r1t;
            uint32_t so = (uint32_t)((r * SSTR + qt * 8) * 2);
            size_t ga = (size_t)(row0 + r) * KDIM + kb + qt * 8;
            cp16(sb + so, g_xhi + ga);
            int n = col0 + r;
            int ok = (n < Ncols) ? 16 : 0;
            size_t gb = (size_t)(ok ? n : 0) * KDIM + kb + qt * 8;
            cp16z(sb + MAT_BYTES + so, g_whi + gb, ok);
        }
        cp_commit();
    };

    float acc[4][4][4];
#pragma unroll
    for (int mi = 0; mi < 4; mi++)
#pragma unroll
        for (int ni = 0; ni < 4; ni++)
#pragma unroll
            for (int q = 0; q < 4; q++) acc[mi][ni][q] = 0.f;

    const int NCH = KDIM / 32;
    issue(0);
    issue(1);

    const int arow = wm0 + (lane & 7) + ((lane >> 3) & 1) * 8;
    const int acol0 = (lane >> 4) * 8;
    const int brow = wn0 + (lane & 7) + ((lane >> 4) & 1) * 8;
    const int bcol0 = ((lane >> 3) & 1) * 8;

    for (int ch = 0; ch < NCH; ch++) {
        cp_wait<1>();
        __syncthreads();

        if (ch + 2 < NCH) issue(ch + 2);

        const uint32_t sb = smem0 + (ch % NSTAGE) * STG_BYTES;

#pragma unroll
        for (int ks = 0; ks < 2; ks++) {
            uint32_t A[4][4], Bq[4], Bh[4][2];
#pragma unroll
            for (int mi = 0; mi < 4; mi++)
                ldmx4(A[mi], sb + (uint32_t)(((arow + mi * 16) * SSTR + ks * 16 + acol0) * 2));
#pragma unroll
            for (int p = 0; p < 2; p++) {
                ldmx4(Bq, sb + MAT_BYTES +
                      (uint32_t)(((brow + p * 16) * SSTR + ks * 16 + bcol0) * 2));
                Bh[2 * p][0] = Bq[0]; Bh[2 * p][1] = Bq[1];
                Bh[2 * p + 1][0] = Bq[2]; Bh[2 * p + 1][1] = Bq[3];
            }
#pragma unroll
            for (int mi = 0; mi < 4; mi++)
#pragma unroll
                for (int ni = 0; ni < 4; ni++)
                    mma16816h(acc[mi][ni], A[mi], Bh[ni]);
        }
    }

#pragma unroll
    for (int ni = 0; ni < 4; ni++) {
        int col = col0 + wn0 + ni * 8 + (lane & 3) * 2;
        if (col >= Ncols) continue;
        float bx = b1[col], by = b1[col + 1];
        if (b2) { bx += b2[col]; by += b2[col + 1]; }
#pragma unroll
        for (int mi = 0; mi < 4; mi++) {
            int row = row0 + wm0 + mi * 16 + (lane >> 2);
            float2 v0 = make_float2(acc[mi][ni][0] + bx, acc[mi][ni][1] + by);
            float2 v1 = make_float2(acc[mi][ni][2] + bx, acc[mi][ni][3] + by);
            *reinterpret_cast<float2*>(&C[(size_t)row * ldc + col])       = v0;
            *reinterpret_cast<float2*>(&C[(size_t)(row + 8) * ldc + col]) = v1;
        }
    }
}

// ---------------- persistent fp16 LSTM recurrence: whole h in smem, 8 warps -
// warps (wid&3) cover m-rows; wid>>2 splits the 32 gate cols into two 16-col
// halves -> 128 MMAs/warp/step.
#define WSTR 1032
#define ASTR 1032
#define OFF_WH 0
#define OFF_AH (32 * WSTR * 2)                    // 66048
#define OFF_SS (OFF_AH + 64 * ASTR * 2)           // 198144
#define SMEM_P (OFF_SS + 64 * 36 * 4)             // 207360

__global__ void __launch_bounds__(256, 1) tc_persist()
{
    extern __shared__ char dsm[];
    __half* sWh = reinterpret_cast<__half*>(dsm + OFF_WH);
    __half* sAh = reinterpret_cast<__half*>(dsm + OFF_AH);
    float (*Ssm)[36] = reinterpret_cast<float(*)[36]>(dsm + OFF_SS);

    const int tid  = threadIdx.x;
    const int wid  = tid >> 5;
    const int lane = tid & 31;
    const int jblk = blockIdx.x;

    const uint32_t baseAh = smem_u32(sAh);
    const uint32_t baseWh = smem_u32(sWh);

    // load W slice once: 32 rows x 1024 fp16 (4096 uint4 over 256 threads)
    for (int i = tid; i < 32 * 128; i += 256) {
        int r = i >> 7, q = i & 127;
        size_t gb = (size_t)(jblk * 32 + r) * H + q * 8;
        *reinterpret_cast<uint4*>(sWh + r * WSTR + q * 8) = *reinterpret_cast<const uint4*>(g_wrhi + gb);
    }
    __syncthreads();

    const int arow = (wid & 3) * 16 + (lane & 7) + ((lane >> 3) & 1) * 8;
    const int acol0 = (lane >> 4) * 8;
    const int brow = (wid >> 2) * 16 + (lane & 7) + ((lane >> 4) & 1) * 8;
    const int bcol0 = ((lane >> 3) & 1) * 8;

    for (int t = 0; t < T; t++) {
        const __half* __restrict__ hbh = g_hbf[t & 1];

        // issue full h load: 4 commit groups x 256 k-cols (32 KB each)
#pragma unroll
        for (int g = 0; g < 4; g++) {
#pragma unroll
            for (int i = 0; i < 8; i++) {
                int idx = i * 256 + tid;          // 0..2047
                int r = idx >> 5, q = idx & 31;
                uint32_t so = (uint32_t)((r * ASTR + g * 256 + q * 8) * 2);
                cp16(baseAh + so, hbh + (size_t)r * H + g * 256 + q * 8);
            }
            cp_commit();
        }

        float acc[2][4];
#pragma unroll
        for (int ni = 0; ni < 2; ni++)
#pragma unroll
            for (int q = 0; q < 4; q++) acc[ni][q] = 0.f;

#pragma unroll
        for (int g = 0; g < 4; g++) {
            if (g == 0) cp_wait<3>();
            else if (g == 1) cp_wait<2>();
            else if (g == 2) cp_wait<1>();
            else cp_wait<0>();
            __syncthreads();

#pragma unroll
            for (int ks = 0; ks < 16; ks++) {
                int kc = g * 256 + ks * 16;
                uint32_t Ah[4], Bq[4], Bh[2][2];
                ldmx4(Ah, baseAh + (uint32_t)((arow * ASTR + kc + acol0) * 2));
                ldmx4(Bq, baseWh + (uint32_t)((brow * WSTR + kc + bcol0) * 2));
                Bh[0][0] = Bq[0]; Bh[0][1] = Bq[1];
                Bh[1][0] = Bq[2]; Bh[1][1] = Bq[3];
#pragma unroll
                for (int ni = 0; ni < 2; ni++)
                    mma16816h(acc[ni], Ah, Bh[ni]);
            }
        }

        __syncthreads();
        {
            int row = (wid & 3) * 16 + (lane >> 2);
            int cc  = (wid >> 2) * 16 + (lane & 3) * 2;
#pragma unroll
            for (int ni = 0; ni < 2; ni++) {
                int c = cc + ni * 8;
                Ssm[row][c]         = acc[ni][0];
                Ssm[row][c + 1]     = acc[ni][1];
                Ssm[row + 8][c]     = acc[ni][2];
                Ssm[row + 8][c + 1] = acc[ni][3];
            }
        }
        __syncthreads();

        const float* __restrict__ hin  = g_h[t & 1];
        float* __restrict__       hout = g_h[(t + 1) & 1];
        __half* __restrict__      hbho = g_hbf[(t + 1) & 1];

#pragma unroll
        for (int ii = 0; ii < 2; ii++) {
            int idx = ii * 256 + tid;
            int b = idx >> 3, jl = idx & 7;
            int j = jblk * 8 + jl;
            size_t gr = ((size_t)b * T + t) * G4;
            float iv = Ssm[b][4 * jl + 0] + g_gx[gr + j];
            float fv = Ssm[b][4 * jl + 1] + g_gx[gr + H + j];
            float gv = Ssm[b][4 * jl + 2] + g_gx[gr + 2 * H + j];
            float ov = Ssm[b][4 * jl + 3] + g_gx[gr + 3 * H + j];

            float c_old = g_c[b * H + j];
            float h_old = hin[b * H + j];

            float si = 1.f / (1.f + expf(-iv));
            float sf = 1.f / (1.f + expf(-fv));
            float so = 1.f / (1.f + expf(-ov));
            float cn = fmaf(sf, c_old, si * tanhf(gv));
            float hn = so * tanhf(cn);

            bool ok = t < g_len[b];
            float cw = ok ? cn : c_old;
            float hw = ok ? hn : h_old;
            g_c[b * H + j]  = cw;
            hout[b * H + j] = hw;
            hbho[b * H + j] = __float2half_rn(hw);
            g_xhi[((size_t)b * T + t) * E + j] = __float2half_rn(ok ? hn : 0.f);
        }

        if (t + 1 < T) {
            __syncthreads();
            if (tid == 0) {
                __threadfence();
                atomicAdd(&g_bar, 1u);
                unsigned tgt = (unsigned)(t + 1) * gridDim.x;
                unsigned v;
                do {
                    asm volatile("ld.acquire.gpu.u32 %0, [%1];" : "=r"(v) : "l"(&g_bar));
                    if (v >= tgt) break;
                    __nanosleep(64);
                } while (true);
            }
            __syncthreads();
        }
    }
}

__global__ void copy_states_kernel(float* __restrict__ hs_out, float* __restrict__ cs_out) {
    int i = blockIdx.x * blockDim.x + threadIdx.x;
    if (i < B * H) {
        hs_out[i] = g_h[0][i];
        cs_out[i] = g_c[i];
    }
}

// ---------------- launch ------------------------------------------------------
extern "C" void kernel_launch(void* const* d_in, const int* in_sizes, int n_in,
                              void* d_out, int out_size)
{
    const int*   ids  = (const int*)d_in[0];
    const int*   mask = (const int*)d_in[1];
    const float* emb  = (const float*)d_in[2];
    const float* Wih  = (const float*)d_in[3];
    const float* Whh  = (const float*)d_in[4];
    const float* bih  = (const float*)d_in[5];
    const float* bhh  = (const float*)d_in[6];
    const float* fcw  = (const float*)d_in[7];
    const float* fcb  = (const float*)d_in[8];
    float* out = (float*)d_out;

    cudaFuncSetAttribute(tc_persist, cudaFuncAttributeMaxDynamicSharedMemorySize, SMEM_P);
    cudaFuncSetAttribute(mma_gemm, cudaFuncAttributeMaxDynamicSharedMemorySize, GEMM_SMEM);

    lengths_kernel<<<B, T>>>(mask);
    embed_kernel<<<B * T, E / 4>>>(ids, emb);

    const size_t HS_OFF = (size_t)B * T * V;
    const size_t CS_OFF = HS_OFF + (size_t)L * B * H;

    for (int l = 0; l < L; l++) {
        const int W4 = G4 * E / 4;
        convert_w<<<(W4 + 255) / 256, 256>>>(Wih + (size_t)l * G4 * E, W4);

        mma_gemm<<<dim3(G4 / 128, (B * T) / 128), 256, GEMM_SMEM>>>(
            nullptr, bih + (size_t)l * G4, bhh + (size_t)l * G4, G4, G4, /*mode=*/0);

        reorder_whh<<<G4, 256>>>(Whh + (size_t)l * G4 * H);
        zero_hc<<<(B * H + 511) / 512, 512>>>();

        tc_persist<<<128, 256, SMEM_P>>>();

        copy_states_kernel<<<(B * H + 511) / 512, 512>>>(
            out + HS_OFF + (size_t)l * B * H,
            out + CS_OFF + (size_t)l * B * H);
    }

    const int F4 = V * H / 4;
    convert_w<<<(F4 + 255) / 256, 256>>>(fcw, F4);

    mma_gemm<<<dim3((V + 127) / 128, (B * T) / 128), 256, GEMM_SMEM>>>(
        out, fcb, nullptr, V, V, /*mode=*/1);
}

// round 15
// speedup vs baseline: 17.3559x; 1.1394x over previous
#include <cuda_runtime.h>
#include <cuda_fp16.h>
#include <math.h>
#include <stdint.h>

#define B 64
#define T 128
#define V 10000
#define E 1024
#define H 1024
#define G4 4096
#define L 2
#define KDIM 1024

// ---------------- scratch (device globals) ----------------------------------
__device__ float g_gx[(size_t)B * T * G4];
__device__ int   g_len[B];
__device__ unsigned g_bar;
__device__ __half g_xhi[(size_t)B * T * E];
__device__ __half g_whi[(size_t)V * H];
__device__ __half g_hbf[2][B * H];               // fp16 hidden state (pingpong)
__device__ __half g_wrhi[(size_t)G4 * H];        // gate-interleaved Whh (fp16)

// ---------------- PTX helpers (portable sm_80+ PTX) --------------------------
__device__ __forceinline__ uint32_t smem_u32(const void* p) {
    uint32_t a;
    asm("{ .reg .u64 t; cvta.to.shared.u64 t, %1; cvt.u32.u64 %0, t; }" : "=r"(a) : "l"(p));
    return a;
}
__device__ __forceinline__ void ldmx4(uint32_t r[4], uint32_t addr) {
    asm volatile("ldmatrix.sync.aligned.m8n8.x4.shared.b16 {%0,%1,%2,%3}, [%4];"
                 : "=r"(r[0]), "=r"(r[1]), "=r"(r[2]), "=r"(r[3]) : "r"(addr));
}
__device__ __forceinline__ void mma16816h(float d[4], const uint32_t a[4], const uint32_t b[2]) {
    asm volatile("mma.sync.aligned.m16n8k16.row.col.f32.f16.f16.f32 "
                 "{%0,%1,%2,%3}, {%4,%5,%6,%7}, {%8,%9}, {%0,%1,%2,%3};"
                 : "+f"(d[0]), "+f"(d[1]), "+f"(d[2]), "+f"(d[3])
                 : "r"(a[0]), "r"(a[1]), "r"(a[2]), "r"(a[3]), "r"(b[0]), "r"(b[1]));
}
__device__ __forceinline__ void cp16(uint32_t saddr, const void* gaddr) {
    asm volatile("cp.async.cg.shared.global [%0], [%1], 16;" :: "r"(saddr), "l"(gaddr));
}
__device__ __forceinline__ void cp16z(uint32_t saddr, const void* gaddr, int nbytes) {
    asm volatile("cp.async.cg.shared.global [%0], [%1], 16, %2;"
                 :: "r"(saddr), "l"(gaddr), "r"(nbytes));
}
__device__ __forceinline__ void cp_commit() {
    asm volatile("cp.async.commit_group;" ::: "memory");
}
template <int N>
__device__ __forceinline__ void cp_wait() {
    asm volatile("cp.async.wait_group %0;" :: "n"(N) : "memory");
}

// ---------------- small kernels ----------------------------------------------
__global__ void lengths_kernel(const int* __restrict__ mask) {
    int b = blockIdx.x;
    int v = mask[b * T + threadIdx.x];
#pragma unroll
    for (int o = 16; o > 0; o >>= 1) v += __shfl_down_sync(0xffffffffu, v, o);
    __shared__ int sh[4];
    if ((threadIdx.x & 31) == 0) sh[threadIdx.x >> 5] = v;
    __syncthreads();
    if (threadIdx.x == 0) g_len[b] = sh[0] + sh[1] + sh[2] + sh[3];
}

__global__ void embed_kernel(const int* __restrict__ ids, const float* __restrict__ emb) {
    int r = blockIdx.x;
    int id = __ldg(&ids[r]);
    const float4* s = reinterpret_cast<const float4*>(emb) + (size_t)id * (E / 4);
    float4 v = s[threadIdx.x];
    __half2* hp = reinterpret_cast<__half2*>(g_xhi) + (size_t)r * (E / 2) + 2 * threadIdx.x;
    hp[0] = __half2(__float2half_rn(v.x), __float2half_rn(v.y));
    hp[1] = __half2(__float2half_rn(v.z), __float2half_rn(v.w));
}

__global__ void zero_hb() {
    int i = blockIdx.x * blockDim.x + threadIdx.x;
    if (i == 0) g_bar = 0u;
    if (i < B * H) {
        __half z = __float2half_rn(0.f);
        g_hbf[0][i] = z; g_hbf[1][i] = z;
    }
}

__global__ void convert_w(const float* __restrict__ wsrc, int n4) {
    int i = blockIdx.x * blockDim.x + threadIdx.x;
    if (i >= n4) return;
    float4 v = reinterpret_cast<const float4*>(wsrc)[i];
    __half2* hp = reinterpret_cast<__half2*>(g_whi) + 2 * i;
    hp[0] = __half2(__float2half_rn(v.x), __float2half_rn(v.y));
    hp[1] = __half2(__float2half_rn(v.z), __float2half_rn(v.w));
}

__global__ void reorder_whh(const float* __restrict__ Whh) {
    int r = blockIdx.x;
    int j = r >> 2, g = r & 3;
    const float4* src = reinterpret_cast<const float4*>(Whh + (size_t)(g * H + j) * H);
    int i = threadIdx.x;
    float4 v = src[i];
    __half2* hp = reinterpret_cast<__half2*>(g_wrhi + (size_t)r * H) + 2 * i;
    hp[0] = __half2(__float2half_rn(v.x), __float2half_rn(v.y));
    hp[1] = __half2(__float2half_rn(v.z), __float2half_rn(v.w));
}

// ---------------- fp16 1-pass GEMM, 3-stage cp.async, 1 sync/chunk, occ=2 ---
#define SSTR 40
#define MAT_BYTES (128 * SSTR * 2)      // 10240 B
#define STG_BYTES (2 * MAT_BYTES)       // A|W = 20480 B per stage
#define NSTAGE 3
#define GEMM_SMEM (NSTAGE * STG_BYTES)  // 61440 B

__global__ void __launch_bounds__(256, 2) mma_gemm(
    float* __restrict__ Cout, const float* __restrict__ b1,
    const float* __restrict__ b2, int Ncols, int ldc, int mode)
{
    extern __shared__ char dsm[];
    float* __restrict__ C = (mode == 0) ? g_gx : Cout;

    const int tid  = threadIdx.x;
    const int wid  = tid >> 5;
    const int lane = tid & 31;
    const int row0 = blockIdx.y * 128;
    const int col0 = blockIdx.x * 128;
    const int wm0  = (wid >> 2) * 64;
    const int wn0  = (wid & 3) * 32;

    const uint32_t smem0 = smem_u32(dsm);

    const int r0t = tid >> 2, r1t = (256 + tid) >> 2;
    const int qt  = tid & 3;

    auto issue = [&](int ch) {
        const uint32_t sb = smem0 + (ch % NSTAGE) * STG_BYTES;
        const int kb = ch * 32;
#pragma unroll
        for (int s = 0; s < 2; s++) {
            int r = (s == 0) ? r0t : r1t;
            uint32_t so = (uint32_t)((r * SSTR + qt * 8) * 2);
            size_t ga = (size_t)(row0 + r) * KDIM + kb + qt * 8;
            cp16(sb + so, g_xhi + ga);
            int n = col0 + r;
            int ok = (n < Ncols) ? 16 : 0;
            size_t gb = (size_t)(ok ? n : 0) * KDIM + kb + qt * 8;
            cp16z(sb + MAT_BYTES + so, g_whi + gb, ok);
        }
        cp_commit();
    };

    float acc[4][4][4];
#pragma unroll
    for (int mi = 0; mi < 4; mi++)
#pragma unroll
        for (int ni = 0; ni < 4; ni++)
#pragma unroll
            for (int q = 0; q < 4; q++) acc[mi][ni][q] = 0.f;

    const int NCH = KDIM / 32;
    issue(0);
    issue(1);

    const int arow = wm0 + (lane & 7) + ((lane >> 3) & 1) * 8;
    const int acol0 = (lane >> 4) * 8;
    const int brow = wn0 + (lane & 7) + ((lane >> 4) & 1) * 8;
    const int bcol0 = ((lane >> 3) & 1) * 8;

    for (int ch = 0; ch < NCH; ch++) {
        cp_wait<1>();
        __syncthreads();

        if (ch + 2 < NCH) issue(ch + 2);

        const uint32_t sb = smem0 + (ch % NSTAGE) * STG_BYTES;

#pragma unroll
        for (int ks = 0; ks < 2; ks++) {
            uint32_t A[4][4], Bq[4], Bh[4][2];
#pragma unroll
            for (int mi = 0; mi < 4; mi++)
                ldmx4(A[mi], sb + (uint32_t)(((arow + mi * 16) * SSTR + ks * 16 + acol0) * 2));
#pragma unroll
            for (int p = 0; p < 2; p++) {
                ldmx4(Bq, sb + MAT_BYTES +
                      (uint32_t)(((brow + p * 16) * SSTR + ks * 16 + bcol0) * 2));
                Bh[2 * p][0] = Bq[0]; Bh[2 * p][1] = Bq[1];
                Bh[2 * p + 1][0] = Bq[2]; Bh[2 * p + 1][1] = Bq[3];
            }
#pragma unroll
            for (int mi = 0; mi < 4; mi++)
#pragma unroll
                for (int ni = 0; ni < 4; ni++)
                    mma16816h(acc[mi][ni], A[mi], Bh[ni]);
        }
    }

#pragma unroll
    for (int ni = 0; ni < 4; ni++) {
        int col = col0 + wn0 + ni * 8 + (lane & 3) * 2;
        if (col >= Ncols) continue;
        float bx = b1[col], by = b1[col + 1];
        if (b2) { bx += b2[col]; by += b2[col + 1]; }
#pragma unroll
        for (int mi = 0; mi < 4; mi++) {
            int row = row0 + wm0 + mi * 16 + (lane >> 2);
            float2 v0 = make_float2(acc[mi][ni][0] + bx, acc[mi][ni][1] + by);
            float2 v1 = make_float2(acc[mi][ni][2] + bx, acc[mi][ni][3] + by);
            *reinterpret_cast<float2*>(&C[(size_t)row * ldc + col])       = v0;
            *reinterpret_cast<float2*>(&C[(size_t)(row + 8) * ldc + col]) = v1;
        }
    }
}

// ---------------- persistent fp16 LSTM recurrence ---------------------------
// 128 CTAs x 256 threads; whole h (128 KB) + gx tile (8 KB) cp.async'd per
// step; c and fp32-h state CTA-local in smem; minimal pre-barrier store set.
#define WSTR 1032
#define ASTR 1032
#define OFF_WH 0
#define OFF_AH (32 * WSTR * 2)                    // 66048
#define OFF_SS (OFF_AH + 64 * ASTR * 2)           // 198144
#define OFF_GX (OFF_SS + 64 * 36 * 4)             // 207360
#define OFF_HL (OFF_GX + 64 * 32 * 4)             // 215552
#define OFF_CL (OFF_HL + 512 * 4)                 // 217600
#define SMEM_P (OFF_CL + 512 * 4)                 // 219648

__global__ void __launch_bounds__(256, 1) tc_persist(
    float* __restrict__ hs_out, float* __restrict__ cs_out)
{
    extern __shared__ char dsm[];
    __half* sWh = reinterpret_cast<__half*>(dsm + OFF_WH);
    __half* sAh = reinterpret_cast<__half*>(dsm + OFF_AH);
    float (*Ssm)[36] = reinterpret_cast<float(*)[36]>(dsm + OFF_SS);
    float* gxs  = reinterpret_cast<float*>(dsm + OFF_GX);   // [b][gate][jl]
    float* hloc = reinterpret_cast<float*>(dsm + OFF_HL);
    float* cloc = reinterpret_cast<float*>(dsm + OFF_CL);

    const int tid  = threadIdx.x;
    const int wid  = tid >> 5;
    const int lane = tid & 31;
    const int jblk = blockIdx.x;

    const uint32_t baseAh = smem_u32(sAh);
    const uint32_t baseWh = smem_u32(sWh);
    const uint32_t baseGx = smem_u32(gxs);

    // load W slice once: 32 rows x 1024 fp16
    for (int i = tid; i < 32 * 128; i += 256) {
        int r = i >> 7, q = i & 127;
        size_t gb = (size_t)(jblk * 32 + r) * H + q * 8;
        *reinterpret_cast<uint4*>(sWh + r * WSTR + q * 8) = *reinterpret_cast<const uint4*>(g_wrhi + gb);
    }
    hloc[tid] = 0.f; hloc[tid + 256] = 0.f;
    cloc[tid] = 0.f; cloc[tid + 256] = 0.f;
    __syncthreads();

    // per-thread constant epilogue mapping: idx in {tid, tid+256}
    const int b0 = tid >> 3, b1 = (tid + 256) >> 3;
    const int jl = tid & 7;
    const int j  = jblk * 8 + jl;
    const int len0 = g_len[b0], len1 = g_len[b1];

    const int arow  = (wid & 3) * 16 + (lane & 7) + ((lane >> 3) & 1) * 8;
    const int acol0 = (lane >> 4) * 8;
    const int brow  = (wid >> 2) * 16 + (lane & 7) + ((lane >> 4) & 1) * 8;
    const int bcol0 = ((lane >> 3) & 1) * 8;

    // gx cp slots (constant per thread): idx = i*256+tid -> b, gate, half
    const int gb0 = tid >> 3,        gg0 = (tid >> 1) & 3,        gh0 = tid & 1;
    const int gb1 = (tid + 256) >> 3, gg1 = ((tid + 256) >> 1) & 3, gh1 = tid & 1;

    for (int t = 0; t < T; t++) {
        const __half* __restrict__ hbh = g_hbf[t & 1];

        // groups 0..3: full h tile (32 KB each)
#pragma unroll
        for (int g = 0; g < 4; g++) {
#pragma unroll
            for (int i = 0; i < 8; i++) {
                int idx = i * 256 + tid;
                int r = idx >> 5, q = idx & 31;
                uint32_t so = (uint32_t)((r * ASTR + g * 256 + q * 8) * 2);
                cp16(baseAh + so, hbh + (size_t)r * H + g * 256 + q * 8);
            }
            cp_commit();
        }
        // group 4: gx tile (8 KB) — needed only at epilogue
        {
            const float* gsrc = g_gx + (size_t)t * G4;   // + b*T*G4 per row
            cp16(baseGx + (uint32_t)((gb0 * 32 + gg0 * 8 + gh0 * 4) * 4),
                 gsrc + (size_t)gb0 * T * G4 + gg0 * H + jblk * 8 + gh0 * 4);
            cp16(baseGx + (uint32_t)((gb1 * 32 + gg1 * 8 + gh1 * 4) * 4),
                 gsrc + (size_t)gb1 * T * G4 + gg1 * H + jblk * 8 + gh1 * 4);
            cp_commit();
        }

        float acc[2][4];
#pragma unroll
        for (int ni = 0; ni < 2; ni++)
#pragma unroll
            for (int q = 0; q < 4; q++) acc[ni][q] = 0.f;

#pragma unroll
        for (int g = 0; g < 4; g++) {
            if (g == 0) cp_wait<4>();
            else if (g == 1) cp_wait<3>();
            else if (g == 2) cp_wait<2>();
            else cp_wait<1>();
            __syncthreads();

#pragma unroll
            for (int ks = 0; ks < 16; ks++) {
                int kc = g * 256 + ks * 16;
                uint32_t Ah[4], Bq[4], Bh[2][2];
                ldmx4(Ah, baseAh + (uint32_t)((arow * ASTR + kc + acol0) * 2));
                ldmx4(Bq, baseWh + (uint32_t)((brow * WSTR + kc + bcol0) * 2));
                Bh[0][0] = Bq[0]; Bh[0][1] = Bq[1];
                Bh[1][0] = Bq[2]; Bh[1][1] = Bq[3];
#pragma unroll
                for (int ni = 0; ni < 2; ni++)
                    mma16816h(acc[ni], Ah, Bh[ni]);
            }
        }

        cp_wait<0>();          // gx tile landed
        __syncthreads();
        {
            int row = (wid & 3) * 16 + (lane >> 2);
            int cc  = (wid >> 2) * 16 + (lane & 3) * 2;
#pragma unroll
            for (int ni = 0; ni < 2; ni++) {
                int c = cc + ni * 8;
                Ssm[row][c]         = acc[ni][0];
                Ssm[row][c + 1]     = acc[ni][1];
                Ssm[row + 8][c]     = acc[ni][2];
                Ssm[row + 8][c + 1] = acc[ni][3];
            }
        }
        __syncthreads();

        __half* __restrict__ hbho = g_hbf[(t + 1) & 1];
        float xo[2];

#pragma unroll
        for (int ii = 0; ii < 2; ii++) {
            int b   = ii ? b1 : b0;
            int idx = tid + ii * 256;
            float iv = Ssm[b][4 * jl + 0] + gxs[b * 32 + jl];
            float fv = Ssm[b][4 * jl + 1] + gxs[b * 32 + 8 + jl];
            float gv = Ssm[b][4 * jl + 2] + gxs[b * 32 + 16 + jl];
            float ov = Ssm[b][4 * jl + 3] + gxs[b * 32 + 24 + jl];

            float c_old = cloc[idx];
            float h_old = hloc[idx];

            float si = 1.f / (1.f + expf(-iv));
            float sf = 1.f / (1.f + expf(-fv));
            float so = 1.f / (1.f + expf(-ov));
            float cn = fmaf(sf, c_old, si * tanhf(gv));
            float hn = so * tanhf(cn);

            bool ok = t < (ii ? len1 : len0);
            float cw = ok ? cn : c_old;
            float hw = ok ? hn : h_old;
            cloc[idx] = cw;
            hloc[idx] = hw;
            hbho[b * H + j] = __float2half_rn(hw);   // the ONLY critical store
            xo[ii] = ok ? hn : 0.f;
        }

        if (t + 1 < T) {
            __syncthreads();   // all hbf stores issued block-wide
            if (tid == 0) {
                __threadfence();
                atomicAdd(&g_bar, 1u);
            }
            // non-critical store overlapped with barrier wait
            g_xhi[((size_t)b0 * T + t) * E + j] = __float2half_rn(xo[0]);
            g_xhi[((size_t)b1 * T + t) * E + j] = __float2half_rn(xo[1]);
            if (tid == 0) {
                unsigned tgt = (unsigned)(t + 1) * gridDim.x;
                unsigned v;
                do {
                    asm volatile("ld.acquire.gpu.u32 %0, [%1];" : "=r"(v) : "l"(&g_bar));
                    if (v >= tgt) break;
                    __nanosleep(32);
                } while (true);
            }
            __syncthreads();
        } else {
            g_xhi[((size_t)b0 * T + t) * E + j] = __float2half_rn(xo[0]);
            g_xhi[((size_t)b1 * T + t) * E + j] = __float2half_rn(xo[1]);
        }
    }

    // final states straight from CTA-local smem
    hs_out[b0 * H + j] = hloc[tid];
    hs_out[b1 * H + j] = hloc[tid + 256];
    cs_out[b0 * H + j] = cloc[tid];
    cs_out[b1 * H + j] = cloc[tid + 256];
}

// ---------------- launch ------------------------------------------------------
extern "C" void kernel_launch(void* const* d_in, const int* in_sizes, int n_in,
                              void* d_out, int out_size)
{
    const int*   ids  = (const int*)d_in[0];
    const int*   mask = (const int*)d_in[1];
    const float* emb  = (const float*)d_in[2];
    const float* Wih  = (const float*)d_in[3];
    const float* Whh  = (const float*)d_in[4];
    const float* bih  = (const float*)d_in[5];
    const float* bhh  = (const float*)d_in[6];
    const float* fcw  = (const float*)d_in[7];
    const float* fcb  = (const float*)d_in[8];
    float* out = (float*)d_out;

    cudaFuncSetAttribute(tc_persist, cudaFuncAttributeMaxDynamicSharedMemorySize, SMEM_P);
    cudaFuncSetAttribute(mma_gemm, cudaFuncAttributeMaxDynamicSharedMemorySize, GEMM_SMEM);

    lengths_kernel<<<B, T>>>(mask);
    embed_kernel<<<B * T, E / 4>>>(ids, emb);

    const size_t HS_OFF = (size_t)B * T * V;
    const size_t CS_OFF = HS_OFF + (size_t)L * B * H;

    for (int l = 0; l < L; l++) {
        const int W4 = G4 * E / 4;
        convert_w<<<(W4 + 255) / 256, 256>>>(Wih + (size_t)l * G4 * E, W4);

        mma_gemm<<<dim3(G4 / 128, (B * T) / 128), 256, GEMM_SMEM>>>(
            nullptr, bih + (size_t)l * G4, bhh + (size_t)l * G4, G4, G4, /*mode=*/0);

        reorder_whh<<<G4, 256>>>(Whh + (size_t)l * G4 * H);
        zero_hb<<<(B * H + 511) / 512, 512>>>();

        tc_persist<<<128, 256, SMEM_P>>>(
            out + HS_OFF + (size_t)l * B * H,
            out + CS_OFF + (size_t)l * B * H);
    }

    const int F4 = V * H / 4;
    convert_w<<<(F4 + 255) / 256, 256>>>(fcw, F4);

    mma_gemm<<<dim3((V + 127) / 128, (B * T) / 128), 256, GEMM_SMEM>>>(
        out, fcb, nullptr, V, V, /*mode=*/1);
}